// round 6
// baseline (speedup 1.0000x reference)
#include <cuda_runtime.h>
#include <cuda_bf16.h>
#include <cstdint>

#define BATCH 4
#define L 4096
#define CM 192
#define DI 384
#define DS 16
#define DTR 12
#define M_ROWS (BATCH * L)   // 16384
#define NCH 128
#define CHL (L / NCH)        // 32
#define BDN (BATCH * DI * DS) // 24576
#define NX (2 * DI)          // 768

// ---------------- scratch (device globals; no allocation) ----------------
__device__ float g_xi[(size_t)M_ROWS * DI];
__device__ float g_z[(size_t)M_ROWS * DI];
__device__ float g_u[(size_t)M_ROWS * DI];
__device__ float g_delta[(size_t)M_ROWS * DI];
__device__ float g_dtr[(size_t)M_ROWS * DTR];
__device__ float g_Bs[(size_t)M_ROWS * DS];
__device__ float g_Cs[(size_t)M_ROWS * DS];
__device__ float g_hpart[(size_t)NCH * BDN];
__device__ float g_aP[(size_t)NCH * BDN];
__device__ float g_hin[(size_t)NCH * BDN];
__device__ __nv_bfloat16 g_whi[(size_t)NX * CM];   // transposed: [n][k]
__device__ __nv_bfloat16 g_wlo[(size_t)NX * CM];

// ---------------- k_split_w: fp32 -> bf16 hi/lo (weights only) ----------------
__global__ void k_split_w(const float* __restrict__ Win)
{
    const int i = blockIdx.x * 256 + threadIdx.x;
    if (i >= CM * NX) return;
    const int k = i / NX, n = i % NX;
    const float v = Win[i];
    const __nv_bfloat16 h = __float2bfloat16(v);
    g_whi[(size_t)n * CM + k] = h;
    g_wlo[(size_t)n * CM + k] = __float2bfloat16(v - __bfloat162float(h));
}

// ---------------- K1: xz = x @ W_in via bf16x3 mma.sync + ldmatrix ----------------
#define KP 40   // bf16 row pitch (80B): conflict-free ldmatrix

__device__ __forceinline__ void mma_bf16(float* d, const uint32_t* a, const uint32_t* b)
{
    asm volatile(
        "mma.sync.aligned.m16n8k16.row.col.f32.bf16.bf16.f32 "
        "{%0,%1,%2,%3}, {%4,%5,%6,%7}, {%8,%9}, {%0,%1,%2,%3};"
        : "+f"(d[0]), "+f"(d[1]), "+f"(d[2]), "+f"(d[3])
        : "r"(a[0]), "r"(a[1]), "r"(a[2]), "r"(a[3]), "r"(b[0]), "r"(b[1]));
}
#define LDSM4(r0, r1, r2, r3, addr) \
    asm volatile("ldmatrix.sync.aligned.m8n8.x4.shared.b16 {%0,%1,%2,%3}, [%4];" \
                 : "=r"(r0), "=r"(r1), "=r"(r2), "=r"(r3) : "r"(addr))

__device__ __forceinline__ uint32_t sptr(const void* p)
{
    return (uint32_t)__cvta_generic_to_shared(p);
}

__global__ __launch_bounds__(256) void k_gemm_mma(const float* __restrict__ X)
{
    __shared__ __nv_bfloat16 sAh[128][KP], sAl[128][KP], sBh[128][KP], sBl[128][KP];
    const int tid = threadIdx.x;
    const int wid = tid >> 5, t = tid & 31;
    const int m0 = blockIdx.x * 128, n0 = blockIdx.y * 128;
    const int wr = wid & 3, wc = wid >> 2;
    const int g = t >> 2, c2 = (t & 3) * 2;
    const int qrow = ((t >> 3) & 1) * 8 + (t & 7);
    const int qcol = (t >> 4) * 8;

    float acc[2][8][4];
#pragma unroll
    for (int mt = 0; mt < 2; mt++)
#pragma unroll
        for (int nt = 0; nt < 8; nt++)
#pragma unroll
            for (int e = 0; e < 4; e++) acc[mt][nt][e] = 0.f;

    const int lr = tid >> 1;
    const int lh = (tid & 1) * 16;

    for (int kc = 0; kc < CM; kc += 32) {
        {
            const float* xp = X + (size_t)(m0 + lr) * CM + kc + lh;
            uint32_t hi[8], lo[8];
#pragma unroll
            for (int q = 0; q < 4; q++) {
                float4 v = *(const float4*)(xp + q * 4);
                __nv_bfloat16 h0 = __float2bfloat16(v.x), h1 = __float2bfloat16(v.y),
                              h2 = __float2bfloat16(v.z), h3 = __float2bfloat16(v.w);
                __nv_bfloat162 H0(h0, h1), H1(h2, h3);
                __nv_bfloat162 L0(__float2bfloat16(v.x - __bfloat162float(h0)),
                                  __float2bfloat16(v.y - __bfloat162float(h1)));
                __nv_bfloat162 L1(__float2bfloat16(v.z - __bfloat162float(h2)),
                                  __float2bfloat16(v.w - __bfloat162float(h3)));
                hi[q * 2] = *(uint32_t*)&H0; hi[q * 2 + 1] = *(uint32_t*)&H1;
                lo[q * 2] = *(uint32_t*)&L0; lo[q * 2 + 1] = *(uint32_t*)&L1;
            }
            *(uint4*)&sAh[lr][lh]     = make_uint4(hi[0], hi[1], hi[2], hi[3]);
            *(uint4*)&sAh[lr][lh + 8] = make_uint4(hi[4], hi[5], hi[6], hi[7]);
            *(uint4*)&sAl[lr][lh]     = make_uint4(lo[0], lo[1], lo[2], lo[3]);
            *(uint4*)&sAl[lr][lh + 8] = make_uint4(lo[4], lo[5], lo[6], lo[7]);
            const __nv_bfloat16* bh = g_whi + (size_t)(n0 + lr) * CM + kc + lh;
            const __nv_bfloat16* bl = g_wlo + (size_t)(n0 + lr) * CM + kc + lh;
            *(uint4*)&sBh[lr][lh]     = *(const uint4*)(bh);
            *(uint4*)&sBh[lr][lh + 8] = *(const uint4*)(bh + 8);
            *(uint4*)&sBl[lr][lh]     = *(const uint4*)(bl);
            *(uint4*)&sBl[lr][lh + 8] = *(const uint4*)(bl + 8);
        }
        __syncthreads();

#pragma unroll
        for (int ks = 0; ks < 2; ks++) {
            const int K0 = ks * 16;
            uint32_t ahf[2][4], alf[2][4];
#pragma unroll
            for (int mt = 0; mt < 2; mt++) {
                const int R = wr * 32 + mt * 16 + qrow;
                LDSM4(ahf[mt][0], ahf[mt][1], ahf[mt][2], ahf[mt][3],
                      sptr(&sAh[R][K0 + qcol]));
                LDSM4(alf[mt][0], alf[mt][1], alf[mt][2], alf[mt][3],
                      sptr(&sAl[R][K0 + qcol]));
            }
#pragma unroll
            for (int ntp = 0; ntp < 4; ntp++) {
                const int N = wc * 64 + ntp * 16 + qrow;
                uint32_t h0, h1, h2, h3, l0, l1, l2, l3;
                LDSM4(h0, h1, h2, h3, sptr(&sBh[N][K0 + qcol]));
                LDSM4(l0, l1, l2, l3, sptr(&sBl[N][K0 + qcol]));
                uint32_t bhf0[2] = {h0, h2}, bhf1[2] = {h1, h3};
                uint32_t blf0[2] = {l0, l2}, blf1[2] = {l1, l3};
#pragma unroll
                for (int mt = 0; mt < 2; mt++) {
                    mma_bf16(acc[mt][ntp * 2],     ahf[mt], bhf0);
                    mma_bf16(acc[mt][ntp * 2],     ahf[mt], blf0);
                    mma_bf16(acc[mt][ntp * 2],     alf[mt], bhf0);
                    mma_bf16(acc[mt][ntp * 2 + 1], ahf[mt], bhf1);
                    mma_bf16(acc[mt][ntp * 2 + 1], ahf[mt], blf1);
                    mma_bf16(acc[mt][ntp * 2 + 1], alf[mt], bhf1);
                }
            }
        }
        __syncthreads();
    }

    const bool toZ = (n0 >= DI);
#pragma unroll
    for (int mt = 0; mt < 2; mt++) {
#pragma unroll
        for (int nt = 0; nt < 8; nt++) {
            int nc = n0 + wc * 64 + nt * 8 + c2;
            if (toZ) nc -= DI;
            const int r0 = m0 + wr * 32 + mt * 16 + g;
            float* base = toZ ? g_z : g_xi;
            *(float2*)&base[(size_t)r0 * DI + nc] =
                make_float2(acc[mt][nt][0], acc[mt][nt][1]);
            *(float2*)&base[(size_t)(r0 + 8) * DI + nc] =
                make_float2(acc[mt][nt][2], acc[mt][nt][3]);
        }
    }
}

// ---------------- conv: depthwise 3x3 + bias + SiLU, 8 outputs/thread ----------------
__global__ __launch_bounds__(1024) void k_conv(const float* __restrict__ cw,
                                               const float* __restrict__ cb)
{
    extern __shared__ float cs[];   // [100][128]
    const int b = blockIdx.z;
    const int d = blockIdx.y * 128 + threadIdx.x;
    const int h0 = (blockIdx.x >> 3) * 8;
    const int w0 = (blockIdx.x & 7) * 8;
    const int tx = threadIdx.x, ty = threadIdx.y;
    const size_t base = (size_t)b * L * DI;

#pragma unroll
    for (int i = 0; i < 13; i++) {
        const int p = ty + 8 * i;
        if (p < 100) {
            const int rr = p / 10, cc = p % 10;
            const int hh = h0 + rr - 1, ww = w0 + cc - 1;
            float v = 0.f;
            if (hh >= 0 && hh < 64 && ww >= 0 && ww < 64)
                v = g_xi[base + (size_t)(hh * 64 + ww) * DI + d];
            cs[p * 128 + tx] = v;
        }
    }
    __syncthreads();

    float W[9];
#pragma unroll
    for (int i = 0; i < 9; i++) W[i] = cw[d * 9 + i];
    const float bias = cb[d];

    float acc[8];
#pragma unroll
    for (int j = 0; j < 8; j++) acc[j] = bias;

#pragma unroll
    for (int r = 0; r < 3; r++) {
        float rv[10];
#pragma unroll
        for (int c = 0; c < 10; c++) rv[c] = cs[((ty + r) * 10 + c) * 128 + tx];
#pragma unroll
        for (int j = 0; j < 8; j++) {
            acc[j] = fmaf(rv[j],     W[r * 3 + 0], acc[j]);
            acc[j] = fmaf(rv[j + 1], W[r * 3 + 1], acc[j]);
            acc[j] = fmaf(rv[j + 2], W[r * 3 + 2], acc[j]);
        }
    }
#pragma unroll
    for (int j = 0; j < 8; j++) {
        const float sig = 1.f / (1.f + __expf(-acc[j]));
        g_u[base + (size_t)((h0 + ty) * 64 + w0 + j) * DI + d] = acc[j] * sig;
    }
}

// ---------------- k_proj2: x_dbl = u@Wx fused with Cs += prompt@Wp ----------------
// 32-row tiles, 512 blocks, 256 threads.
__global__ __launch_bounds__(256) void k_proj2(const float* __restrict__ Wx,
                                               const float* __restrict__ prompt,
                                               const float* __restrict__ Wp)
{
    __shared__ float Us[16][33];
    __shared__ float Wxs[16][48];
    __shared__ float sdC[32][16];
    __shared__ float Ps[32][192];
    __shared__ float Wps[192][16];
    const int tid = threadIdx.x;
    const int m0 = blockIdx.x * 32;
    const int tm = tid / 16, tn = tid % 16;

    // ---- phase A: x_dbl = u @ Wx ----
    float acc[2][3];
#pragma unroll
    for (int i = 0; i < 2; i++)
#pragma unroll
        for (int j = 0; j < 3; j++) acc[i][j] = 0.f;

    const int ur = tid / 8, ukq = (tid % 8) * 2;

    for (int k0 = 0; k0 < DI; k0 += 16) {
        float2 uv = *(const float2*)&g_u[(size_t)(m0 + ur) * DI + k0 + ukq];
        Us[ukq][ur] = uv.x;
        Us[ukq + 1][ur] = uv.y;
#pragma unroll
        for (int i = 0; i < 3; i++) {
            const int f = tid + i * 256;
            const int rr = f / 48, cc = f % 48;
            Wxs[rr][cc] = (cc < 44) ? Wx[(size_t)(k0 + rr) * 44 + cc] : 0.f;
        }
        __syncthreads();
#pragma unroll
        for (int k = 0; k < 16; k++) {
            const float a0 = Us[k][tm * 2], a1 = Us[k][tm * 2 + 1];
            const float b0 = Wxs[k][tn * 3 + 0];
            const float b1 = Wxs[k][tn * 3 + 1];
            const float b2 = Wxs[k][tn * 3 + 2];
            acc[0][0] = fmaf(a0, b0, acc[0][0]);
            acc[0][1] = fmaf(a0, b1, acc[0][1]);
            acc[0][2] = fmaf(a0, b2, acc[0][2]);
            acc[1][0] = fmaf(a1, b0, acc[1][0]);
            acc[1][1] = fmaf(a1, b1, acc[1][1]);
            acc[1][2] = fmaf(a1, b2, acc[1][2]);
        }
        __syncthreads();
    }
#pragma unroll
    for (int i = 0; i < 2; i++) {
        const int r = tm * 2 + i;
        const size_t m = (size_t)(m0 + r);
#pragma unroll
        for (int j = 0; j < 3; j++) {
            const int c = tn * 3 + j;
            const float v = acc[i][j];
            if (c < DTR)            g_dtr[m * DTR + c] = v;
            else if (c < DTR + DS)  g_Bs[m * DS + (c - DTR)] = v;
            else if (c < 44)        sdC[r][c - DTR - DS] = v;
        }
    }

    // ---- phase B: Cs = sdC + prompt @ Wp ----
#pragma unroll
    for (int i = 0; i < 6; i++) {
        const int e = tid + i * 256;        // float4 index, 0..1535
        const int rr = e / 48, c4 = (e % 48) * 4;
        *(float4*)&Ps[rr][c4] = *(const float4*)&prompt[(size_t)(m0 + rr) * CM + c4];
    }
#pragma unroll
    for (int i = 0; i < 12; i++) {
        const int e = tid + i * 256;        // 0..3071
        Wps[e / 16][e % 16] = Wp[e];
    }
    __syncthreads();

#pragma unroll
    for (int rep = 0; rep < 2; rep++) {
        const int o = tid + rep * 256;
        const int r = o >> 4, n = o & 15;
        float s0 = 0.f, s1 = 0.f;
#pragma unroll 8
        for (int k = 0; k < CM; k += 2) {
            s0 = fmaf(Ps[r][k],     Wps[k][n],     s0);
            s1 = fmaf(Ps[r][k + 1], Wps[k + 1][n], s1);
        }
        g_Cs[(size_t)(m0 + r) * DS + n] = s0 + s1 + sdC[r][n];
    }
}

// ---------------- k_delta ----------------
__global__ void k_delta(const float* __restrict__ Wdt, const float* __restrict__ bdt)
{
    __shared__ float sd[8][DTR];
    const int tid = threadIdx.x; // 384
    const int row0 = blockIdx.x * 8;
    if (tid < 8 * DTR) sd[tid / DTR][tid % DTR] = g_dtr[(size_t)(row0 + tid / DTR) * DTR + tid % DTR];
    __syncthreads();

    float w[DTR];
#pragma unroll
    for (int rr = 0; rr < DTR; rr++) w[rr] = Wdt[(size_t)rr * DI + tid];
    const float bb = bdt[tid];
#pragma unroll
    for (int rr = 0; rr < 8; rr++) {
        float acc = bb;
#pragma unroll
        for (int r2 = 0; r2 < DTR; r2++) acc = fmaf(sd[rr][r2], w[r2], acc);
        const float sp = acc > 20.f ? acc : log1pf(__expf(acc));
        g_delta[(size_t)(row0 + rr) * DI + tid] = sp;
    }
}

// ---------------- scan helpers ----------------
__device__ __forceinline__ void pow_chain(float e1, float* av)
{
    const float e2 = e1 * e1, e4 = e2 * e2, e8 = e4 * e4;
    av[0] = e1;       av[1] = e2;       av[2] = e2 * e1;   av[3] = e4;
    av[4] = e4 * e1;  av[5] = e4 * e2;  av[6] = e4 * av[2]; av[7] = e8;
    av[8] = e8 * e1;  av[9] = e8 * e2;  av[10] = e8 * av[2]; av[11] = e8 * e4;
    av[12] = e8 * av[4]; av[13] = e8 * av[5]; av[14] = e8 * av[6]; av[15] = e8 * e8;
}

__device__ __forceinline__ bool a_structured(const float* __restrict__ Alog, int d, float& A0)
{
    A0 = -__expf(Alog[(size_t)d * DS]);
    bool ok = true;
#pragma unroll
    for (int n = 1; n < DS; n++) {
        const float Av = -__expf(Alog[(size_t)d * DS + n]);
        ok &= fabsf(Av - (n + 1) * A0) <= 1e-4f * fabsf((n + 1) * A0);
    }
    return ok;
}

// ---------------- S1 ----------------
__global__ void k_scan1(const float* __restrict__ Alog)
{
    __shared__ float sB[CHL][DS];
    const int d = blockIdx.x * 128 + threadIdx.x;
    const int c = blockIdx.y;
    const int b = blockIdx.z;
    const int l0 = c * CHL;

    {
        const float4* src = (const float4*)g_Bs + ((size_t)b * L + l0) * 4;
        ((float4*)sB)[threadIdx.x] = src[threadIdx.x];
    }

    float A0;
    const bool st = a_structured(Alog, d, A0);
    __syncthreads();

    float h[DS];
#pragma unroll
    for (int n = 0; n < DS; n++) h[n] = 0.f;
    float dsum = 0.f;

    const float* dp = g_delta + ((size_t)b * L + l0) * DI + d;
    const float* up = g_u + ((size_t)b * L + l0) * DI + d;

    if (st) {
        for (int l = 0; l < CHL; l++) {
            const float dl = dp[(size_t)l * DI];
            const float du = dl * up[(size_t)l * DI];
            dsum += dl;
            float av[DS];
            pow_chain(__expf(dl * A0), av);
#pragma unroll
            for (int n = 0; n < DS; n++) h[n] = fmaf(av[n], h[n], du * sB[l][n]);
        }
        float av[DS];
        pow_chain(__expf(dsum * A0), av);
        const size_t base = (size_t)c * BDN + ((size_t)b * DI + d) * DS;
#pragma unroll
        for (int n = 0; n < DS; n++) {
            g_hpart[base + n] = h[n];
            g_aP[base + n] = av[n];
        }
    } else {
        float A[DS];
#pragma unroll
        for (int n = 0; n < DS; n++) A[n] = -__expf(Alog[(size_t)d * DS + n]);
        for (int l = 0; l < CHL; l++) {
            const float dl = dp[(size_t)l * DI];
            const float du = dl * up[(size_t)l * DI];
            dsum += dl;
#pragma unroll
            for (int n = 0; n < DS; n++)
                h[n] = fmaf(__expf(dl * A[n]), h[n], du * sB[l][n]);
        }
        const size_t base = (size_t)c * BDN + ((size_t)b * DI + d) * DS;
#pragma unroll
        for (int n = 0; n < DS; n++) {
            g_hpart[base + n] = h[n];
            g_aP[base + n] = __expf(A[n] * dsum);
        }
    }
}

// ---------------- S2 ----------------
__global__ void k_scan2()
{
    const int idx = blockIdx.x * 256 + threadIdx.x;
    if (idx >= BDN) return;
    float h = 0.f;
    for (int c = 0; c < NCH; c++) {
        const size_t o = (size_t)c * BDN + idx;
        g_hin[o] = h;
        h = fmaf(g_aP[o], h, g_hpart[o]);
    }
}

// ---------------- S3 fused with LN + gate + out GEMM ----------------
// grid (NCH, BATCH), 384 threads. smem: ys[32][385] + sB + sC + Wt[16][192]
#define YSP 385
__global__ __launch_bounds__(384) void k_scan3out(const float* __restrict__ Alog,
                                                  const float* __restrict__ Dvec,
                                                  const float* __restrict__ lng,
                                                  const float* __restrict__ lnb,
                                                  const float* __restrict__ Wout,
                                                  float* __restrict__ out)
{
    extern __shared__ float sm[];
    float* ys = sm;                       // 32*385 = 12320
    float* sB = sm + 32 * YSP;            // 512
    float* sC = sB + 512;                 // 512
    float* Wt = sC + 512;                 // 3072

    const int tid = threadIdx.x;
    const int d = tid;
    const int c = blockIdx.x, b = blockIdx.y;
    const int l0 = c * CHL;

    if (tid < 128)
        ((float4*)sB)[tid] = ((const float4*)g_Bs)[((size_t)b * L + l0) * 4 + tid];
    else if (tid < 256)
        ((float4*)sC)[tid - 128] = ((const float4*)g_Cs)[((size_t)b * L + l0) * 4 + tid - 128];

    float A0;
    const bool st = a_structured(Alog, d, A0);
    const float Dd = Dvec[d];

    float h[DS];
    {
        const size_t base = (size_t)c * BDN + ((size_t)b * DI + d) * DS;
#pragma unroll
        for (int n = 0; n < DS; n++) h[n] = g_hin[base + n];
    }
    __syncthreads();

    const float* dp = g_delta + ((size_t)b * L + l0) * DI + d;
    const float* up = g_u + ((size_t)b * L + l0) * DI + d;

    if (st) {
        for (int l = 0; l < CHL; l++) {
            const float dl = dp[(size_t)l * DI];
            const float uu = up[(size_t)l * DI];
            const float du = dl * uu;
            float av[DS];
            pow_chain(__expf(dl * A0), av);
            float y = uu * Dd;
#pragma unroll
            for (int n = 0; n < DS; n++) {
                h[n] = fmaf(av[n], h[n], du * sB[l * DS + n]);
                y = fmaf(h[n], sC[l * DS + n], y);
            }
            ys[l * YSP + d] = y;
        }
    } else {
        float A[DS];
#pragma unroll
        for (int n = 0; n < DS; n++) A[n] = -__expf(Alog[(size_t)d * DS + n]);
        for (int l = 0; l < CHL; l++) {
            const float dl = dp[(size_t)l * DI];
            const float uu = up[(size_t)l * DI];
            const float du = dl * uu;
            float y = uu * Dd;
#pragma unroll
            for (int n = 0; n < DS; n++) {
                h[n] = fmaf(__expf(dl * A[n]), h[n], du * sB[l * DS + n]);
                y = fmaf(h[n], sC[l * DS + n], y);
            }
            ys[l * YSP + d] = y;
        }
    }
    __syncthreads();

    // ---- LN + SiLU gate (12 warps over 32 rows) ----
    const int warp = tid >> 5, lane = tid & 31;
    for (int r = warp; r < CHL; r += 12) {
        float v[12];
        float s = 0.f, sq = 0.f;
#pragma unroll
        for (int i = 0; i < 12; i++) {
            v[i] = ys[r * YSP + lane + 32 * i];
            s += v[i];
            sq = fmaf(v[i], v[i], sq);
        }
#pragma unroll
        for (int o = 16; o > 0; o >>= 1) {
            s += __shfl_xor_sync(0xFFFFFFFFu, s, o);
            sq += __shfl_xor_sync(0xFFFFFFFFu, sq, o);
        }
        const float mu = s * (1.f / DI);
        const float var = sq * (1.f / DI) - mu * mu;
        const float rs = rsqrtf(var + 1e-5f);
        const size_t grow = (size_t)b * L + l0 + r;
#pragma unroll
        for (int i = 0; i < 12; i++) {
            const int k = lane + 32 * i;
            const float zn = g_z[grow * DI + k];
            const float sig = 1.f / (1.f + __expf(-zn));
            const float g = fmaf((v[i] - mu) * rs, lng[k], lnb[k]);
            ys[r * YSP + k] = g * zn * sig;
        }
    }
    __syncthreads();

    // ---- out GEMM: 32x384 @ 384x192 ----
    const int tr = tid / 96;   // 0..3 -> rows tr*8..+8
    const int tc = tid % 96;   // cols tc*2, tc*2+1
    float acc[8][2];
#pragma unroll
    for (int i = 0; i < 8; i++) { acc[i][0] = 0.f; acc[i][1] = 0.f; }

    for (int kt = 0; kt < DI; kt += 16) {
#pragma unroll
        for (int q = 0; q < 2; q++) {
            const int e = tid + q * 384;          // float4 index 0..767
            const int kr = e / 48, c4 = (e % 48) * 4;
            *(float4*)&Wt[kr * CM + c4] = *(const float4*)&Wout[(size_t)(kt + kr) * CM + c4];
        }
        __syncthreads();
#pragma unroll
        for (int k = 0; k < 16; k++) {
            const float2 w = *(const float2*)&Wt[k * CM + tc * 2];
#pragma unroll
            for (int i = 0; i < 8; i++) {
                const float a = ys[(tr * 8 + i) * YSP + kt + k];
                acc[i][0] = fmaf(a, w.x, acc[i][0]);
                acc[i][1] = fmaf(a, w.y, acc[i][1]);
            }
        }
        __syncthreads();
    }
#pragma unroll
    for (int i = 0; i < 8; i++) {
        const size_t row = (size_t)b * L + l0 + tr * 8 + i;
        *(float2*)&out[row * CM + tc * 2] = make_float2(acc[i][0], acc[i][1]);
    }
}

// ---------------- launch ----------------
extern "C" void kernel_launch(void* const* d_in, const int* in_sizes, int n_in,
                              void* d_out, int out_size)
{
    const float* x      = (const float*)d_in[0];
    const float* prompt = (const float*)d_in[1];
    const float* W_in   = (const float*)d_in[2];
    const float* conv_w = (const float*)d_in[3];
    const float* conv_b = (const float*)d_in[4];
    const float* Wx     = (const float*)d_in[5];
    const float* Wdt    = (const float*)d_in[6];
    const float* b_dt   = (const float*)d_in[7];
    const float* A_log  = (const float*)d_in[8];
    const float* Dv     = (const float*)d_in[9];
    const float* Wp     = (const float*)d_in[10];
    const float* ln_g   = (const float*)d_in[11];
    const float* ln_b   = (const float*)d_in[12];
    const float* Wout   = (const float*)d_in[13];
    float* out = (float*)d_out;

    static bool attr_set = false;
    if (!attr_set) {
        cudaFuncSetAttribute(k_conv, cudaFuncAttributeMaxDynamicSharedMemorySize, 51200);
        cudaFuncSetAttribute(k_scan3out, cudaFuncAttributeMaxDynamicSharedMemorySize, 65664);
        attr_set = true;
    }

    k_split_w<<<(CM * NX + 255) / 256, 256>>>(W_in);
    k_gemm_mma<<<dim3(M_ROWS / 128, NX / 128), 256>>>(x);
    k_conv<<<dim3(64, 3, BATCH), dim3(128, 8), 51200>>>(conv_w, conv_b);
    k_proj2<<<M_ROWS / 32, 256>>>(Wx, prompt, Wp);
    k_delta<<<M_ROWS / 8, DI>>>(Wdt, b_dt);
    k_scan1<<<dim3(DI / 128, NCH, BATCH), 128>>>(A_log);
    k_scan2<<<(BDN + 255) / 256, 256>>>();
    k_scan3out<<<dim3(NCH, BATCH), 384, 65664>>>(A_log, Dv, ln_g, ln_b, Wout, out);
}

// round 7
// speedup vs baseline: 1.0526x; 1.0526x over previous
#include <cuda_runtime.h>
#include <cuda_bf16.h>
#include <cstdint>

#define BATCH 4
#define L 4096
#define CM 192
#define DI 384
#define DS 16
#define DTR 12
#define M_ROWS (BATCH * L)   // 16384
#define NCH 128
#define CHL (L / NCH)        // 32
#define BDN (BATCH * DI * DS) // 24576
#define NX (2 * DI)          // 768

// ---------------- scratch (device globals; no allocation) ----------------
__device__ float g_xi[(size_t)M_ROWS * DI];
__device__ float g_z[(size_t)M_ROWS * DI];
__device__ float g_u[(size_t)M_ROWS * DI];
__device__ float g_delta[(size_t)M_ROWS * DI];
__device__ float g_dtr[(size_t)M_ROWS * DTR];
__device__ float g_Bs[(size_t)M_ROWS * DS];
__device__ float g_Cs[(size_t)M_ROWS * DS];
__device__ float g_y[(size_t)M_ROWS * DI];
__device__ float g_hpart[(size_t)NCH * BDN];
__device__ float g_aP[(size_t)NCH * BDN];
__device__ float g_hin[(size_t)NCH * BDN];
__device__ __nv_bfloat16 g_whi[(size_t)NX * CM];   // transposed: [n][k]
__device__ __nv_bfloat16 g_wlo[(size_t)NX * CM];

// ---------------- k_split_w: fp32 -> bf16 hi/lo (weights only) ----------------
__global__ void k_split_w(const float* __restrict__ Win)
{
    const int i = blockIdx.x * 256 + threadIdx.x;
    if (i >= CM * NX) return;
    const int k = i / NX, n = i % NX;
    const float v = Win[i];
    const __nv_bfloat16 h = __float2bfloat16(v);
    g_whi[(size_t)n * CM + k] = h;
    g_wlo[(size_t)n * CM + k] = __float2bfloat16(v - __bfloat162float(h));
}

// ---------------- K1: xz = x @ W_in via bf16x3 mma.sync + ldmatrix ----------------
#define KP 40   // bf16 row pitch (80B): conflict-free ldmatrix

__device__ __forceinline__ void mma_bf16(float* d, const uint32_t* a, const uint32_t* b)
{
    asm volatile(
        "mma.sync.aligned.m16n8k16.row.col.f32.bf16.bf16.f32 "
        "{%0,%1,%2,%3}, {%4,%5,%6,%7}, {%8,%9}, {%0,%1,%2,%3};"
        : "+f"(d[0]), "+f"(d[1]), "+f"(d[2]), "+f"(d[3])
        : "r"(a[0]), "r"(a[1]), "r"(a[2]), "r"(a[3]), "r"(b[0]), "r"(b[1]));
}
#define LDSM4(r0, r1, r2, r3, addr) \
    asm volatile("ldmatrix.sync.aligned.m8n8.x4.shared.b16 {%0,%1,%2,%3}, [%4];" \
                 : "=r"(r0), "=r"(r1), "=r"(r2), "=r"(r3) : "r"(addr))

__device__ __forceinline__ uint32_t sptr(const void* p)
{
    return (uint32_t)__cvta_generic_to_shared(p);
}

__global__ __launch_bounds__(256) void k_gemm_mma(const float* __restrict__ X)
{
    __shared__ __nv_bfloat16 sAh[128][KP], sAl[128][KP], sBh[128][KP], sBl[128][KP];
    const int tid = threadIdx.x;
    const int wid = tid >> 5, t = tid & 31;
    const int m0 = blockIdx.x * 128, n0 = blockIdx.y * 128;
    const int wr = wid & 3, wc = wid >> 2;
    const int g = t >> 2, c2 = (t & 3) * 2;
    const int qrow = ((t >> 3) & 1) * 8 + (t & 7);
    const int qcol = (t >> 4) * 8;

    float acc[2][8][4];
#pragma unroll
    for (int mt = 0; mt < 2; mt++)
#pragma unroll
        for (int nt = 0; nt < 8; nt++)
#pragma unroll
            for (int e = 0; e < 4; e++) acc[mt][nt][e] = 0.f;

    const int lr = tid >> 1;
    const int lh = (tid & 1) * 16;

    const float* xrow = X + (size_t)(m0 + lr) * CM + lh;
    const __nv_bfloat16* bhrow = g_whi + (size_t)(n0 + lr) * CM + lh;
    const __nv_bfloat16* blrow = g_wlo + (size_t)(n0 + lr) * CM + lh;

    // prefetch chunk 0
    float4 xv[4];
    uint4 bhv[2], blv[2];
#pragma unroll
    for (int q = 0; q < 4; q++) xv[q] = *(const float4*)(xrow + q * 4);
    bhv[0] = *(const uint4*)(bhrow);
    bhv[1] = *(const uint4*)(bhrow + 8);
    blv[0] = *(const uint4*)(blrow);
    blv[1] = *(const uint4*)(blrow + 8);

    for (int kc = 0; kc < CM; kc += 32) {
        // store current chunk (convert A in regs)
        {
            uint32_t hi[8], lo[8];
#pragma unroll
            for (int q = 0; q < 4; q++) {
                float4 v = xv[q];
                __nv_bfloat16 h0 = __float2bfloat16(v.x), h1 = __float2bfloat16(v.y),
                              h2 = __float2bfloat16(v.z), h3 = __float2bfloat16(v.w);
                __nv_bfloat162 H0(h0, h1), H1(h2, h3);
                __nv_bfloat162 L0(__float2bfloat16(v.x - __bfloat162float(h0)),
                                  __float2bfloat16(v.y - __bfloat162float(h1)));
                __nv_bfloat162 L1(__float2bfloat16(v.z - __bfloat162float(h2)),
                                  __float2bfloat16(v.w - __bfloat162float(h3)));
                hi[q * 2] = *(uint32_t*)&H0; hi[q * 2 + 1] = *(uint32_t*)&H1;
                lo[q * 2] = *(uint32_t*)&L0; lo[q * 2 + 1] = *(uint32_t*)&L1;
            }
            *(uint4*)&sAh[lr][lh]     = make_uint4(hi[0], hi[1], hi[2], hi[3]);
            *(uint4*)&sAh[lr][lh + 8] = make_uint4(hi[4], hi[5], hi[6], hi[7]);
            *(uint4*)&sAl[lr][lh]     = make_uint4(lo[0], lo[1], lo[2], lo[3]);
            *(uint4*)&sAl[lr][lh + 8] = make_uint4(lo[4], lo[5], lo[6], lo[7]);
            *(uint4*)&sBh[lr][lh]     = bhv[0];
            *(uint4*)&sBh[lr][lh + 8] = bhv[1];
            *(uint4*)&sBl[lr][lh]     = blv[0];
            *(uint4*)&sBl[lr][lh + 8] = blv[1];
        }
        __syncthreads();

        // prefetch next chunk (overlaps with MMA below)
        if (kc + 32 < CM) {
            const float* xp = xrow + kc + 32;
            const __nv_bfloat16* bh = bhrow + kc + 32;
            const __nv_bfloat16* bl = blrow + kc + 32;
#pragma unroll
            for (int q = 0; q < 4; q++) xv[q] = *(const float4*)(xp + q * 4);
            bhv[0] = *(const uint4*)(bh);
            bhv[1] = *(const uint4*)(bh + 8);
            blv[0] = *(const uint4*)(bl);
            blv[1] = *(const uint4*)(bl + 8);
        }

#pragma unroll
        for (int ks = 0; ks < 2; ks++) {
            const int K0 = ks * 16;
            uint32_t ahf[2][4], alf[2][4];
#pragma unroll
            for (int mt = 0; mt < 2; mt++) {
                const int R = wr * 32 + mt * 16 + qrow;
                LDSM4(ahf[mt][0], ahf[mt][1], ahf[mt][2], ahf[mt][3],
                      sptr(&sAh[R][K0 + qcol]));
                LDSM4(alf[mt][0], alf[mt][1], alf[mt][2], alf[mt][3],
                      sptr(&sAl[R][K0 + qcol]));
            }
#pragma unroll
            for (int ntp = 0; ntp < 4; ntp++) {
                const int N = wc * 64 + ntp * 16 + qrow;
                uint32_t h0, h1, h2, h3, l0, l1, l2, l3;
                LDSM4(h0, h1, h2, h3, sptr(&sBh[N][K0 + qcol]));
                LDSM4(l0, l1, l2, l3, sptr(&sBl[N][K0 + qcol]));
                uint32_t bhf0[2] = {h0, h2}, bhf1[2] = {h1, h3};
                uint32_t blf0[2] = {l0, l2}, blf1[2] = {l1, l3};
#pragma unroll
                for (int mt = 0; mt < 2; mt++) {
                    mma_bf16(acc[mt][ntp * 2],     ahf[mt], bhf0);
                    mma_bf16(acc[mt][ntp * 2],     ahf[mt], blf0);
                    mma_bf16(acc[mt][ntp * 2],     alf[mt], bhf0);
                    mma_bf16(acc[mt][ntp * 2 + 1], ahf[mt], bhf1);
                    mma_bf16(acc[mt][ntp * 2 + 1], ahf[mt], blf1);
                    mma_bf16(acc[mt][ntp * 2 + 1], alf[mt], bhf1);
                }
            }
        }
        __syncthreads();
    }

    const bool toZ = (n0 >= DI);
#pragma unroll
    for (int mt = 0; mt < 2; mt++) {
#pragma unroll
        for (int nt = 0; nt < 8; nt++) {
            int nc = n0 + wc * 64 + nt * 8 + c2;
            if (toZ) nc -= DI;
            const int r0 = m0 + wr * 32 + mt * 16 + g;
            float* base = toZ ? g_z : g_xi;
            *(float2*)&base[(size_t)r0 * DI + nc] =
                make_float2(acc[mt][nt][0], acc[mt][nt][1]);
            *(float2*)&base[(size_t)(r0 + 8) * DI + nc] =
                make_float2(acc[mt][nt][2], acc[mt][nt][3]);
        }
    }
}

// ---------------- conv: depthwise 3x3 + bias + SiLU, 8 outputs/thread ----------------
__global__ __launch_bounds__(1024) void k_conv(const float* __restrict__ cw,
                                               const float* __restrict__ cb)
{
    extern __shared__ float cs[];   // [100][128]
    const int b = blockIdx.z;
    const int d = blockIdx.y * 128 + threadIdx.x;
    const int h0 = (blockIdx.x >> 3) * 8;
    const int w0 = (blockIdx.x & 7) * 8;
    const int tx = threadIdx.x, ty = threadIdx.y;
    const size_t base = (size_t)b * L * DI;

#pragma unroll
    for (int i = 0; i < 13; i++) {
        const int p = ty + 8 * i;
        if (p < 100) {
            const int rr = p / 10, cc = p % 10;
            const int hh = h0 + rr - 1, ww = w0 + cc - 1;
            float v = 0.f;
            if (hh >= 0 && hh < 64 && ww >= 0 && ww < 64)
                v = g_xi[base + (size_t)(hh * 64 + ww) * DI + d];
            cs[p * 128 + tx] = v;
        }
    }
    __syncthreads();

    float W[9];
#pragma unroll
    for (int i = 0; i < 9; i++) W[i] = cw[d * 9 + i];
    const float bias = cb[d];

    float acc[8];
#pragma unroll
    for (int j = 0; j < 8; j++) acc[j] = bias;

#pragma unroll
    for (int r = 0; r < 3; r++) {
        float rv[10];
#pragma unroll
        for (int c = 0; c < 10; c++) rv[c] = cs[((ty + r) * 10 + c) * 128 + tx];
#pragma unroll
        for (int j = 0; j < 8; j++) {
            acc[j] = fmaf(rv[j],     W[r * 3 + 0], acc[j]);
            acc[j] = fmaf(rv[j + 1], W[r * 3 + 1], acc[j]);
            acc[j] = fmaf(rv[j + 2], W[r * 3 + 2], acc[j]);
        }
    }
#pragma unroll
    for (int j = 0; j < 8; j++) {
        const float sig = 1.f / (1.f + __expf(-acc[j]));
        g_u[base + (size_t)((h0 + ty) * 64 + w0 + j) * DI + d] = acc[j] * sig;
    }
}

// ---------------- k_xdbl: x_dbl = u @ Wx  (32-row tiles, 512 blocks) ----------------
__global__ __launch_bounds__(256) void k_xdbl(const float* __restrict__ Wx)
{
    __shared__ float Us[16][33];
    __shared__ float Wxs[16][48];
    const int tid = threadIdx.x;
    const int m0 = blockIdx.x * 32;
    const int tm = tid / 16, tn = tid % 16;

    float acc[2][3];
#pragma unroll
    for (int i = 0; i < 2; i++)
#pragma unroll
        for (int j = 0; j < 3; j++) acc[i][j] = 0.f;

    const int ur = tid / 8, ukq = (tid % 8) * 2;

    for (int k0 = 0; k0 < DI; k0 += 16) {
        float2 uv = *(const float2*)&g_u[(size_t)(m0 + ur) * DI + k0 + ukq];
        Us[ukq][ur] = uv.x;
        Us[ukq + 1][ur] = uv.y;
#pragma unroll
        for (int i = 0; i < 3; i++) {
            const int f = tid + i * 256;
            const int rr = f / 48, cc = f % 48;
            Wxs[rr][cc] = (cc < 44) ? Wx[(size_t)(k0 + rr) * 44 + cc] : 0.f;
        }
        __syncthreads();
#pragma unroll
        for (int k = 0; k < 16; k++) {
            const float a0 = Us[k][tm * 2], a1 = Us[k][tm * 2 + 1];
            const float b0 = Wxs[k][tn * 3 + 0];
            const float b1 = Wxs[k][tn * 3 + 1];
            const float b2 = Wxs[k][tn * 3 + 2];
            acc[0][0] = fmaf(a0, b0, acc[0][0]);
            acc[0][1] = fmaf(a0, b1, acc[0][1]);
            acc[0][2] = fmaf(a0, b2, acc[0][2]);
            acc[1][0] = fmaf(a1, b0, acc[1][0]);
            acc[1][1] = fmaf(a1, b1, acc[1][1]);
            acc[1][2] = fmaf(a1, b2, acc[1][2]);
        }
        __syncthreads();
    }
#pragma unroll
    for (int i = 0; i < 2; i++) {
        const size_t m = (size_t)(m0 + tm * 2 + i);
#pragma unroll
        for (int j = 0; j < 3; j++) {
            const int c = tn * 3 + j;
            const float v = acc[i][j];
            if (c < DTR)            g_dtr[m * DTR + c] = v;
            else if (c < DTR + DS)  g_Bs[m * DS + (c - DTR)] = v;
            else if (c < 44)        g_Cs[m * DS + (c - DTR - DS)] = v;
        }
    }
}

// ---------------- k_promptC: Cs += prompt @ Wp (16384 x 16, K=192) ----------------
__global__ void k_promptC(const float* __restrict__ prompt, const float* __restrict__ Wp)
{
    __shared__ float p[16 * 192];
    const int tid = threadIdx.x;
    const int row0 = blockIdx.x * 16;
    const float4* src = (const float4*)(prompt + (size_t)row0 * CM);
#pragma unroll
    for (int i = 0; i < 3; i++)
        ((float4*)p)[tid + i * 256] = src[tid + i * 256];
    __syncthreads();

    const int r = tid / 16, n = tid % 16;
    float a0 = 0.f, a1 = 0.f;
    const float* pr = p + r * CM;
#pragma unroll 8
    for (int k = 0; k < CM; k += 2) {
        a0 = fmaf(pr[k],     Wp[(size_t)k * DS + n],       a0);
        a1 = fmaf(pr[k + 1], Wp[(size_t)(k + 1) * DS + n], a1);
    }
    g_Cs[(size_t)(row0 + r) * DS + n] += a0 + a1;
}

// ---------------- k_delta ----------------
__global__ void k_delta(const float* __restrict__ Wdt, const float* __restrict__ bdt)
{
    __shared__ float sd[8][DTR];
    const int tid = threadIdx.x; // 384
    const int row0 = blockIdx.x * 8;
    if (tid < 8 * DTR) sd[tid / DTR][tid % DTR] = g_dtr[(size_t)(row0 + tid / DTR) * DTR + tid % DTR];
    __syncthreads();

    float w[DTR];
#pragma unroll
    for (int rr = 0; rr < DTR; rr++) w[rr] = Wdt[(size_t)rr * DI + tid];
    const float bb = bdt[tid];
#pragma unroll
    for (int rr = 0; rr < 8; rr++) {
        float acc = bb;
#pragma unroll
        for (int r2 = 0; r2 < DTR; r2++) acc = fmaf(sd[rr][r2], w[r2], acc);
        const float sp = acc > 20.f ? acc : log1pf(__expf(acc));
        g_delta[(size_t)(row0 + rr) * DI + tid] = sp;
    }
}

// ---------------- scan helpers ----------------
__device__ __forceinline__ void pow_chain(float e1, float* av)
{
    const float e2 = e1 * e1, e4 = e2 * e2, e8 = e4 * e4;
    av[0] = e1;       av[1] = e2;       av[2] = e2 * e1;   av[3] = e4;
    av[4] = e4 * e1;  av[5] = e4 * e2;  av[6] = e4 * av[2]; av[7] = e8;
    av[8] = e8 * e1;  av[9] = e8 * e2;  av[10] = e8 * av[2]; av[11] = e8 * e4;
    av[12] = e8 * av[4]; av[13] = e8 * av[5]; av[14] = e8 * av[6]; av[15] = e8 * e8;
}

__device__ __forceinline__ bool a_structured(const float* __restrict__ Alog, int d, float& A0)
{
    A0 = -__expf(Alog[(size_t)d * DS]);
    bool ok = true;
#pragma unroll
    for (int n = 1; n < DS; n++) {
        const float Av = -__expf(Alog[(size_t)d * DS + n]);
        ok &= fabsf(Av - (n + 1) * A0) <= 1e-4f * fabsf((n + 1) * A0);
    }
    return ok;
}

// ---------------- S1 ----------------
__global__ void k_scan1(const float* __restrict__ Alog)
{
    __shared__ float sB[CHL][DS];
    const int d = blockIdx.x * 128 + threadIdx.x;
    const int c = blockIdx.y;
    const int b = blockIdx.z;
    const int l0 = c * CHL;

    {
        const float4* src = (const float4*)g_Bs + ((size_t)b * L + l0) * 4;
        ((float4*)sB)[threadIdx.x] = src[threadIdx.x];
    }

    float A0;
    const bool st = a_structured(Alog, d, A0);
    __syncthreads();

    float h[DS];
#pragma unroll
    for (int n = 0; n < DS; n++) h[n] = 0.f;
    float dsum = 0.f;

    const float* dp = g_delta + ((size_t)b * L + l0) * DI + d;
    const float* up = g_u + ((size_t)b * L + l0) * DI + d;

    if (st) {
        for (int l = 0; l < CHL; l++) {
            const float dl = dp[(size_t)l * DI];
            const float du = dl * up[(size_t)l * DI];
            dsum += dl;
            float av[DS];
            pow_chain(__expf(dl * A0), av);
#pragma unroll
            for (int n = 0; n < DS; n++) h[n] = fmaf(av[n], h[n], du * sB[l][n]);
        }
        float av[DS];
        pow_chain(__expf(dsum * A0), av);
        const size_t base = (size_t)c * BDN + ((size_t)b * DI + d) * DS;
#pragma unroll
        for (int n = 0; n < DS; n++) {
            g_hpart[base + n] = h[n];
            g_aP[base + n] = av[n];
        }
    } else {
        float A[DS];
#pragma unroll
        for (int n = 0; n < DS; n++) A[n] = -__expf(Alog[(size_t)d * DS + n]);
        for (int l = 0; l < CHL; l++) {
            const float dl = dp[(size_t)l * DI];
            const float du = dl * up[(size_t)l * DI];
            dsum += dl;
#pragma unroll
            for (int n = 0; n < DS; n++)
                h[n] = fmaf(__expf(dl * A[n]), h[n], du * sB[l][n]);
        }
        const size_t base = (size_t)c * BDN + ((size_t)b * DI + d) * DS;
#pragma unroll
        for (int n = 0; n < DS; n++) {
            g_hpart[base + n] = h[n];
            g_aP[base + n] = __expf(A[n] * dsum);
        }
    }
}

// ---------------- S2 ----------------
__global__ void k_scan2()
{
    const int idx = blockIdx.x * 256 + threadIdx.x;
    if (idx >= BDN) return;
    float h = 0.f;
    for (int c = 0; c < NCH; c++) {
        const size_t o = (size_t)c * BDN + idx;
        g_hin[o] = h;
        h = fmaf(g_aP[o], h, g_hpart[o]);
    }
}

// ---------------- S3 ----------------
__global__ void k_scan3(const float* __restrict__ Alog, const float* __restrict__ Dvec)
{
    __shared__ float sB[CHL][DS];
    __shared__ float sC[CHL][DS];
    const int d = blockIdx.x * 128 + threadIdx.x;
    const int c = blockIdx.y;
    const int b = blockIdx.z;
    const int l0 = c * CHL;

    {
        const float4* srcB = (const float4*)g_Bs + ((size_t)b * L + l0) * 4;
        const float4* srcC = (const float4*)g_Cs + ((size_t)b * L + l0) * 4;
        ((float4*)sB)[threadIdx.x] = srcB[threadIdx.x];
        ((float4*)sC)[threadIdx.x] = srcC[threadIdx.x];
    }

    float A0;
    const bool st = a_structured(Alog, d, A0);
    const float Dd = Dvec[d];
    __syncthreads();

    float h[DS];
    {
        const size_t base = (size_t)c * BDN + ((size_t)b * DI + d) * DS;
#pragma unroll
        for (int n = 0; n < DS; n++) h[n] = g_hin[base + n];
    }

    const float* dp = g_delta + ((size_t)b * L + l0) * DI + d;
    const float* up = g_u + ((size_t)b * L + l0) * DI + d;
    float* yp = g_y + ((size_t)b * L + l0) * DI + d;

    if (st) {
        for (int l = 0; l < CHL; l++) {
            const float dl = dp[(size_t)l * DI];
            const float uu = up[(size_t)l * DI];
            const float du = dl * uu;
            float av[DS];
            pow_chain(__expf(dl * A0), av);
            float y = uu * Dd;
#pragma unroll
            for (int n = 0; n < DS; n++) {
                h[n] = fmaf(av[n], h[n], du * sB[l][n]);
                y = fmaf(h[n], sC[l][n], y);
            }
            yp[(size_t)l * DI] = y;
        }
    } else {
        float A[DS];
#pragma unroll
        for (int n = 0; n < DS; n++) A[n] = -__expf(Alog[(size_t)d * DS + n]);
        for (int l = 0; l < CHL; l++) {
            const float dl = dp[(size_t)l * DI];
            const float uu = up[(size_t)l * DI];
            const float du = dl * uu;
            float y = uu * Dd;
#pragma unroll
            for (int n = 0; n < DS; n++) {
                h[n] = fmaf(__expf(dl * A[n]), h[n], du * sB[l][n]);
                y = fmaf(h[n], sC[l][n], y);
            }
            yp[(size_t)l * DI] = y;
        }
    }
}

// ---------------- K4: LayerNorm + SiLU gate + out GEMM ----------------
__global__ void k_out(const float* __restrict__ lng, const float* __restrict__ lnb,
                      const float* __restrict__ Wout, float* __restrict__ out)
{
    __shared__ float yg[16][DI];
    __shared__ float Wt[16][CM];
    const int tid = threadIdx.x; // 256
    const int r0 = blockIdx.x * 16;
    const int warp = tid >> 5, lane = tid & 31;

#pragma unroll
    for (int rr = 0; rr < 2; rr++) {
        const int r = warp * 2 + rr;
        const size_t row = (size_t)(r0 + r);
        float v[12];
        float s = 0.f, sq = 0.f;
#pragma unroll
        for (int i = 0; i < 12; i++) {
            v[i] = g_y[row * DI + lane + 32 * i];
            s += v[i];
            sq = fmaf(v[i], v[i], sq);
        }
#pragma unroll
        for (int o = 16; o > 0; o >>= 1) {
            s += __shfl_xor_sync(0xFFFFFFFFu, s, o);
            sq += __shfl_xor_sync(0xFFFFFFFFu, sq, o);
        }
        const float mu = s * (1.f / DI);
        const float var = sq * (1.f / DI) - mu * mu;
        const float rs = rsqrtf(var + 1e-5f);
#pragma unroll
        for (int i = 0; i < 12; i++) {
            const int k = lane + 32 * i;
            const float zn = g_z[row * DI + k];
            const float sig = 1.f / (1.f + __expf(-zn));
            const float g = fmaf((v[i] - mu) * rs, lng[k], lnb[k]);
            yg[r][k] = g * zn * sig;
        }
    }
    __syncthreads();

    const int tr = tid >> 6;
    const int tc = tid & 63;
    float acc[4][3];
#pragma unroll
    for (int r = 0; r < 4; r++)
#pragma unroll
        for (int cc = 0; cc < 3; cc++) acc[r][cc] = 0.f;

    for (int kt = 0; kt < DI; kt += 16) {
#pragma unroll
        for (int i = 0; i < 3; i++) {
            const int e = tid + i * 256;
            const int kr = e / 48;
            const int c4 = (e % 48) * 4;
            *(float4*)&Wt[kr][c4] = *(const float4*)&Wout[(size_t)(kt + kr) * CM + c4];
        }
        __syncthreads();
#pragma unroll
        for (int k = 0; k < 16; k++) {
            const float w0 = Wt[k][tc * 3 + 0];
            const float w1 = Wt[k][tc * 3 + 1];
            const float w2 = Wt[k][tc * 3 + 2];
#pragma unroll
            for (int r = 0; r < 4; r++) {
                const float a = yg[tr * 4 + r][kt + k];
                acc[r][0] = fmaf(a, w0, acc[r][0]);
                acc[r][1] = fmaf(a, w1, acc[r][1]);
                acc[r][2] = fmaf(a, w2, acc[r][2]);
            }
        }
        __syncthreads();
    }
#pragma unroll
    for (int r = 0; r < 4; r++) {
        const size_t row = (size_t)(r0 + tr * 4 + r);
#pragma unroll
        for (int cc = 0; cc < 3; cc++)
            out[row * CM + tc * 3 + cc] = acc[r][cc];
    }
}

// ---------------- launch ----------------
extern "C" void kernel_launch(void* const* d_in, const int* in_sizes, int n_in,
                              void* d_out, int out_size)
{
    const float* x      = (const float*)d_in[0];
    const float* prompt = (const float*)d_in[1];
    const float* W_in   = (const float*)d_in[2];
    const float* conv_w = (const float*)d_in[3];
    const float* conv_b = (const float*)d_in[4];
    const float* Wx     = (const float*)d_in[5];
    const float* Wdt    = (const float*)d_in[6];
    const float* b_dt   = (const float*)d_in[7];
    const float* A_log  = (const float*)d_in[8];
    const float* Dv     = (const float*)d_in[9];
    const float* Wp     = (const float*)d_in[10];
    const float* ln_g   = (const float*)d_in[11];
    const float* ln_b   = (const float*)d_in[12];
    const float* Wout   = (const float*)d_in[13];
    float* out = (float*)d_out;

    static bool attr_set = false;
    if (!attr_set) {
        cudaFuncSetAttribute(k_conv, cudaFuncAttributeMaxDynamicSharedMemorySize, 51200);
        attr_set = true;
    }

    k_split_w<<<(CM * NX + 255) / 256, 256>>>(W_in);
    k_gemm_mma<<<dim3(M_ROWS / 128, NX / 128), 256>>>(x);
    k_conv<<<dim3(64, 3, BATCH), dim3(128, 8), 51200>>>(conv_w, conv_b);
    k_xdbl<<<M_ROWS / 32, 256>>>(Wx);
    k_promptC<<<M_ROWS / 16, 256>>>(prompt, Wp);
    k_delta<<<M_ROWS / 8, DI>>>(Wdt, b_dt);
    k_scan1<<<dim3(DI / 128, NCH, BATCH), 128>>>(A_log);
    k_scan2<<<(BDN + 255) / 256, 256>>>();
    k_scan3<<<dim3(DI / 128, NCH, BATCH), 128>>>(A_log, Dv);
    k_out<<<M_ROWS / 16, 256>>>(ln_g, ln_b, Wout, out);
}

// round 8
// speedup vs baseline: 1.1693x; 1.1108x over previous
#include <cuda_runtime.h>
#include <cuda_bf16.h>
#include <cstdint>

#define BATCH 4
#define L 4096
#define CM 192
#define DI 384
#define DS 16
#define DTR 12
#define M_ROWS (BATCH * L)   // 16384
#define NCH 128
#define CHL (L / NCH)        // 32
#define BDN (BATCH * DI * DS) // 24576
#define NX (2 * DI)          // 768

// ---------------- scratch (device globals; no allocation) ----------------
__device__ float g_xi[(size_t)M_ROWS * DI];
__device__ float g_z[(size_t)M_ROWS * DI];
__device__ float g_u[(size_t)M_ROWS * DI];
__device__ float g_delta[(size_t)M_ROWS * DI];
__device__ float g_dtr[(size_t)M_ROWS * DTR];
__device__ float g_Bs[(size_t)M_ROWS * DS];
__device__ float g_Cs[(size_t)M_ROWS * DS];
__device__ float g_y[(size_t)M_ROWS * DI];
__device__ float g_hpart[(size_t)NCH * BDN];
__device__ float g_aP[(size_t)NCH * BDN];
__device__ float g_hin[(size_t)NCH * BDN];
__device__ float g_wt[(size_t)NX * CM];   // W_in transposed [n][k], tf32-rounded

__device__ __forceinline__ uint32_t f2tf32(float f)
{
    uint32_t r;
    asm("cvt.rna.tf32.f32 %0, %1;" : "=r"(r) : "f"(f));
    return r;
}

// ---------------- k_prep_w: transpose + tf32-round W_in ----------------
__global__ void k_prep_w(const float* __restrict__ Win)
{
    const int i = blockIdx.x * 256 + threadIdx.x;
    if (i >= CM * NX) return;
    const int k = i / NX, n = i % NX;
    g_wt[(size_t)n * CM + k] = __uint_as_float(f2tf32(Win[i]));
}

// ---------------- K1: xz = x @ W_in via single-pass tf32 mma.sync ----------------
#define AP 36   // fp32 row pitch: (4g+c) bank pattern, conflict-free

__device__ __forceinline__ void mma_tf32(float* d, const uint32_t* a, const uint32_t* b)
{
    asm volatile(
        "mma.sync.aligned.m16n8k8.row.col.f32.tf32.tf32.f32 "
        "{%0,%1,%2,%3}, {%4,%5,%6,%7}, {%8,%9}, {%0,%1,%2,%3};"
        : "+f"(d[0]), "+f"(d[1]), "+f"(d[2]), "+f"(d[3])
        : "r"(a[0]), "r"(a[1]), "r"(a[2]), "r"(a[3]), "r"(b[0]), "r"(b[1]));
}

__global__ __launch_bounds__(256) void k_gemm_tf32(const float* __restrict__ X)
{
    __shared__ float sA[128][AP], sB[128][AP];
    const int tid = threadIdx.x;
    const int wid = tid >> 5, t = tid & 31;
    const int m0 = blockIdx.x * 128, n0 = blockIdx.y * 128;
    const int wr = wid & 3, wc = wid >> 2;
    const int g = t >> 2, c = t & 3, c2 = c * 2;

    float acc[2][8][4];
#pragma unroll
    for (int mt = 0; mt < 2; mt++)
#pragma unroll
        for (int nt = 0; nt < 8; nt++)
#pragma unroll
            for (int e = 0; e < 4; e++) acc[mt][nt][e] = 0.f;

    const int lr = tid >> 1;            // row 0..127
    const int lh = (tid & 1) * 16;      // 16-float half

    for (int kc = 0; kc < CM; kc += 32) {
        {
            const float* xp = X + (size_t)(m0 + lr) * CM + kc + lh;
#pragma unroll
            for (int q = 0; q < 4; q++) {
                float4 v = *(const float4*)(xp + q * 4);
                sA[lr][lh + q * 4 + 0] = __uint_as_float(f2tf32(v.x));
                sA[lr][lh + q * 4 + 1] = __uint_as_float(f2tf32(v.y));
                sA[lr][lh + q * 4 + 2] = __uint_as_float(f2tf32(v.z));
                sA[lr][lh + q * 4 + 3] = __uint_as_float(f2tf32(v.w));
            }
            const float* wp = g_wt + (size_t)(n0 + lr) * CM + kc + lh;
#pragma unroll
            for (int q = 0; q < 4; q++)
                *(float4*)&sB[lr][lh + q * 4] = *(const float4*)(wp + q * 4);
        }
        __syncthreads();

#pragma unroll
        for (int ks = 0; ks < 4; ks++) {
            const int K0 = ks * 8;
            uint32_t af[2][4];
#pragma unroll
            for (int mt = 0; mt < 2; mt++) {
                const int R = wr * 32 + mt * 16;
                af[mt][0] = *(const uint32_t*)&sA[R + g][K0 + c];
                af[mt][1] = *(const uint32_t*)&sA[R + g + 8][K0 + c];
                af[mt][2] = *(const uint32_t*)&sA[R + g][K0 + c + 4];
                af[mt][3] = *(const uint32_t*)&sA[R + g + 8][K0 + c + 4];
            }
#pragma unroll
            for (int nt = 0; nt < 8; nt++) {
                const int N = wc * 64 + nt * 8;
                uint32_t bf[2];
                bf[0] = *(const uint32_t*)&sB[N + g][K0 + c];
                bf[1] = *(const uint32_t*)&sB[N + g][K0 + c + 4];
#pragma unroll
                for (int mt = 0; mt < 2; mt++)
                    mma_tf32(acc[mt][nt], af[mt], bf);
            }
        }
        __syncthreads();
    }

    const bool toZ = (n0 >= DI);
#pragma unroll
    for (int mt = 0; mt < 2; mt++) {
#pragma unroll
        for (int nt = 0; nt < 8; nt++) {
            int nc = n0 + wc * 64 + nt * 8 + c2;
            if (toZ) nc -= DI;
            const int r0 = m0 + wr * 32 + mt * 16 + g;
            float* base = toZ ? g_z : g_xi;
            *(float2*)&base[(size_t)r0 * DI + nc] =
                make_float2(acc[mt][nt][0], acc[mt][nt][1]);
            *(float2*)&base[(size_t)(r0 + 8) * DI + nc] =
                make_float2(acc[mt][nt][2], acc[mt][nt][3]);
        }
    }
}

// ---------------- conv: depthwise 3x3 + bias + SiLU, 8 outputs/thread ----------------
__global__ __launch_bounds__(1024) void k_conv(const float* __restrict__ cw,
                                               const float* __restrict__ cb)
{
    extern __shared__ float cs[];   // [100][128]
    const int b = blockIdx.z;
    const int d = blockIdx.y * 128 + threadIdx.x;
    const int h0 = (blockIdx.x >> 3) * 8;
    const int w0 = (blockIdx.x & 7) * 8;
    const int tx = threadIdx.x, ty = threadIdx.y;
    const size_t base = (size_t)b * L * DI;

#pragma unroll
    for (int i = 0; i < 13; i++) {
        const int p = ty + 8 * i;
        if (p < 100) {
            const int rr = p / 10, cc = p % 10;
            const int hh = h0 + rr - 1, ww = w0 + cc - 1;
            float v = 0.f;
            if (hh >= 0 && hh < 64 && ww >= 0 && ww < 64)
                v = g_xi[base + (size_t)(hh * 64 + ww) * DI + d];
            cs[p * 128 + tx] = v;
        }
    }
    __syncthreads();

    float W[9];
#pragma unroll
    for (int i = 0; i < 9; i++) W[i] = cw[d * 9 + i];
    const float bias = cb[d];

    float acc[8];
#pragma unroll
    for (int j = 0; j < 8; j++) acc[j] = bias;

#pragma unroll
    for (int r = 0; r < 3; r++) {
        float rv[10];
#pragma unroll
        for (int cc = 0; cc < 10; cc++) rv[cc] = cs[((ty + r) * 10 + cc) * 128 + tx];
#pragma unroll
        for (int j = 0; j < 8; j++) {
            acc[j] = fmaf(rv[j],     W[r * 3 + 0], acc[j]);
            acc[j] = fmaf(rv[j + 1], W[r * 3 + 1], acc[j]);
            acc[j] = fmaf(rv[j + 2], W[r * 3 + 2], acc[j]);
        }
    }
#pragma unroll
    for (int j = 0; j < 8; j++) {
        const float sig = 1.f / (1.f + __expf(-acc[j]));
        g_u[base + (size_t)((h0 + ty) * 64 + w0 + j) * DI + d] = acc[j] * sig;
    }
}

// ---------------- k_xdbl: x_dbl = u @ Wx  (16384 x 44, K=384), R5 version ----------------
__global__ __launch_bounds__(256) void k_xdbl(const float* __restrict__ Wx)
{
    __shared__ float Us[16][64];
    __shared__ float Wxs[16][48];
    const int tid = threadIdx.x;
    const int m0 = blockIdx.x * 64;
    const int tm = tid / 16, tn = tid % 16;

    float acc[4][3];
#pragma unroll
    for (int i = 0; i < 4; i++)
#pragma unroll
        for (int j = 0; j < 3; j++) acc[i][j] = 0.f;

    const int urow = tid / 4, ukq = (tid % 4) * 4;

    for (int k0 = 0; k0 < DI; k0 += 16) {
        float4 uv = *(const float4*)&g_u[(size_t)(m0 + urow) * DI + k0 + ukq];
        Us[ukq + 0][urow] = uv.x;
        Us[ukq + 1][urow] = uv.y;
        Us[ukq + 2][urow] = uv.z;
        Us[ukq + 3][urow] = uv.w;
#pragma unroll
        for (int i = 0; i < 3; i++) {
            const int f = tid + i * 256;
            const int rr = f / 48, cc = f % 48;
            Wxs[rr][cc] = (cc < 44) ? Wx[(size_t)(k0 + rr) * 44 + cc] : 0.f;
        }
        __syncthreads();
#pragma unroll
        for (int k = 0; k < 16; k++) {
            float4 a4 = *(const float4*)&Us[k][tm * 4];
            float a[4] = {a4.x, a4.y, a4.z, a4.w};
            float b0 = Wxs[k][tn * 3 + 0];
            float b1 = Wxs[k][tn * 3 + 1];
            float b2 = Wxs[k][tn * 3 + 2];
#pragma unroll
            for (int i = 0; i < 4; i++) {
                acc[i][0] = fmaf(a[i], b0, acc[i][0]);
                acc[i][1] = fmaf(a[i], b1, acc[i][1]);
                acc[i][2] = fmaf(a[i], b2, acc[i][2]);
            }
        }
        __syncthreads();
    }
#pragma unroll
    for (int i = 0; i < 4; i++) {
        const size_t m = (size_t)(m0 + tm * 4 + i);
#pragma unroll
        for (int j = 0; j < 3; j++) {
            const int cc = tn * 3 + j;
            const float v = acc[i][j];
            if (cc < DTR)            g_dtr[m * DTR + cc] = v;
            else if (cc < DTR + DS)  g_Bs[m * DS + (cc - DTR)] = v;
            else if (cc < 44)        g_Cs[m * DS + (cc - DTR - DS)] = v;
        }
    }
}

// ---------------- k_promptC: Cs += prompt @ Wp (16384 x 16, K=192) ----------------
__global__ void k_promptC(const float* __restrict__ prompt, const float* __restrict__ Wp)
{
    __shared__ float p[16 * 192];
    const int tid = threadIdx.x;
    const int row0 = blockIdx.x * 16;
    const float4* src = (const float4*)(prompt + (size_t)row0 * CM);
#pragma unroll
    for (int i = 0; i < 3; i++)
        ((float4*)p)[tid + i * 256] = src[tid + i * 256];
    __syncthreads();

    const int r = tid / 16, n = tid % 16;
    float a0 = 0.f, a1 = 0.f;
    const float* pr = p + r * CM;
#pragma unroll 8
    for (int k = 0; k < CM; k += 2) {
        a0 = fmaf(pr[k],     Wp[(size_t)k * DS + n],       a0);
        a1 = fmaf(pr[k + 1], Wp[(size_t)(k + 1) * DS + n], a1);
    }
    g_Cs[(size_t)(row0 + r) * DS + n] += a0 + a1;
}

// ---------------- k_delta ----------------
__global__ void k_delta(const float* __restrict__ Wdt, const float* __restrict__ bdt)
{
    __shared__ float sd[8][DTR];
    const int tid = threadIdx.x; // 384
    const int row0 = blockIdx.x * 8;
    if (tid < 8 * DTR) sd[tid / DTR][tid % DTR] = g_dtr[(size_t)(row0 + tid / DTR) * DTR + tid % DTR];
    __syncthreads();

    float w[DTR];
#pragma unroll
    for (int rr = 0; rr < DTR; rr++) w[rr] = Wdt[(size_t)rr * DI + tid];
    const float bb = bdt[tid];
#pragma unroll
    for (int rr = 0; rr < 8; rr++) {
        float acc = bb;
#pragma unroll
        for (int r2 = 0; r2 < DTR; r2++) acc = fmaf(sd[rr][r2], w[r2], acc);
        const float sp = acc > 20.f ? acc : log1pf(__expf(acc));
        g_delta[(size_t)(row0 + rr) * DI + tid] = sp;
    }
}

// ---------------- scan helpers ----------------
__device__ __forceinline__ void pow_chain(float e1, float* av)
{
    const float e2 = e1 * e1, e4 = e2 * e2, e8 = e4 * e4;
    av[0] = e1;       av[1] = e2;       av[2] = e2 * e1;   av[3] = e4;
    av[4] = e4 * e1;  av[5] = e4 * e2;  av[6] = e4 * av[2]; av[7] = e8;
    av[8] = e8 * e1;  av[9] = e8 * e2;  av[10] = e8 * av[2]; av[11] = e8 * e4;
    av[12] = e8 * av[4]; av[13] = e8 * av[5]; av[14] = e8 * av[6]; av[15] = e8 * e8;
}

__device__ __forceinline__ bool a_structured(const float* __restrict__ Alog, int d, float& A0)
{
    A0 = -__expf(Alog[(size_t)d * DS]);
    bool ok = true;
#pragma unroll
    for (int n = 1; n < DS; n++) {
        const float Av = -__expf(Alog[(size_t)d * DS + n]);
        ok &= fabsf(Av - (n + 1) * A0) <= 1e-4f * fabsf((n + 1) * A0);
    }
    return ok;
}

// ---------------- S1 ----------------
__global__ void k_scan1(const float* __restrict__ Alog)
{
    __shared__ float sB[CHL][DS];
    const int d = blockIdx.x * 128 + threadIdx.x;
    const int c = blockIdx.y;
    const int b = blockIdx.z;
    const int l0 = c * CHL;

    {
        const float4* src = (const float4*)g_Bs + ((size_t)b * L + l0) * 4;
        ((float4*)sB)[threadIdx.x] = src[threadIdx.x];
    }

    float A0;
    const bool st = a_structured(Alog, d, A0);
    __syncthreads();

    float h[DS];
#pragma unroll
    for (int n = 0; n < DS; n++) h[n] = 0.f;
    float dsum = 0.f;

    const float* dp = g_delta + ((size_t)b * L + l0) * DI + d;
    const float* up = g_u + ((size_t)b * L + l0) * DI + d;

    if (st) {
        for (int l = 0; l < CHL; l++) {
            const float dl = dp[(size_t)l * DI];
            const float du = dl * up[(size_t)l * DI];
            dsum += dl;
            float av[DS];
            pow_chain(__expf(dl * A0), av);
#pragma unroll
            for (int n = 0; n < DS; n++) h[n] = fmaf(av[n], h[n], du * sB[l][n]);
        }
        float av[DS];
        pow_chain(__expf(dsum * A0), av);
        const size_t base = (size_t)c * BDN + ((size_t)b * DI + d) * DS;
#pragma unroll
        for (int n = 0; n < DS; n++) {
            g_hpart[base + n] = h[n];
            g_aP[base + n] = av[n];
        }
    } else {
        float A[DS];
#pragma unroll
        for (int n = 0; n < DS; n++) A[n] = -__expf(Alog[(size_t)d * DS + n]);
        for (int l = 0; l < CHL; l++) {
            const float dl = dp[(size_t)l * DI];
            const float du = dl * up[(size_t)l * DI];
            dsum += dl;
#pragma unroll
            for (int n = 0; n < DS; n++)
                h[n] = fmaf(__expf(dl * A[n]), h[n], du * sB[l][n]);
        }
        const size_t base = (size_t)c * BDN + ((size_t)b * DI + d) * DS;
#pragma unroll
        for (int n = 0; n < DS; n++) {
            g_hpart[base + n] = h[n];
            g_aP[base + n] = __expf(A[n] * dsum);
        }
    }
}

// ---------------- S2 ----------------
__global__ void k_scan2()
{
    const int idx = blockIdx.x * 256 + threadIdx.x;
    if (idx >= BDN) return;
    float h = 0.f;
    for (int c = 0; c < NCH; c++) {
        const size_t o = (size_t)c * BDN + idx;
        g_hin[o] = h;
        h = fmaf(g_aP[o], h, g_hpart[o]);
    }
}

// ---------------- S3 ----------------
__global__ void k_scan3(const float* __restrict__ Alog, const float* __restrict__ Dvec)
{
    __shared__ float sB[CHL][DS];
    __shared__ float sC[CHL][DS];
    const int d = blockIdx.x * 128 + threadIdx.x;
    const int c = blockIdx.y;
    const int b = blockIdx.z;
    const int l0 = c * CHL;

    {
        const float4* srcB = (const float4*)g_Bs + ((size_t)b * L + l0) * 4;
        const float4* srcC = (const float4*)g_Cs + ((size_t)b * L + l0) * 4;
        ((float4*)sB)[threadIdx.x] = srcB[threadIdx.x];
        ((float4*)sC)[threadIdx.x] = srcC[threadIdx.x];
    }

    float A0;
    const bool st = a_structured(Alog, d, A0);
    const float Dd = Dvec[d];
    __syncthreads();

    float h[DS];
    {
        const size_t base = (size_t)c * BDN + ((size_t)b * DI + d) * DS;
#pragma unroll
        for (int n = 0; n < DS; n++) h[n] = g_hin[base + n];
    }

    const float* dp = g_delta + ((size_t)b * L + l0) * DI + d;
    const float* up = g_u + ((size_t)b * L + l0) * DI + d;
    float* yp = g_y + ((size_t)b * L + l0) * DI + d;

    if (st) {
        for (int l = 0; l < CHL; l++) {
            const float dl = dp[(size_t)l * DI];
            const float uu = up[(size_t)l * DI];
            const float du = dl * uu;
            float av[DS];
            pow_chain(__expf(dl * A0), av);
            float y = uu * Dd;
#pragma unroll
            for (int n = 0; n < DS; n++) {
                h[n] = fmaf(av[n], h[n], du * sB[l][n]);
                y = fmaf(h[n], sC[l][n], y);
            }
            yp[(size_t)l * DI] = y;
        }
    } else {
        float A[DS];
#pragma unroll
        for (int n = 0; n < DS; n++) A[n] = -__expf(Alog[(size_t)d * DS + n]);
        for (int l = 0; l < CHL; l++) {
            const float dl = dp[(size_t)l * DI];
            const float uu = up[(size_t)l * DI];
            const float du = dl * uu;
            float y = uu * Dd;
#pragma unroll
            for (int n = 0; n < DS; n++) {
                h[n] = fmaf(__expf(dl * A[n]), h[n], du * sB[l][n]);
                y = fmaf(h[n], sC[l][n], y);
            }
            yp[(size_t)l * DI] = y;
        }
    }
}

// ---------------- K4: LayerNorm + SiLU gate + out GEMM ----------------
__global__ void k_out(const float* __restrict__ lng, const float* __restrict__ lnb,
                      const float* __restrict__ Wout, float* __restrict__ out)
{
    __shared__ float yg[16][DI];
    __shared__ float Wt[16][CM];
    const int tid = threadIdx.x; // 256
    const int r0 = blockIdx.x * 16;
    const int warp = tid >> 5, lane = tid & 31;

#pragma unroll
    for (int rr = 0; rr < 2; rr++) {
        const int r = warp * 2 + rr;
        const size_t row = (size_t)(r0 + r);
        float v[12];
        float s = 0.f, sq = 0.f;
#pragma unroll
        for (int i = 0; i < 12; i++) {
            v[i] = g_y[row * DI + lane + 32 * i];
            s += v[i];
            sq = fmaf(v[i], v[i], sq);
        }
#pragma unroll
        for (int o = 16; o > 0; o >>= 1) {
            s += __shfl_xor_sync(0xFFFFFFFFu, s, o);
            sq += __shfl_xor_sync(0xFFFFFFFFu, sq, o);
        }
        const float mu = s * (1.f / DI);
        const float var = sq * (1.f / DI) - mu * mu;
        const float rs = rsqrtf(var + 1e-5f);
#pragma unroll
        for (int i = 0; i < 12; i++) {
            const int k = lane + 32 * i;
            const float zn = g_z[row * DI + k];
            const float sig = 1.f / (1.f + __expf(-zn));
            const float g = fmaf((v[i] - mu) * rs, lng[k], lnb[k]);
            yg[r][k] = g * zn * sig;
        }
    }
    __syncthreads();

    const int tr = tid >> 6;
    const int tc = tid & 63;
    float acc[4][3];
#pragma unroll
    for (int r = 0; r < 4; r++)
#pragma unroll
        for (int cc = 0; cc < 3; cc++) acc[r][cc] = 0.f;

    for (int kt = 0; kt < DI; kt += 16) {
#pragma unroll
        for (int i = 0; i < 3; i++) {
            const int e = tid + i * 256;
            const int kr = e / 48;
            const int c4 = (e % 48) * 4;
            *(float4*)&Wt[kr][c4] = *(const float4*)&Wout[(size_t)(kt + kr) * CM + c4];
        }
        __syncthreads();
#pragma unroll
        for (int k = 0; k < 16; k++) {
            const float w0 = Wt[k][tc * 3 + 0];
            const float w1 = Wt[k][tc * 3 + 1];
            const float w2 = Wt[k][tc * 3 + 2];
#pragma unroll
            for (int r = 0; r < 4; r++) {
                const float a = yg[tr * 4 + r][kt + k];
                acc[r][0] = fmaf(a, w0, acc[r][0]);
                acc[r][1] = fmaf(a, w1, acc[r][1]);
                acc[r][2] = fmaf(a, w2, acc[r][2]);
            }
        }
        __syncthreads();
    }
#pragma unroll
    for (int r = 0; r < 4; r++) {
        const size_t row = (size_t)(r0 + tr * 4 + r);
#pragma unroll
        for (int cc = 0; cc < 3; cc++)
            out[row * CM + tc * 3 + cc] = acc[r][cc];
    }
}

// ---------------- launch ----------------
extern "C" void kernel_launch(void* const* d_in, const int* in_sizes, int n_in,
                              void* d_out, int out_size)
{
    const float* x      = (const float*)d_in[0];
    const float* prompt = (const float*)d_in[1];
    const float* W_in   = (const float*)d_in[2];
    const float* conv_w = (const float*)d_in[3];
    const float* conv_b = (const float*)d_in[4];
    const float* Wx     = (const float*)d_in[5];
    const float* Wdt    = (const float*)d_in[6];
    const float* b_dt   = (const float*)d_in[7];
    const float* A_log  = (const float*)d_in[8];
    const float* Dv     = (const float*)d_in[9];
    const float* Wp     = (const float*)d_in[10];
    const float* ln_g   = (const float*)d_in[11];
    const float* ln_b   = (const float*)d_in[12];
    const float* Wout   = (const float*)d_in[13];
    float* out = (float*)d_out;

    static bool attr_set = false;
    if (!attr_set) {
        cudaFuncSetAttribute(k_conv, cudaFuncAttributeMaxDynamicSharedMemorySize, 51200);
        attr_set = true;
    }

    k_prep_w<<<(CM * NX + 255) / 256, 256>>>(W_in);
    k_gemm_tf32<<<dim3(M_ROWS / 128, NX / 128), 256>>>(x);
    k_conv<<<dim3(64, 3, BATCH), dim3(128, 8), 51200>>>(conv_w, conv_b);
    k_xdbl<<<M_ROWS / 64, 256>>>(Wx);
    k_promptC<<<M_ROWS / 16, 256>>>(prompt, Wp);
    k_delta<<<M_ROWS / 8, DI>>>(Wdt, b_dt);
    k_scan1<<<dim3(DI / 128, NCH, BATCH), 128>>>(A_log);
    k_scan2<<<(BDN + 255) / 256, 256>>>();
    k_scan3<<<dim3(DI / 128, NCH, BATCH), 128>>>(A_log, Dv);
    k_out<<<M_ROWS / 16, 256>>>(ln_g, ln_b, Wout, out);
}

// round 9
// speedup vs baseline: 1.1710x; 1.0015x over previous
#include <cuda_runtime.h>
#include <cuda_bf16.h>
#include <cstdint>

#define BATCH 4
#define L 4096
#define CM 192
#define DI 384
#define DS 16
#define DTR 12
#define M_ROWS (BATCH * L)   // 16384
#define NCH 128
#define CHL (L / NCH)        // 32
#define BDN (BATCH * DI * DS) // 24576
#define NX (2 * DI)          // 768
#define KC 576               // concat K for proj GEMM
#define NP 64                // padded N for proj GEMM

// ---------------- scratch (device globals; no allocation) ----------------
__device__ float g_xi[(size_t)M_ROWS * DI];
__device__ float g_z[(size_t)M_ROWS * DI];
__device__ float g_u[(size_t)M_ROWS * DI];
__device__ float g_delta[(size_t)M_ROWS * DI];
__device__ float g_dtr[(size_t)M_ROWS * DTR];
__device__ float g_Bs[(size_t)M_ROWS * DS];
__device__ float g_Cs[(size_t)M_ROWS * DS];
__device__ float g_y[(size_t)M_ROWS * DI];
__device__ float g_hpart[(size_t)NCH * BDN];
__device__ float g_aP[(size_t)NCH * BDN];
__device__ float g_hin[(size_t)NCH * BDN];
__device__ float g_wt[(size_t)NX * CM];      // W_in transposed, tf32-rounded
__device__ float g_pwhi[(size_t)NP * KC];    // proj Wcat hi, [n][k]
__device__ float g_pwlo[(size_t)NP * KC];    // proj Wcat lo

__device__ __forceinline__ uint32_t f2tf32(float f)
{
    uint32_t r;
    asm("cvt.rna.tf32.f32 %0, %1;" : "=r"(r) : "f"(f));
    return r;
}

// ---------------- k_prep_w: transpose + tf32-round W_in ----------------
__global__ void k_prep_w(const float* __restrict__ Win)
{
    const int i = blockIdx.x * 256 + threadIdx.x;
    if (i >= CM * NX) return;
    const int k = i / NX, n = i % NX;
    g_wt[(size_t)n * CM + k] = __uint_as_float(f2tf32(Win[i]));
}

// ---------------- k_prep_pw: build Wcat [64][576] hi/lo ----------------
// cols 0..43 of Wcat: rows 0..383 = Wx[:,n]; rows 384..575 = Wp[:,n-28] (n>=28)
__global__ void k_prep_pw(const float* __restrict__ Wx, const float* __restrict__ Wp)
{
    const int i = blockIdx.x * 256 + threadIdx.x;
    if (i >= NP * KC) return;
    const int n = i / KC, k = i % KC;
    float v = 0.f;
    if (n < 44) {
        if (k < DI) v = Wx[(size_t)k * 44 + n];
        else if (n >= 28) v = Wp[(size_t)(k - DI) * DS + (n - 28)];
    }
    const float hi = __uint_as_float(f2tf32(v));
    g_pwhi[i] = hi;
    g_pwlo[i] = __uint_as_float(f2tf32(v - hi));
}

// ---------------- tf32 mma helper ----------------
#define AP 36   // fp32 row pitch: conflict-free fragment pattern

__device__ __forceinline__ void mma_tf32(float* d, const uint32_t* a, const uint32_t* b)
{
    asm volatile(
        "mma.sync.aligned.m16n8k8.row.col.f32.tf32.tf32.f32 "
        "{%0,%1,%2,%3}, {%4,%5,%6,%7}, {%8,%9}, {%0,%1,%2,%3};"
        : "+f"(d[0]), "+f"(d[1]), "+f"(d[2]), "+f"(d[3])
        : "r"(a[0]), "r"(a[1]), "r"(a[2]), "r"(a[3]), "r"(b[0]), "r"(b[1]));
}

// ---------------- K1: xz = x @ W_in via single-pass tf32 mma.sync ----------------
__global__ __launch_bounds__(256) void k_gemm_tf32(const float* __restrict__ X)
{
    __shared__ float sA[128][AP], sB[128][AP];
    const int tid = threadIdx.x;
    const int wid = tid >> 5, t = tid & 31;
    const int m0 = blockIdx.x * 128, n0 = blockIdx.y * 128;
    const int wr = wid & 3, wc = wid >> 2;
    const int g = t >> 2, c = t & 3, c2 = c * 2;

    float acc[2][8][4];
#pragma unroll
    for (int mt = 0; mt < 2; mt++)
#pragma unroll
        for (int nt = 0; nt < 8; nt++)
#pragma unroll
            for (int e = 0; e < 4; e++) acc[mt][nt][e] = 0.f;

    const int lr = tid >> 1;
    const int lh = (tid & 1) * 16;

    for (int kc = 0; kc < CM; kc += 32) {
        {
            const float* xp = X + (size_t)(m0 + lr) * CM + kc + lh;
#pragma unroll
            for (int q = 0; q < 4; q++) {
                float4 v = *(const float4*)(xp + q * 4);
                sA[lr][lh + q * 4 + 0] = __uint_as_float(f2tf32(v.x));
                sA[lr][lh + q * 4 + 1] = __uint_as_float(f2tf32(v.y));
                sA[lr][lh + q * 4 + 2] = __uint_as_float(f2tf32(v.z));
                sA[lr][lh + q * 4 + 3] = __uint_as_float(f2tf32(v.w));
            }
            const float* wp = g_wt + (size_t)(n0 + lr) * CM + kc + lh;
#pragma unroll
            for (int q = 0; q < 4; q++)
                *(float4*)&sB[lr][lh + q * 4] = *(const float4*)(wp + q * 4);
        }
        __syncthreads();

#pragma unroll
        for (int ks = 0; ks < 4; ks++) {
            const int K0 = ks * 8;
            uint32_t af[2][4];
#pragma unroll
            for (int mt = 0; mt < 2; mt++) {
                const int R = wr * 32 + mt * 16;
                af[mt][0] = *(const uint32_t*)&sA[R + g][K0 + c];
                af[mt][1] = *(const uint32_t*)&sA[R + g + 8][K0 + c];
                af[mt][2] = *(const uint32_t*)&sA[R + g][K0 + c + 4];
                af[mt][3] = *(const uint32_t*)&sA[R + g + 8][K0 + c + 4];
            }
#pragma unroll
            for (int nt = 0; nt < 8; nt++) {
                const int N = wc * 64 + nt * 8;
                uint32_t bf[2];
                bf[0] = *(const uint32_t*)&sB[N + g][K0 + c];
                bf[1] = *(const uint32_t*)&sB[N + g][K0 + c + 4];
#pragma unroll
                for (int mt = 0; mt < 2; mt++)
                    mma_tf32(acc[mt][nt], af[mt], bf);
            }
        }
        __syncthreads();
    }

    const bool toZ = (n0 >= DI);
#pragma unroll
    for (int mt = 0; mt < 2; mt++) {
#pragma unroll
        for (int nt = 0; nt < 8; nt++) {
            int nc = n0 + wc * 64 + nt * 8 + c2;
            if (toZ) nc -= DI;
            const int r0 = m0 + wr * 32 + mt * 16 + g;
            float* base = toZ ? g_z : g_xi;
            *(float2*)&base[(size_t)r0 * DI + nc] =
                make_float2(acc[mt][nt][0], acc[mt][nt][1]);
            *(float2*)&base[(size_t)(r0 + 8) * DI + nc] =
                make_float2(acc[mt][nt][2], acc[mt][nt][3]);
        }
    }
}

// ---------------- conv: depthwise 3x3 + bias + SiLU, 8 outputs/thread ----------------
__global__ __launch_bounds__(1024) void k_conv(const float* __restrict__ cw,
                                               const float* __restrict__ cb)
{
    extern __shared__ float cs[];   // [100][128]
    const int b = blockIdx.z;
    const int d = blockIdx.y * 128 + threadIdx.x;
    const int h0 = (blockIdx.x >> 3) * 8;
    const int w0 = (blockIdx.x & 7) * 8;
    const int tx = threadIdx.x, ty = threadIdx.y;
    const size_t base = (size_t)b * L * DI;

#pragma unroll
    for (int i = 0; i < 13; i++) {
        const int p = ty + 8 * i;
        if (p < 100) {
            const int rr = p / 10, cc = p % 10;
            const int hh = h0 + rr - 1, ww = w0 + cc - 1;
            float v = 0.f;
            if (hh >= 0 && hh < 64 && ww >= 0 && ww < 64)
                v = g_xi[base + (size_t)(hh * 64 + ww) * DI + d];
            cs[p * 128 + tx] = v;
        }
    }
    __syncthreads();

    float W[9];
#pragma unroll
    for (int i = 0; i < 9; i++) W[i] = cw[d * 9 + i];
    const float bias = cb[d];

    float acc[8];
#pragma unroll
    for (int j = 0; j < 8; j++) acc[j] = bias;

#pragma unroll
    for (int r = 0; r < 3; r++) {
        float rv[10];
#pragma unroll
        for (int cc = 0; cc < 10; cc++) rv[cc] = cs[((ty + r) * 10 + cc) * 128 + tx];
#pragma unroll
        for (int j = 0; j < 8; j++) {
            acc[j] = fmaf(rv[j],     W[r * 3 + 0], acc[j]);
            acc[j] = fmaf(rv[j + 1], W[r * 3 + 1], acc[j]);
            acc[j] = fmaf(rv[j + 2], W[r * 3 + 2], acc[j]);
        }
    }
#pragma unroll
    for (int j = 0; j < 8; j++) {
        const float sig = 1.f / (1.f + __expf(-acc[j]));
        g_u[base + (size_t)((h0 + ty) * 64 + w0 + j) * DI + d] = acc[j] * sig;
    }
}

// ---------------- k_proj_mma: [u|prompt] @ Wcat via tf32x3 ----------------
// 128-row tiles, N=64, K=576 in 18 chunks of 32. 256 threads.
// emits g_dtr (cols 0..11), g_Bs (12..27), g_Cs (28..43, prompt term included)
__global__ __launch_bounds__(256) void k_proj_mma(const float* __restrict__ prompt)
{
    extern __shared__ float psm[];
    float (*sAh)[AP] = (float(*)[AP])psm;                 // 128 x 36
    float (*sAl)[AP] = (float(*)[AP])(psm + 128 * AP);    // 128 x 36
    float (*sBh)[AP] = (float(*)[AP])(psm + 256 * AP);    // 64 x 36
    float (*sBl)[AP] = (float(*)[AP])(psm + 256 * AP + 64 * AP);

    const int tid = threadIdx.x;
    const int wid = tid >> 5, t = tid & 31;
    const int m0 = blockIdx.x * 128;
    const int wr = wid & 3, wc = wid >> 2;   // 4 row-groups x 2 col-groups
    const int g = t >> 2, c = t & 3, c2 = c * 2;

    float acc[2][4][4];
#pragma unroll
    for (int mt = 0; mt < 2; mt++)
#pragma unroll
        for (int nt = 0; nt < 4; nt++)
#pragma unroll
            for (int e = 0; e < 4; e++) acc[mt][nt][e] = 0.f;

    const int lr = tid >> 1;            // A row 0..127
    const int lh = (tid & 1) * 16;
    const int lrB = tid >> 2;           // B row 0..63
    const int lhB = (tid & 3) * 8;

    for (int kc = 0; kc < KC; kc += 32) {
        {
            const float* ap = (kc < DI)
                ? g_u + (size_t)(m0 + lr) * DI + kc + lh
                : prompt + (size_t)(m0 + lr) * CM + (kc - DI) + lh;
#pragma unroll
            for (int q = 0; q < 4; q++) {
                float4 v = *(const float4*)(ap + q * 4);
                float h0 = __uint_as_float(f2tf32(v.x));
                float h1 = __uint_as_float(f2tf32(v.y));
                float h2 = __uint_as_float(f2tf32(v.z));
                float h3 = __uint_as_float(f2tf32(v.w));
                sAh[lr][lh + q * 4 + 0] = h0;
                sAh[lr][lh + q * 4 + 1] = h1;
                sAh[lr][lh + q * 4 + 2] = h2;
                sAh[lr][lh + q * 4 + 3] = h3;
                sAl[lr][lh + q * 4 + 0] = __uint_as_float(f2tf32(v.x - h0));
                sAl[lr][lh + q * 4 + 1] = __uint_as_float(f2tf32(v.y - h1));
                sAl[lr][lh + q * 4 + 2] = __uint_as_float(f2tf32(v.z - h2));
                sAl[lr][lh + q * 4 + 3] = __uint_as_float(f2tf32(v.w - h3));
            }
            const float* bh = g_pwhi + (size_t)lrB * KC + kc + lhB;
            const float* bl = g_pwlo + (size_t)lrB * KC + kc + lhB;
#pragma unroll
            for (int q = 0; q < 2; q++) {
                *(float4*)&sBh[lrB][lhB + q * 4] = *(const float4*)(bh + q * 4);
                *(float4*)&sBl[lrB][lhB + q * 4] = *(const float4*)(bl + q * 4);
            }
        }
        __syncthreads();

#pragma unroll
        for (int ks = 0; ks < 4; ks++) {
            const int K0 = ks * 8;
            uint32_t ah[2][4], al[2][4];
#pragma unroll
            for (int mt = 0; mt < 2; mt++) {
                const int R = wr * 32 + mt * 16;
                ah[mt][0] = *(const uint32_t*)&sAh[R + g][K0 + c];
                ah[mt][1] = *(const uint32_t*)&sAh[R + g + 8][K0 + c];
                ah[mt][2] = *(const uint32_t*)&sAh[R + g][K0 + c + 4];
                ah[mt][3] = *(const uint32_t*)&sAh[R + g + 8][K0 + c + 4];
                al[mt][0] = *(const uint32_t*)&sAl[R + g][K0 + c];
                al[mt][1] = *(const uint32_t*)&sAl[R + g + 8][K0 + c];
                al[mt][2] = *(const uint32_t*)&sAl[R + g][K0 + c + 4];
                al[mt][3] = *(const uint32_t*)&sAl[R + g + 8][K0 + c + 4];
            }
#pragma unroll
            for (int nt = 0; nt < 4; nt++) {
                const int N = wc * 32 + nt * 8;
                uint32_t bh[2], bl[2];
                bh[0] = *(const uint32_t*)&sBh[N + g][K0 + c];
                bh[1] = *(const uint32_t*)&sBh[N + g][K0 + c + 4];
                bl[0] = *(const uint32_t*)&sBl[N + g][K0 + c];
                bl[1] = *(const uint32_t*)&sBl[N + g][K0 + c + 4];
#pragma unroll
                for (int mt = 0; mt < 2; mt++) {
                    mma_tf32(acc[mt][nt], ah[mt], bh);
                    mma_tf32(acc[mt][nt], ah[mt], bl);
                    mma_tf32(acc[mt][nt], al[mt], bh);
                }
            }
        }
        __syncthreads();
    }

    // epilogue: scatter to dtr / Bs / Cs (region boundaries 12/28/44 are even)
#pragma unroll
    for (int mt = 0; mt < 2; mt++) {
#pragma unroll
        for (int nt = 0; nt < 4; nt++) {
            const int col = wc * 32 + nt * 8 + c2;
            const int r0 = m0 + wr * 32 + mt * 16 + g;
#pragma unroll
            for (int hrow = 0; hrow < 2; hrow++) {
                const size_t row = (size_t)(r0 + hrow * 8);
                const float v0 = acc[mt][nt][hrow * 2 + 0];
                const float v1 = acc[mt][nt][hrow * 2 + 1];
                if (col < DTR)
                    *(float2*)&g_dtr[row * DTR + col] = make_float2(v0, v1);
                else if (col < DTR + DS)
                    *(float2*)&g_Bs[row * DS + (col - DTR)] = make_float2(v0, v1);
                else if (col < 44)
                    *(float2*)&g_Cs[row * DS + (col - DTR - DS)] = make_float2(v0, v1);
            }
        }
    }
}

// ---------------- k_delta ----------------
__global__ void k_delta(const float* __restrict__ Wdt, const float* __restrict__ bdt)
{
    __shared__ float sd[8][DTR];
    const int tid = threadIdx.x; // 384
    const int row0 = blockIdx.x * 8;
    if (tid < 8 * DTR) sd[tid / DTR][tid % DTR] = g_dtr[(size_t)(row0 + tid / DTR) * DTR + tid % DTR];
    __syncthreads();

    float w[DTR];
#pragma unroll
    for (int rr = 0; rr < DTR; rr++) w[rr] = Wdt[(size_t)rr * DI + tid];
    const float bb = bdt[tid];
#pragma unroll
    for (int rr = 0; rr < 8; rr++) {
        float acc = bb;
#pragma unroll
        for (int r2 = 0; r2 < DTR; r2++) acc = fmaf(sd[rr][r2], w[r2], acc);
        const float sp = acc > 20.f ? acc : log1pf(__expf(acc));
        g_delta[(size_t)(row0 + rr) * DI + tid] = sp;
    }
}

// ---------------- scan helpers ----------------
__device__ __forceinline__ void pow_chain(float e1, float* av)
{
    const float e2 = e1 * e1, e4 = e2 * e2, e8 = e4 * e4;
    av[0] = e1;       av[1] = e2;       av[2] = e2 * e1;   av[3] = e4;
    av[4] = e4 * e1;  av[5] = e4 * e2;  av[6] = e4 * av[2]; av[7] = e8;
    av[8] = e8 * e1;  av[9] = e8 * e2;  av[10] = e8 * av[2]; av[11] = e8 * e4;
    av[12] = e8 * av[4]; av[13] = e8 * av[5]; av[14] = e8 * av[6]; av[15] = e8 * e8;
}

__device__ __forceinline__ bool a_structured(const float* __restrict__ Alog, int d, float& A0)
{
    A0 = -__expf(Alog[(size_t)d * DS]);
    bool ok = true;
#pragma unroll
    for (int n = 1; n < DS; n++) {
        const float Av = -__expf(Alog[(size_t)d * DS + n]);
        ok &= fabsf(Av - (n + 1) * A0) <= 1e-4f * fabsf((n + 1) * A0);
    }
    return ok;
}

// ---------------- S1 ----------------
__global__ void k_scan1(const float* __restrict__ Alog)
{
    __shared__ float sB[CHL][DS];
    const int d = blockIdx.x * 128 + threadIdx.x;
    const int c = blockIdx.y;
    const int b = blockIdx.z;
    const int l0 = c * CHL;

    {
        const float4* src = (const float4*)g_Bs + ((size_t)b * L + l0) * 4;
        ((float4*)sB)[threadIdx.x] = src[threadIdx.x];
    }

    float A0;
    const bool st = a_structured(Alog, d, A0);
    __syncthreads();

    float h[DS];
#pragma unroll
    for (int n = 0; n < DS; n++) h[n] = 0.f;
    float dsum = 0.f;

    const float* dp = g_delta + ((size_t)b * L + l0) * DI + d;
    const float* up = g_u + ((size_t)b * L + l0) * DI + d;

    if (st) {
        for (int l = 0; l < CHL; l++) {
            const float dl = dp[(size_t)l * DI];
            const float du = dl * up[(size_t)l * DI];
            dsum += dl;
            float av[DS];
            pow_chain(__expf(dl * A0), av);
#pragma unroll
            for (int n = 0; n < DS; n++) h[n] = fmaf(av[n], h[n], du * sB[l][n]);
        }
        float av[DS];
        pow_chain(__expf(dsum * A0), av);
        const size_t base = (size_t)c * BDN + ((size_t)b * DI + d) * DS;
#pragma unroll
        for (int n = 0; n < DS; n++) {
            g_hpart[base + n] = h[n];
            g_aP[base + n] = av[n];
        }
    } else {
        float A[DS];
#pragma unroll
        for (int n = 0; n < DS; n++) A[n] = -__expf(Alog[(size_t)d * DS + n]);
        for (int l = 0; l < CHL; l++) {
            const float dl = dp[(size_t)l * DI];
            const float du = dl * up[(size_t)l * DI];
            dsum += dl;
#pragma unroll
            for (int n = 0; n < DS; n++)
                h[n] = fmaf(__expf(dl * A[n]), h[n], du * sB[l][n]);
        }
        const size_t base = (size_t)c * BDN + ((size_t)b * DI + d) * DS;
#pragma unroll
        for (int n = 0; n < DS; n++) {
            g_hpart[base + n] = h[n];
            g_aP[base + n] = __expf(A[n] * dsum);
        }
    }
}

// ---------------- S2 ----------------
__global__ void k_scan2()
{
    const int idx = blockIdx.x * 256 + threadIdx.x;
    if (idx >= BDN) return;
    float h = 0.f;
    for (int c = 0; c < NCH; c++) {
        const size_t o = (size_t)c * BDN + idx;
        g_hin[o] = h;
        h = fmaf(g_aP[o], h, g_hpart[o]);
    }
}

// ---------------- S3 ----------------
__global__ void k_scan3(const float* __restrict__ Alog, const float* __restrict__ Dvec)
{
    __shared__ float sB[CHL][DS];
    __shared__ float sC[CHL][DS];
    const int d = blockIdx.x * 128 + threadIdx.x;
    const int c = blockIdx.y;
    const int b = blockIdx.z;
    const int l0 = c * CHL;

    {
        const float4* srcB = (const float4*)g_Bs + ((size_t)b * L + l0) * 4;
        const float4* srcC = (const float4*)g_Cs + ((size_t)b * L + l0) * 4;
        ((float4*)sB)[threadIdx.x] = srcB[threadIdx.x];
        ((float4*)sC)[threadIdx.x] = srcC[threadIdx.x];
    }

    float A0;
    const bool st = a_structured(Alog, d, A0);
    const float Dd = Dvec[d];
    __syncthreads();

    float h[DS];
    {
        const size_t base = (size_t)c * BDN + ((size_t)b * DI + d) * DS;
#pragma unroll
        for (int n = 0; n < DS; n++) h[n] = g_hin[base + n];
    }

    const float* dp = g_delta + ((size_t)b * L + l0) * DI + d;
    const float* up = g_u + ((size_t)b * L + l0) * DI + d;
    float* yp = g_y + ((size_t)b * L + l0) * DI + d;

    if (st) {
        for (int l = 0; l < CHL; l++) {
            const float dl = dp[(size_t)l * DI];
            const float uu = up[(size_t)l * DI];
            const float du = dl * uu;
            float av[DS];
            pow_chain(__expf(dl * A0), av);
            float y = uu * Dd;
#pragma unroll
            for (int n = 0; n < DS; n++) {
                h[n] = fmaf(av[n], h[n], du * sB[l][n]);
                y = fmaf(h[n], sC[l][n], y);
            }
            yp[(size_t)l * DI] = y;
        }
    } else {
        float A[DS];
#pragma unroll
        for (int n = 0; n < DS; n++) A[n] = -__expf(Alog[(size_t)d * DS + n]);
        for (int l = 0; l < CHL; l++) {
            const float dl = dp[(size_t)l * DI];
            const float uu = up[(size_t)l * DI];
            const float du = dl * uu;
            float y = uu * Dd;
#pragma unroll
            for (int n = 0; n < DS; n++) {
                h[n] = fmaf(__expf(dl * A[n]), h[n], du * sB[l][n]);
                y = fmaf(h[n], sC[l][n], y);
            }
            yp[(size_t)l * DI] = y;
        }
    }
}

// ---------------- K4: LayerNorm + SiLU gate + out GEMM ----------------
__global__ void k_out(const float* __restrict__ lng, const float* __restrict__ lnb,
                      const float* __restrict__ Wout, float* __restrict__ out)
{
    __shared__ float yg[16][DI];
    __shared__ float Wt[16][CM];
    const int tid = threadIdx.x; // 256
    const int r0 = blockIdx.x * 16;
    const int warp = tid >> 5, lane = tid & 31;

#pragma unroll
    for (int rr = 0; rr < 2; rr++) {
        const int r = warp * 2 + rr;
        const size_t row = (size_t)(r0 + r);
        float v[12];
        float s = 0.f, sq = 0.f;
#pragma unroll
        for (int i = 0; i < 12; i++) {
            v[i] = g_y[row * DI + lane + 32 * i];
            s += v[i];
            sq = fmaf(v[i], v[i], sq);
        }
#pragma unroll
        for (int o = 16; o > 0; o >>= 1) {
            s += __shfl_xor_sync(0xFFFFFFFFu, s, o);
            sq += __shfl_xor_sync(0xFFFFFFFFu, sq, o);
        }
        const float mu = s * (1.f / DI);
        const float var = sq * (1.f / DI) - mu * mu;
        const float rs = rsqrtf(var + 1e-5f);
#pragma unroll
        for (int i = 0; i < 12; i++) {
            const int k = lane + 32 * i;
            const float zn = g_z[row * DI + k];
            const float sig = 1.f / (1.f + __expf(-zn));
            const float g = fmaf((v[i] - mu) * rs, lng[k], lnb[k]);
            yg[r][k] = g * zn * sig;
        }
    }
    __syncthreads();

    const int tr = tid >> 6;
    const int tc = tid & 63;
    float acc[4][3];
#pragma unroll
    for (int r = 0; r < 4; r++)
#pragma unroll
        for (int cc = 0; cc < 3; cc++) acc[r][cc] = 0.f;

    for (int kt = 0; kt < DI; kt += 16) {
#pragma unroll
        for (int i = 0; i < 3; i++) {
            const int e = tid + i * 256;
            const int kr = e / 48;
            const int c4 = (e % 48) * 4;
            *(float4*)&Wt[kr][c4] = *(const float4*)&Wout[(size_t)(kt + kr) * CM + c4];
        }
        __syncthreads();
#pragma unroll
        for (int k = 0; k < 16; k++) {
            const float w0 = Wt[k][tc * 3 + 0];
            const float w1 = Wt[k][tc * 3 + 1];
            const float w2 = Wt[k][tc * 3 + 2];
#pragma unroll
            for (int r = 0; r < 4; r++) {
                const float a = yg[tr * 4 + r][kt + k];
                acc[r][0] = fmaf(a, w0, acc[r][0]);
                acc[r][1] = fmaf(a, w1, acc[r][1]);
                acc[r][2] = fmaf(a, w2, acc[r][2]);
            }
        }
        __syncthreads();
    }
#pragma unroll
    for (int r = 0; r < 4; r++) {
        const size_t row = (size_t)(r0 + tr * 4 + r);
#pragma unroll
        for (int cc = 0; cc < 3; cc++)
            out[row * CM + tc * 3 + cc] = acc[r][cc];
    }
}

// ---------------- launch ----------------
extern "C" void kernel_launch(void* const* d_in, const int* in_sizes, int n_in,
                              void* d_out, int out_size)
{
    const float* x      = (const float*)d_in[0];
    const float* prompt = (const float*)d_in[1];
    const float* W_in   = (const float*)d_in[2];
    const float* conv_w = (const float*)d_in[3];
    const float* conv_b = (const float*)d_in[4];
    const float* Wx     = (const float*)d_in[5];
    const float* Wdt    = (const float*)d_in[6];
    const float* b_dt   = (const float*)d_in[7];
    const float* A_log  = (const float*)d_in[8];
    const float* Dv     = (const float*)d_in[9];
    const float* Wp     = (const float*)d_in[10];
    const float* ln_g   = (const float*)d_in[11];
    const float* ln_b   = (const float*)d_in[12];
    const float* Wout   = (const float*)d_in[13];
    float* out = (float*)d_out;

    static bool attr_set = false;
    if (!attr_set) {
        cudaFuncSetAttribute(k_conv, cudaFuncAttributeMaxDynamicSharedMemorySize, 51200);
        cudaFuncSetAttribute(k_proj_mma, cudaFuncAttributeMaxDynamicSharedMemorySize, 55296);
        attr_set = true;
    }

    k_prep_w<<<(CM * NX + 255) / 256, 256>>>(W_in);
    k_prep_pw<<<(NP * KC + 255) / 256, 256>>>(Wx, Wp);
    k_gemm_tf32<<<dim3(M_ROWS / 128, NX / 128), 256>>>(x);
    k_conv<<<dim3(64, 3, BATCH), dim3(128, 8), 51200>>>(conv_w, conv_b);
    k_proj_mma<<<M_ROWS / 128, 256, 55296>>>(prompt);
    k_delta<<<M_ROWS / 8, DI>>>(Wdt, b_dt);
    k_scan1<<<dim3(DI / 128, NCH, BATCH), 128>>>(A_log);
    k_scan2<<<(BDN + 255) / 256, 256>>>();
    k_scan3<<<dim3(DI / 128, NCH, BATCH), 128>>>(A_log, Dv);
    k_out<<<M_ROWS / 16, 256>>>(ln_g, ln_b, Wout, out);
}

// round 10
// speedup vs baseline: 1.2076x; 1.0312x over previous
#include <cuda_runtime.h>
#include <cuda_bf16.h>
#include <cstdint>

#define BATCH 4
#define L 4096
#define CM 192
#define DI 384
#define DS 16
#define DTR 12
#define M_ROWS (BATCH * L)   // 16384
#define NCH 128
#define CHL (L / NCH)        // 32
#define BDN (BATCH * DI * DS) // 24576
#define NX (2 * DI)          // 768
#define KC 576
#define NP 64

// ---------------- scratch ----------------
__device__ float g_xi[(size_t)M_ROWS * DI];     // xi, later reused as yg
__device__ float g_z[(size_t)M_ROWS * DI];
__device__ float g_u[(size_t)M_ROWS * DI];
__device__ float g_delta[(size_t)M_ROWS * DI];
__device__ float g_dtr[(size_t)M_ROWS * DTR];
__device__ float g_Bs[(size_t)M_ROWS * DS];
__device__ float g_Cs[(size_t)M_ROWS * DS];
__device__ float g_y[(size_t)M_ROWS * DI];
__device__ float g_hpart[(size_t)NCH * BDN];
__device__ float g_aP[(size_t)NCH * BDN];
__device__ float g_hin[(size_t)NCH * BDN];
__device__ float g_wt[(size_t)NX * CM];
__device__ float g_pwhi[(size_t)NP * KC];
__device__ float g_pwlo[(size_t)NP * KC];
__device__ float g_wohi[(size_t)CM * DI];   // Wout^T hi [n][k]
__device__ float g_wolo[(size_t)CM * DI];

__device__ __forceinline__ uint32_t f2tf32(float f)
{
    uint32_t r;
    asm("cvt.rna.tf32.f32 %0, %1;" : "=r"(r) : "f"(f));
    return r;
}
__device__ __forceinline__ float tf32v(float f) { return __uint_as_float(f2tf32(f)); }

// ---------------- prep kernels ----------------
__global__ void k_prep_w(const float* __restrict__ Win)
{
    const int i = blockIdx.x * 256 + threadIdx.x;
    if (i >= CM * NX) return;
    const int k = i / NX, n = i % NX;
    g_wt[(size_t)n * CM + k] = tf32v(Win[i]);
}

__global__ void k_prep_pw(const float* __restrict__ Wx, const float* __restrict__ Wp)
{
    const int i = blockIdx.x * 256 + threadIdx.x;
    if (i >= NP * KC) return;
    const int n = i / KC, k = i % KC;
    float v = 0.f;
    if (n < 44) {
        if (k < DI) v = Wx[(size_t)k * 44 + n];
        else if (n >= 28) v = Wp[(size_t)(k - DI) * DS + (n - 28)];
    }
    const float hi = tf32v(v);
    g_pwhi[i] = hi;
    g_pwlo[i] = tf32v(v - hi);
}

__global__ void k_prep_wout(const float* __restrict__ Wout)
{
    const int i = blockIdx.x * 256 + threadIdx.x;
    if (i >= CM * DI) return;
    const int k = i / CM, n = i % CM;     // Wout[k][n]
    const float v = Wout[i];
    const float hi = tf32v(v);
    g_wohi[(size_t)n * DI + k] = hi;
    g_wolo[(size_t)n * DI + k] = tf32v(v - hi);
}

// ---------------- tf32 mma ----------------
#define AP 36

__device__ __forceinline__ void mma_tf32(float* d, const uint32_t* a, const uint32_t* b)
{
    asm volatile(
        "mma.sync.aligned.m16n8k8.row.col.f32.tf32.tf32.f32 "
        "{%0,%1,%2,%3}, {%4,%5,%6,%7}, {%8,%9}, {%0,%1,%2,%3};"
        : "+f"(d[0]), "+f"(d[1]), "+f"(d[2]), "+f"(d[3])
        : "r"(a[0]), "r"(a[1]), "r"(a[2]), "r"(a[3]), "r"(b[0]), "r"(b[1]));
}

// ---------------- K1: xz = x @ W_in (single-pass tf32) ----------------
__global__ __launch_bounds__(256) void k_gemm_tf32(const float* __restrict__ X)
{
    __shared__ float sA[128][AP], sB[128][AP];
    const int tid = threadIdx.x;
    const int wid = tid >> 5, t = tid & 31;
    const int m0 = blockIdx.x * 128, n0 = blockIdx.y * 128;
    const int wr = wid & 3, wc = wid >> 2;
    const int g = t >> 2, c = t & 3, c2 = c * 2;

    float acc[2][8][4];
#pragma unroll
    for (int mt = 0; mt < 2; mt++)
#pragma unroll
        for (int nt = 0; nt < 8; nt++)
#pragma unroll
            for (int e = 0; e < 4; e++) acc[mt][nt][e] = 0.f;

    const int lr = tid >> 1;
    const int lh = (tid & 1) * 16;

    for (int kc = 0; kc < CM; kc += 32) {
        {
            const float* xp = X + (size_t)(m0 + lr) * CM + kc + lh;
#pragma unroll
            for (int q = 0; q < 4; q++) {
                float4 v = *(const float4*)(xp + q * 4);
                float4 tv = make_float4(tf32v(v.x), tf32v(v.y), tf32v(v.z), tf32v(v.w));
                *(float4*)&sA[lr][lh + q * 4] = tv;
            }
            const float* wp = g_wt + (size_t)(n0 + lr) * CM + kc + lh;
#pragma unroll
            for (int q = 0; q < 4; q++)
                *(float4*)&sB[lr][lh + q * 4] = *(const float4*)(wp + q * 4);
        }
        __syncthreads();

#pragma unroll
        for (int ks = 0; ks < 4; ks++) {
            const int K0 = ks * 8;
            uint32_t af[2][4];
#pragma unroll
            for (int mt = 0; mt < 2; mt++) {
                const int R = wr * 32 + mt * 16;
                af[mt][0] = *(const uint32_t*)&sA[R + g][K0 + c];
                af[mt][1] = *(const uint32_t*)&sA[R + g + 8][K0 + c];
                af[mt][2] = *(const uint32_t*)&sA[R + g][K0 + c + 4];
                af[mt][3] = *(const uint32_t*)&sA[R + g + 8][K0 + c + 4];
            }
#pragma unroll
            for (int nt = 0; nt < 8; nt++) {
                const int N = wc * 64 + nt * 8;
                uint32_t bf[2];
                bf[0] = *(const uint32_t*)&sB[N + g][K0 + c];
                bf[1] = *(const uint32_t*)&sB[N + g][K0 + c + 4];
#pragma unroll
                for (int mt = 0; mt < 2; mt++)
                    mma_tf32(acc[mt][nt], af[mt], bf);
            }
        }
        __syncthreads();
    }

    const bool toZ = (n0 >= DI);
#pragma unroll
    for (int mt = 0; mt < 2; mt++) {
#pragma unroll
        for (int nt = 0; nt < 8; nt++) {
            int nc = n0 + wc * 64 + nt * 8 + c2;
            if (toZ) nc -= DI;
            const int r0 = m0 + wr * 32 + mt * 16 + g;
            float* base = toZ ? g_z : g_xi;
            *(float2*)&base[(size_t)r0 * DI + nc] =
                make_float2(acc[mt][nt][0], acc[mt][nt][1]);
            *(float2*)&base[(size_t)(r0 + 8) * DI + nc] =
                make_float2(acc[mt][nt][2], acc[mt][nt][3]);
        }
    }
}

// ---------------- conv ----------------
__global__ __launch_bounds__(1024) void k_conv(const float* __restrict__ cw,
                                               const float* __restrict__ cb)
{
    extern __shared__ float cs[];
    const int b = blockIdx.z;
    const int d = blockIdx.y * 128 + threadIdx.x;
    const int h0 = (blockIdx.x >> 3) * 8;
    const int w0 = (blockIdx.x & 7) * 8;
    const int tx = threadIdx.x, ty = threadIdx.y;
    const size_t base = (size_t)b * L * DI;

#pragma unroll
    for (int i = 0; i < 13; i++) {
        const int p = ty + 8 * i;
        if (p < 100) {
            const int rr = p / 10, cc = p % 10;
            const int hh = h0 + rr - 1, ww = w0 + cc - 1;
            float v = 0.f;
            if (hh >= 0 && hh < 64 && ww >= 0 && ww < 64)
                v = g_xi[base + (size_t)(hh * 64 + ww) * DI + d];
            cs[p * 128 + tx] = v;
        }
    }
    __syncthreads();

    float W[9];
#pragma unroll
    for (int i = 0; i < 9; i++) W[i] = cw[d * 9 + i];
    const float bias = cb[d];

    float acc[8];
#pragma unroll
    for (int j = 0; j < 8; j++) acc[j] = bias;

#pragma unroll
    for (int r = 0; r < 3; r++) {
        float rv[10];
#pragma unroll
        for (int cc = 0; cc < 10; cc++) rv[cc] = cs[((ty + r) * 10 + cc) * 128 + tx];
#pragma unroll
        for (int j = 0; j < 8; j++) {
            acc[j] = fmaf(rv[j],     W[r * 3 + 0], acc[j]);
            acc[j] = fmaf(rv[j + 1], W[r * 3 + 1], acc[j]);
            acc[j] = fmaf(rv[j + 2], W[r * 3 + 2], acc[j]);
        }
    }
#pragma unroll
    for (int j = 0; j < 8; j++) {
        const float sig = 1.f / (1.f + __expf(-acc[j]));
        g_u[base + (size_t)((h0 + ty) * 64 + w0 + j) * DI + d] = acc[j] * sig;
    }
}

// ---------------- k_proj_mma: [u|prompt] @ Wcat via tf32x3 ----------------
__global__ __launch_bounds__(256) void k_proj_mma(const float* __restrict__ prompt)
{
    extern __shared__ float psm[];
    float (*sAh)[AP] = (float(*)[AP])psm;
    float (*sAl)[AP] = (float(*)[AP])(psm + 128 * AP);
    float (*sBh)[AP] = (float(*)[AP])(psm + 256 * AP);
    float (*sBl)[AP] = (float(*)[AP])(psm + 256 * AP + 64 * AP);

    const int tid = threadIdx.x;
    const int wid = tid >> 5, t = tid & 31;
    const int m0 = blockIdx.x * 128;
    const int wr = wid & 3, wc = wid >> 2;
    const int g = t >> 2, c = t & 3, c2 = c * 2;

    float acc[2][4][4];
#pragma unroll
    for (int mt = 0; mt < 2; mt++)
#pragma unroll
        for (int nt = 0; nt < 4; nt++)
#pragma unroll
            for (int e = 0; e < 4; e++) acc[mt][nt][e] = 0.f;

    const int lr = tid >> 1;
    const int lh = (tid & 1) * 16;
    const int lrB = tid >> 2;
    const int lhB = (tid & 3) * 8;

    for (int kc = 0; kc < KC; kc += 32) {
        {
            const float* ap = (kc < DI)
                ? g_u + (size_t)(m0 + lr) * DI + kc + lh
                : prompt + (size_t)(m0 + lr) * CM + (kc - DI) + lh;
#pragma unroll
            for (int q = 0; q < 4; q++) {
                float4 v = *(const float4*)(ap + q * 4);
                float4 hv = make_float4(tf32v(v.x), tf32v(v.y), tf32v(v.z), tf32v(v.w));
                float4 lv = make_float4(tf32v(v.x - hv.x), tf32v(v.y - hv.y),
                                        tf32v(v.z - hv.z), tf32v(v.w - hv.w));
                *(float4*)&sAh[lr][lh + q * 4] = hv;
                *(float4*)&sAl[lr][lh + q * 4] = lv;
            }
            const float* bh = g_pwhi + (size_t)lrB * KC + kc + lhB;
            const float* bl = g_pwlo + (size_t)lrB * KC + kc + lhB;
#pragma unroll
            for (int q = 0; q < 2; q++) {
                *(float4*)&sBh[lrB][lhB + q * 4] = *(const float4*)(bh + q * 4);
                *(float4*)&sBl[lrB][lhB + q * 4] = *(const float4*)(bl + q * 4);
            }
        }
        __syncthreads();

#pragma unroll
        for (int ks = 0; ks < 4; ks++) {
            const int K0 = ks * 8;
            uint32_t ah[2][4], al[2][4];
#pragma unroll
            for (int mt = 0; mt < 2; mt++) {
                const int R = wr * 32 + mt * 16;
                ah[mt][0] = *(const uint32_t*)&sAh[R + g][K0 + c];
                ah[mt][1] = *(const uint32_t*)&sAh[R + g + 8][K0 + c];
                ah[mt][2] = *(const uint32_t*)&sAh[R + g][K0 + c + 4];
                ah[mt][3] = *(const uint32_t*)&sAh[R + g + 8][K0 + c + 4];
                al[mt][0] = *(const uint32_t*)&sAl[R + g][K0 + c];
                al[mt][1] = *(const uint32_t*)&sAl[R + g + 8][K0 + c];
                al[mt][2] = *(const uint32_t*)&sAl[R + g][K0 + c + 4];
                al[mt][3] = *(const uint32_t*)&sAl[R + g + 8][K0 + c + 4];
            }
#pragma unroll
            for (int nt = 0; nt < 4; nt++) {
                const int N = wc * 32 + nt * 8;
                uint32_t bh[2], bl[2];
                bh[0] = *(const uint32_t*)&sBh[N + g][K0 + c];
                bh[1] = *(const uint32_t*)&sBh[N + g][K0 + c + 4];
                bl[0] = *(const uint32_t*)&sBl[N + g][K0 + c];
                bl[1] = *(const uint32_t*)&sBl[N + g][K0 + c + 4];
#pragma unroll
                for (int mt = 0; mt < 2; mt++) {
                    mma_tf32(acc[mt][nt], ah[mt], bh);
                    mma_tf32(acc[mt][nt], ah[mt], bl);
                    mma_tf32(acc[mt][nt], al[mt], bh);
                }
            }
        }
        __syncthreads();
    }

#pragma unroll
    for (int mt = 0; mt < 2; mt++) {
#pragma unroll
        for (int nt = 0; nt < 4; nt++) {
            const int col = wc * 32 + nt * 8 + c2;
            const int r0 = m0 + wr * 32 + mt * 16 + g;
#pragma unroll
            for (int hrow = 0; hrow < 2; hrow++) {
                const size_t row = (size_t)(r0 + hrow * 8);
                const float v0 = acc[mt][nt][hrow * 2 + 0];
                const float v1 = acc[mt][nt][hrow * 2 + 1];
                if (col < DTR)
                    *(float2*)&g_dtr[row * DTR + col] = make_float2(v0, v1);
                else if (col < DTR + DS)
                    *(float2*)&g_Bs[row * DS + (col - DTR)] = make_float2(v0, v1);
                else if (col < 44)
                    *(float2*)&g_Cs[row * DS + (col - DTR - DS)] = make_float2(v0, v1);
            }
        }
    }
}

// ---------------- k_delta ----------------
__global__ void k_delta(const float* __restrict__ Wdt, const float* __restrict__ bdt)
{
    __shared__ float sd[8][DTR];
    const int tid = threadIdx.x;
    const int row0 = blockIdx.x * 8;
    if (tid < 8 * DTR) sd[tid / DTR][tid % DTR] = g_dtr[(size_t)(row0 + tid / DTR) * DTR + tid % DTR];
    __syncthreads();

    float w[DTR];
#pragma unroll
    for (int rr = 0; rr < DTR; rr++) w[rr] = Wdt[(size_t)rr * DI + tid];
    const float bb = bdt[tid];
#pragma unroll
    for (int rr = 0; rr < 8; rr++) {
        float acc = bb;
#pragma unroll
        for (int r2 = 0; r2 < DTR; r2++) acc = fmaf(sd[rr][r2], w[r2], acc);
        const float sp = acc > 20.f ? acc : log1pf(__expf(acc));
        g_delta[(size_t)(row0 + rr) * DI + tid] = sp;
    }
}

// ---------------- scan helpers ----------------
__device__ __forceinline__ void pow_chain(float e1, float* av)
{
    const float e2 = e1 * e1, e4 = e2 * e2, e8 = e4 * e4;
    av[0] = e1;       av[1] = e2;       av[2] = e2 * e1;   av[3] = e4;
    av[4] = e4 * e1;  av[5] = e4 * e2;  av[6] = e4 * av[2]; av[7] = e8;
    av[8] = e8 * e1;  av[9] = e8 * e2;  av[10] = e8 * av[2]; av[11] = e8 * e4;
    av[12] = e8 * av[4]; av[13] = e8 * av[5]; av[14] = e8 * av[6]; av[15] = e8 * e8;
}

__device__ __forceinline__ bool a_structured(const float* __restrict__ Alog, int d, float& A0)
{
    A0 = -__expf(Alog[(size_t)d * DS]);
    bool ok = true;
#pragma unroll
    for (int n = 1; n < DS; n++) {
        const float Av = -__expf(Alog[(size_t)d * DS + n]);
        ok &= fabsf(Av - (n + 1) * A0) <= 1e-4f * fabsf((n + 1) * A0);
    }
    return ok;
}

// ---------------- S1 ----------------
__global__ void k_scan1(const float* __restrict__ Alog)
{
    __shared__ float sB[CHL][DS];
    const int d = blockIdx.x * 128 + threadIdx.x;
    const int c = blockIdx.y;
    const int b = blockIdx.z;
    const int l0 = c * CHL;

    {
        const float4* src = (const float4*)g_Bs + ((size_t)b * L + l0) * 4;
        ((float4*)sB)[threadIdx.x] = src[threadIdx.x];
    }

    float A0;
    const bool st = a_structured(Alog, d, A0);
    __syncthreads();

    float h[DS];
#pragma unroll
    for (int n = 0; n < DS; n++) h[n] = 0.f;
    float dsum = 0.f;

    const float* dp = g_delta + ((size_t)b * L + l0) * DI + d;
    const float* up = g_u + ((size_t)b * L + l0) * DI + d;

    if (st) {
        for (int l = 0; l < CHL; l++) {
            const float dl = dp[(size_t)l * DI];
            const float du = dl * up[(size_t)l * DI];
            dsum += dl;
            float av[DS];
            pow_chain(__expf(dl * A0), av);
#pragma unroll
            for (int n = 0; n < DS; n++) h[n] = fmaf(av[n], h[n], du * sB[l][n]);
        }
        float av[DS];
        pow_chain(__expf(dsum * A0), av);
        const size_t base = (size_t)c * BDN + ((size_t)b * DI + d) * DS;
#pragma unroll
        for (int n = 0; n < DS; n++) {
            g_hpart[base + n] = h[n];
            g_aP[base + n] = av[n];
        }
    } else {
        float A[DS];
#pragma unroll
        for (int n = 0; n < DS; n++) A[n] = -__expf(Alog[(size_t)d * DS + n]);
        for (int l = 0; l < CHL; l++) {
            const float dl = dp[(size_t)l * DI];
            const float du = dl * up[(size_t)l * DI];
            dsum += dl;
#pragma unroll
            for (int n = 0; n < DS; n++)
                h[n] = fmaf(__expf(dl * A[n]), h[n], du * sB[l][n]);
        }
        const size_t base = (size_t)c * BDN + ((size_t)b * DI + d) * DS;
#pragma unroll
        for (int n = 0; n < DS; n++) {
            g_hpart[base + n] = h[n];
            g_aP[base + n] = __expf(A[n] * dsum);
        }
    }
}

// ---------------- S2 ----------------
__global__ void k_scan2()
{
    const int idx = blockIdx.x * 256 + threadIdx.x;
    if (idx >= BDN) return;
    float h = 0.f;
    for (int c = 0; c < NCH; c++) {
        const size_t o = (size_t)c * BDN + idx;
        g_hin[o] = h;
        h = fmaf(g_aP[o], h, g_hpart[o]);
    }
}

// ---------------- S3 ----------------
__global__ void k_scan3(const float* __restrict__ Alog, const float* __restrict__ Dvec)
{
    __shared__ float sB[CHL][DS];
    __shared__ float sC[CHL][DS];
    const int d = blockIdx.x * 128 + threadIdx.x;
    const int c = blockIdx.y;
    const int b = blockIdx.z;
    const int l0 = c * CHL;

    {
        const float4* srcB = (const float4*)g_Bs + ((size_t)b * L + l0) * 4;
        const float4* srcC = (const float4*)g_Cs + ((size_t)b * L + l0) * 4;
        ((float4*)sB)[threadIdx.x] = srcB[threadIdx.x];
        ((float4*)sC)[threadIdx.x] = srcC[threadIdx.x];
    }

    float A0;
    const bool st = a_structured(Alog, d, A0);
    const float Dd = Dvec[d];
    __syncthreads();

    float h[DS];
    {
        const size_t base = (size_t)c * BDN + ((size_t)b * DI + d) * DS;
#pragma unroll
        for (int n = 0; n < DS; n++) h[n] = g_hin[base + n];
    }

    const float* dp = g_delta + ((size_t)b * L + l0) * DI + d;
    const float* up = g_u + ((size_t)b * L + l0) * DI + d;
    float* yp = g_y + ((size_t)b * L + l0) * DI + d;

    if (st) {
        for (int l = 0; l < CHL; l++) {
            const float dl = dp[(size_t)l * DI];
            const float uu = up[(size_t)l * DI];
            const float du = dl * uu;
            float av[DS];
            pow_chain(__expf(dl * A0), av);
            float y = uu * Dd;
#pragma unroll
            for (int n = 0; n < DS; n++) {
                h[n] = fmaf(av[n], h[n], du * sB[l][n]);
                y = fmaf(h[n], sC[l][n], y);
            }
            yp[(size_t)l * DI] = y;
        }
    } else {
        float A[DS];
#pragma unroll
        for (int n = 0; n < DS; n++) A[n] = -__expf(Alog[(size_t)d * DS + n]);
        for (int l = 0; l < CHL; l++) {
            const float dl = dp[(size_t)l * DI];
            const float uu = up[(size_t)l * DI];
            const float du = dl * uu;
            float y = uu * Dd;
#pragma unroll
            for (int n = 0; n < DS; n++) {
                h[n] = fmaf(__expf(dl * A[n]), h[n], du * sB[l][n]);
                y = fmaf(h[n], sC[l][n], y);
            }
            yp[(size_t)l * DI] = y;
        }
    }
}

// ---------------- k_lngate: yg = LN(y)*g + b, gated by SiLU(z) -> g_xi ----------------
__global__ __launch_bounds__(256) void k_lngate(const float* __restrict__ lng,
                                                const float* __restrict__ lnb)
{
    const int tid = threadIdx.x;
    const int r0 = blockIdx.x * 16;
    const int warp = tid >> 5, lane = tid & 31;

#pragma unroll
    for (int rr = 0; rr < 2; rr++) {
        const int r = warp * 2 + rr;
        const size_t row = (size_t)(r0 + r);
        float v[12];
        float s = 0.f, sq = 0.f;
#pragma unroll
        for (int i = 0; i < 12; i++) {
            v[i] = g_y[row * DI + lane + 32 * i];
            s += v[i];
            sq = fmaf(v[i], v[i], sq);
        }
#pragma unroll
        for (int o = 16; o > 0; o >>= 1) {
            s += __shfl_xor_sync(0xFFFFFFFFu, s, o);
            sq += __shfl_xor_sync(0xFFFFFFFFu, sq, o);
        }
        const float mu = s * (1.f / DI);
        const float var = sq * (1.f / DI) - mu * mu;
        const float rs = rsqrtf(var + 1e-5f);
#pragma unroll
        for (int i = 0; i < 12; i++) {
            const int k = lane + 32 * i;
            const float zn = g_z[row * DI + k];
            const float sig = 1.f / (1.f + __expf(-zn));
            const float g = fmaf((v[i] - mu) * rs, lng[k], lnb[k]);
            g_xi[row * DI + k] = g * zn * sig;
        }
    }
}

// ---------------- k_gemm_out: out = yg @ Wout via tf32x3 ----------------
// 128x64 tile, K=384 in 12 chunks. grid (128, 3).
__global__ __launch_bounds__(256) void k_gemm_out(float* __restrict__ out)
{
    extern __shared__ float osm[];
    float (*sAh)[AP] = (float(*)[AP])osm;
    float (*sAl)[AP] = (float(*)[AP])(osm + 128 * AP);
    float (*sBh)[AP] = (float(*)[AP])(osm + 256 * AP);
    float (*sBl)[AP] = (float(*)[AP])(osm + 256 * AP + 64 * AP);

    const int tid = threadIdx.x;
    const int wid = tid >> 5, t = tid & 31;
    const int m0 = blockIdx.x * 128, n0 = blockIdx.y * 64;
    const int wr = wid & 3, wc = wid >> 2;
    const int g = t >> 2, c = t & 3, c2 = c * 2;

    float acc[2][4][4];
#pragma unroll
    for (int mt = 0; mt < 2; mt++)
#pragma unroll
        for (int nt = 0; nt < 4; nt++)
#pragma unroll
            for (int e = 0; e < 4; e++) acc[mt][nt][e] = 0.f;

    const int lr = tid >> 1;
    const int lh = (tid & 1) * 16;
    const int lrB = tid >> 2;
    const int lhB = (tid & 3) * 8;

    for (int kc = 0; kc < DI; kc += 32) {
        {
            const float* ap = g_xi + (size_t)(m0 + lr) * DI + kc + lh;
#pragma unroll
            for (int q = 0; q < 4; q++) {
                float4 v = *(const float4*)(ap + q * 4);
                float4 hv = make_float4(tf32v(v.x), tf32v(v.y), tf32v(v.z), tf32v(v.w));
                float4 lv = make_float4(tf32v(v.x - hv.x), tf32v(v.y - hv.y),
                                        tf32v(v.z - hv.z), tf32v(v.w - hv.w));
                *(float4*)&sAh[lr][lh + q * 4] = hv;
                *(float4*)&sAl[lr][lh + q * 4] = lv;
            }
            const float* bh = g_wohi + (size_t)(n0 + lrB) * DI + kc + lhB;
            const float* bl = g_wolo + (size_t)(n0 + lrB) * DI + kc + lhB;
#pragma unroll
            for (int q = 0; q < 2; q++) {
                *(float4*)&sBh[lrB][lhB + q * 4] = *(const float4*)(bh + q * 4);
                *(float4*)&sBl[lrB][lhB + q * 4] = *(const float4*)(bl + q * 4);
            }
        }
        __syncthreads();

#pragma unroll
        for (int ks = 0; ks < 4; ks++) {
            const int K0 = ks * 8;
            uint32_t ah[2][4], al[2][4];
#pragma unroll
            for (int mt = 0; mt < 2; mt++) {
                const int R = wr * 32 + mt * 16;
                ah[mt][0] = *(const uint32_t*)&sAh[R + g][K0 + c];
                ah[mt][1] = *(const uint32_t*)&sAh[R + g + 8][K0 + c];
                ah[mt][2] = *(const uint32_t*)&sAh[R + g][K0 + c + 4];
                ah[mt][3] = *(const uint32_t*)&sAh[R + g + 8][K0 + c + 4];
                al[mt][0] = *(const uint32_t*)&sAl[R + g][K0 + c];
                al[mt][1] = *(const uint32_t*)&sAl[R + g + 8][K0 + c];
                al[mt][2] = *(const uint32_t*)&sAl[R + g][K0 + c + 4];
                al[mt][3] = *(const uint32_t*)&sAl[R + g + 8][K0 + c + 4];
            }
#pragma unroll
            for (int nt = 0; nt < 4; nt++) {
                const int N = wc * 32 + nt * 8;
                uint32_t bh[2], bl[2];
                bh[0] = *(const uint32_t*)&sBh[N + g][K0 + c];
                bh[1] = *(const uint32_t*)&sBh[N + g][K0 + c + 4];
                bl[0] = *(const uint32_t*)&sBl[N + g][K0 + c];
                bl[1] = *(const uint32_t*)&sBl[N + g][K0 + c + 4];
#pragma unroll
                for (int mt = 0; mt < 2; mt++) {
                    mma_tf32(acc[mt][nt], ah[mt], bh);
                    mma_tf32(acc[mt][nt], ah[mt], bl);
                    mma_tf32(acc[mt][nt], al[mt], bh);
                }
            }
        }
        __syncthreads();
    }

#pragma unroll
    for (int mt = 0; mt < 2; mt++) {
#pragma unroll
        for (int nt = 0; nt < 4; nt++) {
            const int col = n0 + wc * 32 + nt * 8 + c2;
            const int r0 = m0 + wr * 32 + mt * 16 + g;
            *(float2*)&out[(size_t)r0 * CM + col] =
                make_float2(acc[mt][nt][0], acc[mt][nt][1]);
            *(float2*)&out[(size_t)(r0 + 8) * CM + col] =
                make_float2(acc[mt][nt][2], acc[mt][nt][3]);
        }
    }
}

// ---------------- launch ----------------
extern "C" void kernel_launch(void* const* d_in, const int* in_sizes, int n_in,
                              void* d_out, int out_size)
{
    const float* x      = (const float*)d_in[0];
    const float* prompt = (const float*)d_in[1];
    const float* W_in   = (const float*)d_in[2];
    const float* conv_w = (const float*)d_in[3];
    const float* conv_b = (const float*)d_in[4];
    const float* Wx     = (const float*)d_in[5];
    const float* Wdt    = (const float*)d_in[6];
    const float* b_dt   = (const float*)d_in[7];
    const float* A_log  = (const float*)d_in[8];
    const float* Dv     = (const float*)d_in[9];
    const float* Wp     = (const float*)d_in[10];
    const float* ln_g   = (const float*)d_in[11];
    const float* ln_b   = (const float*)d_in[12];
    const float* Wout   = (const float*)d_in[13];
    float* out = (float*)d_out;

    static bool attr_set = false;
    if (!attr_set) {
        cudaFuncSetAttribute(k_conv, cudaFuncAttributeMaxDynamicSharedMemorySize, 51200);
        cudaFuncSetAttribute(k_proj_mma, cudaFuncAttributeMaxDynamicSharedMemorySize, 55296);
        cudaFuncSetAttribute(k_gemm_out, cudaFuncAttributeMaxDynamicSharedMemorySize, 55296);
        attr_set = true;
    }

    k_prep_w<<<(CM * NX + 255) / 256, 256>>>(W_in);
    k_prep_pw<<<(NP * KC + 255) / 256, 256>>>(Wx, Wp);
    k_prep_wout<<<(CM * DI + 255) / 256, 256>>>(Wout);
    k_gemm_tf32<<<dim3(M_ROWS / 128, NX / 128), 256>>>(x);
    k_conv<<<dim3(64, 3, BATCH), dim3(128, 8), 51200>>>(conv_w, conv_b);
    k_proj_mma<<<M_ROWS / 128, 256, 55296>>>(prompt);
    k_delta<<<M_ROWS / 8, DI>>>(Wdt, b_dt);
    k_scan1<<<dim3(DI / 128, NCH, BATCH), 128>>>(A_log);
    k_scan2<<<(BDN + 255) / 256, 256>>>();
    k_scan3<<<dim3(DI / 128, NCH, BATCH), 128>>>(A_log, Dv);
    k_lngate<<<M_ROWS / 16, 256>>>(ln_g, ln_b);
    k_gemm_out<<<dim3(M_ROWS / 128, 3), 256, 55296>>>(out);
}

// round 11
// speedup vs baseline: 1.2260x; 1.0153x over previous
#include <cuda_runtime.h>
#include <cuda_bf16.h>
#include <cstdint>

#define BATCH 4
#define L 4096
#define CM 192
#define DI 384
#define DS 16
#define DTR 12
#define M_ROWS (BATCH * L)   // 16384
#define NCH 128
#define CHL (L / NCH)        // 32
#define BDN (BATCH * DI * DS) // 24576
#define NX (2 * DI)          // 768
#define KC 576
#define NP 64
#define AP 36
#define ASTG (128 * AP)      // 4608 floats per A stage
#define BSTG (64 * AP)       // 2304 floats per 64-row B stage

// ---------------- scratch ----------------
__device__ float g_xi[(size_t)M_ROWS * DI];
__device__ float g_z[(size_t)M_ROWS * DI];
__device__ float g_u[(size_t)M_ROWS * DI];
__device__ float g_delta[(size_t)M_ROWS * DI];
__device__ float g_dtr[(size_t)M_ROWS * DTR];
__device__ float g_Bs[(size_t)M_ROWS * DS];
__device__ float g_Cs[(size_t)M_ROWS * DS];
__device__ float g_y[(size_t)M_ROWS * DI];
__device__ float g_hpart[(size_t)NCH * BDN];
__device__ float g_aP[(size_t)NCH * BDN];
__device__ float g_hin[(size_t)NCH * BDN];
__device__ float g_wt[(size_t)NX * CM];
__device__ float g_pwhi[(size_t)NP * KC];
__device__ float g_pwlo[(size_t)NP * KC];
__device__ float g_wohi[(size_t)CM * DI];
__device__ float g_wolo[(size_t)CM * DI];

__device__ __forceinline__ uint32_t f2tf32(float f)
{
    uint32_t r;
    asm("cvt.rna.tf32.f32 %0, %1;" : "=r"(r) : "f"(f));
    return r;
}
__device__ __forceinline__ float tf32v(float f) { return __uint_as_float(f2tf32(f)); }

#define CP16(dst, src) \
    asm volatile("cp.async.cg.shared.global [%0], [%1], 16;" :: "r"(dst), "l"(src))
#define CP_COMMIT() asm volatile("cp.async.commit_group;" ::: "memory")
#define CP_WAIT0()  asm volatile("cp.async.wait_group 0;" ::: "memory")
#define CP_WAIT1()  asm volatile("cp.async.wait_group 1;" ::: "memory")

// ---------------- prep kernels ----------------
__global__ void k_prep_w(const float* __restrict__ Win)
{
    const int i = blockIdx.x * 256 + threadIdx.x;
    if (i >= CM * NX) return;
    const int k = i / NX, n = i % NX;
    g_wt[(size_t)n * CM + k] = tf32v(Win[i]);
}

__global__ void k_prep_pw(const float* __restrict__ Wx, const float* __restrict__ Wp)
{
    const int i = blockIdx.x * 256 + threadIdx.x;
    if (i >= NP * KC) return;
    const int n = i / KC, k = i % KC;
    float v = 0.f;
    if (n < 44) {
        if (k < DI) v = Wx[(size_t)k * 44 + n];
        else if (n >= 28) v = Wp[(size_t)(k - DI) * DS + (n - 28)];
    }
    const float hi = tf32v(v);
    g_pwhi[i] = hi;
    g_pwlo[i] = tf32v(v - hi);
}

__global__ void k_prep_wout(const float* __restrict__ Wout)
{
    const int i = blockIdx.x * 256 + threadIdx.x;
    if (i >= CM * DI) return;
    const int k = i / CM, n = i % CM;
    const float v = Wout[i];
    const float hi = tf32v(v);
    g_wohi[(size_t)n * DI + k] = hi;
    g_wolo[(size_t)n * DI + k] = tf32v(v - hi);
}

__device__ __forceinline__ void mma_tf32(float* d, const uint32_t* a, const uint32_t* b)
{
    asm volatile(
        "mma.sync.aligned.m16n8k8.row.col.f32.tf32.tf32.f32 "
        "{%0,%1,%2,%3}, {%4,%5,%6,%7}, {%8,%9}, {%0,%1,%2,%3};"
        : "+f"(d[0]), "+f"(d[1]), "+f"(d[2]), "+f"(d[3])
        : "r"(a[0]), "r"(a[1]), "r"(a[2]), "r"(a[3]), "r"(b[0]), "r"(b[1]));
}

// ---------------- K1: xz = x @ W_in (single-pass tf32, cp.async pipeline) ----------------
// smem: A raw fp32 2 stages @ 0, 4608; B (pre-rounded) 2 stages @ 9216, 13824.
__global__ __launch_bounds__(256) void k_gemm_tf32(const float* __restrict__ X)
{
    extern __shared__ float sm[];
    const uint32_t sbase = (uint32_t)__cvta_generic_to_shared(sm);
    const int tid = threadIdx.x;
    const int wid = tid >> 5, t = tid & 31;
    const int m0 = blockIdx.x * 128, n0 = blockIdx.y * 128;
    const int wr = wid & 3, wc = wid >> 2;
    const int g = t >> 2, c = t & 3, c2 = c * 2;

    float acc[2][8][4];
#pragma unroll
    for (int mt = 0; mt < 2; mt++)
#pragma unroll
        for (int nt = 0; nt < 8; nt++)
#pragma unroll
            for (int e = 0; e < 4; e++) acc[mt][nt][e] = 0.f;

    const int lr = tid >> 1;
    const int lh = (tid & 1) * 16;
    const float* arow = X + (size_t)(m0 + lr) * CM + lh;
    const float* brow = g_wt + (size_t)(n0 + lr) * CM + lh;
    const uint32_t adst = sbase + (uint32_t)(lr * AP + lh) * 4;
    const uint32_t bdst = sbase + (uint32_t)(9216 + lr * AP + lh) * 4;

#define K1_ISSUE(i) do { \
        const int st_ = (i) & 1; const int kc_ = (i) * 32; \
        _Pragma("unroll") \
        for (int q = 0; q < 4; q++) { \
            CP16(adst + (uint32_t)(st_ * ASTG + q * 4) * 4, arow + kc_ + q * 4); \
            CP16(bdst + (uint32_t)(st_ * ASTG + q * 4) * 4, brow + kc_ + q * 4); \
        } \
        CP_COMMIT(); \
    } while (0)

    K1_ISSUE(0);

    for (int i = 0; i < 6; i++) {
        if (i + 1 < 6) { K1_ISSUE(i + 1); CP_WAIT1(); }
        else CP_WAIT0();
        __syncthreads();

        const float* cA = sm + (i & 1) * ASTG;
        const float* cB = sm + 9216 + (i & 1) * ASTG;
#pragma unroll
        for (int ks = 0; ks < 4; ks++) {
            const int K0 = ks * 8;
            uint32_t af[2][4];
#pragma unroll
            for (int mt = 0; mt < 2; mt++) {
                const int R = wr * 32 + mt * 16;
                af[mt][0] = f2tf32(cA[(R + g) * AP + K0 + c]);
                af[mt][1] = f2tf32(cA[(R + g + 8) * AP + K0 + c]);
                af[mt][2] = f2tf32(cA[(R + g) * AP + K0 + c + 4]);
                af[mt][3] = f2tf32(cA[(R + g + 8) * AP + K0 + c + 4]);
            }
#pragma unroll
            for (int nt = 0; nt < 8; nt++) {
                const int N = wc * 64 + nt * 8;
                uint32_t bf[2];
                bf[0] = *(const uint32_t*)&cB[(N + g) * AP + K0 + c];
                bf[1] = *(const uint32_t*)&cB[(N + g) * AP + K0 + c + 4];
#pragma unroll
                for (int mt = 0; mt < 2; mt++)
                    mma_tf32(acc[mt][nt], af[mt], bf);
            }
        }
        __syncthreads();
    }
#undef K1_ISSUE

    const bool toZ = (n0 >= DI);
#pragma unroll
    for (int mt = 0; mt < 2; mt++) {
#pragma unroll
        for (int nt = 0; nt < 8; nt++) {
            int nc = n0 + wc * 64 + nt * 8 + c2;
            if (toZ) nc -= DI;
            const int r0 = m0 + wr * 32 + mt * 16 + g;
            float* base = toZ ? g_z : g_xi;
            *(float2*)&base[(size_t)r0 * DI + nc] =
                make_float2(acc[mt][nt][0], acc[mt][nt][1]);
            *(float2*)&base[(size_t)(r0 + 8) * DI + nc] =
                make_float2(acc[mt][nt][2], acc[mt][nt][3]);
        }
    }
}

// ---------------- conv ----------------
__global__ __launch_bounds__(1024) void k_conv(const float* __restrict__ cw,
                                               const float* __restrict__ cb)
{
    extern __shared__ float cs[];
    const int b = blockIdx.z;
    const int d = blockIdx.y * 128 + threadIdx.x;
    const int h0 = (blockIdx.x >> 3) * 8;
    const int w0 = (blockIdx.x & 7) * 8;
    const int tx = threadIdx.x, ty = threadIdx.y;
    const size_t base = (size_t)b * L * DI;

#pragma unroll
    for (int i = 0; i < 13; i++) {
        const int p = ty + 8 * i;
        if (p < 100) {
            const int rr = p / 10, cc = p % 10;
            const int hh = h0 + rr - 1, ww = w0 + cc - 1;
            float v = 0.f;
            if (hh >= 0 && hh < 64 && ww >= 0 && ww < 64)
                v = g_xi[base + (size_t)(hh * 64 + ww) * DI + d];
            cs[p * 128 + tx] = v;
        }
    }
    __syncthreads();

    float W[9];
#pragma unroll
    for (int i = 0; i < 9; i++) W[i] = cw[d * 9 + i];
    const float bias = cb[d];

    float acc[8];
#pragma unroll
    for (int j = 0; j < 8; j++) acc[j] = bias;

#pragma unroll
    for (int r = 0; r < 3; r++) {
        float rv[10];
#pragma unroll
        for (int cc = 0; cc < 10; cc++) rv[cc] = cs[((ty + r) * 10 + cc) * 128 + tx];
#pragma unroll
        for (int j = 0; j < 8; j++) {
            acc[j] = fmaf(rv[j],     W[r * 3 + 0], acc[j]);
            acc[j] = fmaf(rv[j + 1], W[r * 3 + 1], acc[j]);
            acc[j] = fmaf(rv[j + 2], W[r * 3 + 2], acc[j]);
        }
    }
#pragma unroll
    for (int j = 0; j < 8; j++) {
        const float sig = 1.f / (1.f + __expf(-acc[j]));
        g_u[base + (size_t)((h0 + ty) * 64 + w0 + j) * DI + d] = acc[j] * sig;
    }
}

// ---------------- k_proj_mma: [u|prompt] @ Wcat via tf32x3 (cp.async pipeline) ----------------
// smem: A raw 2 stages @ 0, 4608; Bh @ 9216 + st*2304; Bl @ 13824 + st*2304.
__global__ __launch_bounds__(256) void k_proj_mma(const float* __restrict__ prompt)
{
    extern __shared__ float sm[];
    const uint32_t sbase = (uint32_t)__cvta_generic_to_shared(sm);
    const int tid = threadIdx.x;
    const int wid = tid >> 5, t = tid & 31;
    const int m0 = blockIdx.x * 128;
    const int wr = wid & 3, wc = wid >> 2;
    const int g = t >> 2, c = t & 3, c2 = c * 2;

    float acc[2][4][4];
#pragma unroll
    for (int mt = 0; mt < 2; mt++)
#pragma unroll
        for (int nt = 0; nt < 4; nt++)
#pragma unroll
            for (int e = 0; e < 4; e++) acc[mt][nt][e] = 0.f;

    const int lr = tid >> 1;
    const int lh = (tid & 1) * 16;
    const int lrB = tid >> 2;
    const int lhB = (tid & 3) * 8;
    const float* urow = g_u + (size_t)(m0 + lr) * DI + lh;
    const float* prow = prompt + (size_t)(m0 + lr) * CM + lh;
    const float* bhrow = g_pwhi + (size_t)lrB * KC + lhB;
    const float* blrow = g_pwlo + (size_t)lrB * KC + lhB;
    const uint32_t adst = sbase + (uint32_t)(lr * AP + lh) * 4;
    const uint32_t bhdst = sbase + (uint32_t)(9216 + lrB * AP + lhB) * 4;
    const uint32_t bldst = sbase + (uint32_t)(13824 + lrB * AP + lhB) * 4;

#define PJ_ISSUE(i) do { \
        const int st_ = (i) & 1; const int kc_ = (i) * 32; \
        const float* ar_ = (kc_ < DI) ? urow + kc_ : prow + (kc_ - DI); \
        _Pragma("unroll") \
        for (int q = 0; q < 4; q++) \
            CP16(adst + (uint32_t)(st_ * ASTG + q * 4) * 4, ar_ + q * 4); \
        _Pragma("unroll") \
        for (int q = 0; q < 2; q++) { \
            CP16(bhdst + (uint32_t)(st_ * BSTG + q * 4) * 4, bhrow + kc_ + q * 4); \
            CP16(bldst + (uint32_t)(st_ * BSTG + q * 4) * 4, blrow + kc_ + q * 4); \
        } \
        CP_COMMIT(); \
    } while (0)

    PJ_ISSUE(0);

    for (int i = 0; i < 18; i++) {
        if (i + 1 < 18) { PJ_ISSUE(i + 1); CP_WAIT1(); }
        else CP_WAIT0();
        __syncthreads();

        const float* cA = sm + (i & 1) * ASTG;
        const float* cBh = sm + 9216 + (i & 1) * BSTG;
        const float* cBl = sm + 13824 + (i & 1) * BSTG;
#pragma unroll
        for (int ks = 0; ks < 4; ks++) {
            const int K0 = ks * 8;
            uint32_t ah[2][4], al[2][4];
#pragma unroll
            for (int mt = 0; mt < 2; mt++) {
                const int R = wr * 32 + mt * 16;
#pragma unroll
                for (int j = 0; j < 4; j++) {
                    const int rr = R + g + (j & 1) * 8;
                    const int ccol = K0 + c + (j >> 1) * 4;
                    const float raw = cA[rr * AP + ccol];
                    const float hv = tf32v(raw);
                    ah[mt][j] = __float_as_uint(hv);
                    al[mt][j] = f2tf32(raw - hv);
                }
            }
#pragma unroll
            for (int nt = 0; nt < 4; nt++) {
                const int N = wc * 32 + nt * 8;
                uint32_t bh[2], bl[2];
                bh[0] = *(const uint32_t*)&cBh[(N + g) * AP + K0 + c];
                bh[1] = *(const uint32_t*)&cBh[(N + g) * AP + K0 + c + 4];
                bl[0] = *(const uint32_t*)&cBl[(N + g) * AP + K0 + c];
                bl[1] = *(const uint32_t*)&cBl[(N + g) * AP + K0 + c + 4];
#pragma unroll
                for (int mt = 0; mt < 2; mt++) {
                    mma_tf32(acc[mt][nt], ah[mt], bh);
                    mma_tf32(acc[mt][nt], ah[mt], bl);
                    mma_tf32(acc[mt][nt], al[mt], bh);
                }
            }
        }
        __syncthreads();
    }
#undef PJ_ISSUE

#pragma unroll
    for (int mt = 0; mt < 2; mt++) {
#pragma unroll
        for (int nt = 0; nt < 4; nt++) {
            const int col = wc * 32 + nt * 8 + c2;
            const int r0 = m0 + wr * 32 + mt * 16 + g;
#pragma unroll
            for (int hrow = 0; hrow < 2; hrow++) {
                const size_t row = (size_t)(r0 + hrow * 8);
                const float v0 = acc[mt][nt][hrow * 2 + 0];
                const float v1 = acc[mt][nt][hrow * 2 + 1];
                if (col < DTR)
                    *(float2*)&g_dtr[row * DTR + col] = make_float2(v0, v1);
                else if (col < DTR + DS)
                    *(float2*)&g_Bs[row * DS + (col - DTR)] = make_float2(v0, v1);
                else if (col < 44)
                    *(float2*)&g_Cs[row * DS + (col - DTR - DS)] = make_float2(v0, v1);
            }
        }
    }
}

// ---------------- k_delta ----------------
__global__ void k_delta(const float* __restrict__ Wdt, const float* __restrict__ bdt)
{
    __shared__ float sd[8][DTR];
    const int tid = threadIdx.x;
    const int row0 = blockIdx.x * 8;
    if (tid < 8 * DTR) sd[tid / DTR][tid % DTR] = g_dtr[(size_t)(row0 + tid / DTR) * DTR + tid % DTR];
    __syncthreads();

    float w[DTR];
#pragma unroll
    for (int rr = 0; rr < DTR; rr++) w[rr] = Wdt[(size_t)rr * DI + tid];
    const float bb = bdt[tid];
#pragma unroll
    for (int rr = 0; rr < 8; rr++) {
        float acc = bb;
#pragma unroll
        for (int r2 = 0; r2 < DTR; r2++) acc = fmaf(sd[rr][r2], w[r2], acc);
        const float sp = acc > 20.f ? acc : log1pf(__expf(acc));
        g_delta[(size_t)(row0 + rr) * DI + tid] = sp;
    }
}

// ---------------- scan helpers ----------------
__device__ __forceinline__ void pow_chain(float e1, float* av)
{
    const float e2 = e1 * e1, e4 = e2 * e2, e8 = e4 * e4;
    av[0] = e1;       av[1] = e2;       av[2] = e2 * e1;   av[3] = e4;
    av[4] = e4 * e1;  av[5] = e4 * e2;  av[6] = e4 * av[2]; av[7] = e8;
    av[8] = e8 * e1;  av[9] = e8 * e2;  av[10] = e8 * av[2]; av[11] = e8 * e4;
    av[12] = e8 * av[4]; av[13] = e8 * av[5]; av[14] = e8 * av[6]; av[15] = e8 * e8;
}

__device__ __forceinline__ bool a_structured(const float* __restrict__ Alog, int d, float& A0)
{
    A0 = -__expf(Alog[(size_t)d * DS]);
    bool ok = true;
#pragma unroll
    for (int n = 1; n < DS; n++) {
        const float Av = -__expf(Alog[(size_t)d * DS + n]);
        ok &= fabsf(Av - (n + 1) * A0) <= 1e-4f * fabsf((n + 1) * A0);
    }
    return ok;
}

// ---------------- S1 ----------------
__global__ void k_scan1(const float* __restrict__ Alog)
{
    __shared__ float sB[CHL][DS];
    const int d = blockIdx.x * 128 + threadIdx.x;
    const int c = blockIdx.y;
    const int b = blockIdx.z;
    const int l0 = c * CHL;

    {
        const float4* src = (const float4*)g_Bs + ((size_t)b * L + l0) * 4;
        ((float4*)sB)[threadIdx.x] = src[threadIdx.x];
    }

    float A0;
    const bool st = a_structured(Alog, d, A0);
    __syncthreads();

    float h[DS];
#pragma unroll
    for (int n = 0; n < DS; n++) h[n] = 0.f;
    float dsum = 0.f;

    const float* dp = g_delta + ((size_t)b * L + l0) * DI + d;
    const float* up = g_u + ((size_t)b * L + l0) * DI + d;

    if (st) {
        for (int l = 0; l < CHL; l++) {
            const float dl = dp[(size_t)l * DI];
            const float du = dl * up[(size_t)l * DI];
            dsum += dl;
            float av[DS];
            pow_chain(__expf(dl * A0), av);
#pragma unroll
            for (int n = 0; n < DS; n++) h[n] = fmaf(av[n], h[n], du * sB[l][n]);
        }
        float av[DS];
        pow_chain(__expf(dsum * A0), av);
        const size_t base = (size_t)c * BDN + ((size_t)b * DI + d) * DS;
#pragma unroll
        for (int n = 0; n < DS; n++) {
            g_hpart[base + n] = h[n];
            g_aP[base + n] = av[n];
        }
    } else {
        float A[DS];
#pragma unroll
        for (int n = 0; n < DS; n++) A[n] = -__expf(Alog[(size_t)d * DS + n]);
        for (int l = 0; l < CHL; l++) {
            const float dl = dp[(size_t)l * DI];
            const float du = dl * up[(size_t)l * DI];
            dsum += dl;
#pragma unroll
            for (int n = 0; n < DS; n++)
                h[n] = fmaf(__expf(dl * A[n]), h[n], du * sB[l][n]);
        }
        const size_t base = (size_t)c * BDN + ((size_t)b * DI + d) * DS;
#pragma unroll
        for (int n = 0; n < DS; n++) {
            g_hpart[base + n] = h[n];
            g_aP[base + n] = __expf(A[n] * dsum);
        }
    }
}

// ---------------- S2 ----------------
__global__ void k_scan2()
{
    const int idx = blockIdx.x * 256 + threadIdx.x;
    if (idx >= BDN) return;
    float h = 0.f;
    for (int c = 0; c < NCH; c++) {
        const size_t o = (size_t)c * BDN + idx;
        g_hin[o] = h;
        h = fmaf(g_aP[o], h, g_hpart[o]);
    }
}

// ---------------- S3 ----------------
__global__ void k_scan3(const float* __restrict__ Alog, const float* __restrict__ Dvec)
{
    __shared__ float sB[CHL][DS];
    __shared__ float sC[CHL][DS];
    const int d = blockIdx.x * 128 + threadIdx.x;
    const int c = blockIdx.y;
    const int b = blockIdx.z;
    const int l0 = c * CHL;

    {
        const float4* srcB = (const float4*)g_Bs + ((size_t)b * L + l0) * 4;
        const float4* srcC = (const float4*)g_Cs + ((size_t)b * L + l0) * 4;
        ((float4*)sB)[threadIdx.x] = srcB[threadIdx.x];
        ((float4*)sC)[threadIdx.x] = srcC[threadIdx.x];
    }

    float A0;
    const bool st = a_structured(Alog, d, A0);
    const float Dd = Dvec[d];
    __syncthreads();

    float h[DS];
    {
        const size_t base = (size_t)c * BDN + ((size_t)b * DI + d) * DS;
#pragma unroll
        for (int n = 0; n < DS; n++) h[n] = g_hin[base + n];
    }

    const float* dp = g_delta + ((size_t)b * L + l0) * DI + d;
    const float* up = g_u + ((size_t)b * L + l0) * DI + d;
    float* yp = g_y + ((size_t)b * L + l0) * DI + d;

    if (st) {
        for (int l = 0; l < CHL; l++) {
            const float dl = dp[(size_t)l * DI];
            const float uu = up[(size_t)l * DI];
            const float du = dl * uu;
            float av[DS];
            pow_chain(__expf(dl * A0), av);
            float y = uu * Dd;
#pragma unroll
            for (int n = 0; n < DS; n++) {
                h[n] = fmaf(av[n], h[n], du * sB[l][n]);
                y = fmaf(h[n], sC[l][n], y);
            }
            yp[(size_t)l * DI] = y;
        }
    } else {
        float A[DS];
#pragma unroll
        for (int n = 0; n < DS; n++) A[n] = -__expf(Alog[(size_t)d * DS + n]);
        for (int l = 0; l < CHL; l++) {
            const float dl = dp[(size_t)l * DI];
            const float uu = up[(size_t)l * DI];
            const float du = dl * uu;
            float y = uu * Dd;
#pragma unroll
            for (int n = 0; n < DS; n++) {
                h[n] = fmaf(__expf(dl * A[n]), h[n], du * sB[l][n]);
                y = fmaf(h[n], sC[l][n], y);
            }
            yp[(size_t)l * DI] = y;
        }
    }
}

// ---------------- k_lngate ----------------
__global__ __launch_bounds__(256) void k_lngate(const float* __restrict__ lng,
                                                const float* __restrict__ lnb)
{
    const int tid = threadIdx.x;
    const int r0 = blockIdx.x * 16;
    const int warp = tid >> 5, lane = tid & 31;

#pragma unroll
    for (int rr = 0; rr < 2; rr++) {
        const int r = warp * 2 + rr;
        const size_t row = (size_t)(r0 + r);
        float v[12];
        float s = 0.f, sq = 0.f;
#pragma unroll
        for (int i = 0; i < 12; i++) {
            v[i] = g_y[row * DI + lane + 32 * i];
            s += v[i];
            sq = fmaf(v[i], v[i], sq);
        }
#pragma unroll
        for (int o = 16; o > 0; o >>= 1) {
            s += __shfl_xor_sync(0xFFFFFFFFu, s, o);
            sq += __shfl_xor_sync(0xFFFFFFFFu, sq, o);
        }
        const float mu = s * (1.f / DI);
        const float var = sq * (1.f / DI) - mu * mu;
        const float rs = rsqrtf(var + 1e-5f);
#pragma unroll
        for (int i = 0; i < 12; i++) {
            const int k = lane + 32 * i;
            const float zn = g_z[row * DI + k];
            const float sig = 1.f / (1.f + __expf(-zn));
            const float g = fmaf((v[i] - mu) * rs, lng[k], lnb[k]);
            g_xi[row * DI + k] = g * zn * sig;
        }
    }
}

// ---------------- k_gemm_out: out = yg @ Wout via tf32x3 (cp.async pipeline) ----------------
__global__ __launch_bounds__(256) void k_gemm_out(float* __restrict__ out)
{
    extern __shared__ float sm[];
    const uint32_t sbase = (uint32_t)__cvta_generic_to_shared(sm);
    const int tid = threadIdx.x;
    const int wid = tid >> 5, t = tid & 31;
    const int m0 = blockIdx.x * 128, n0 = blockIdx.y * 64;
    const int wr = wid & 3, wc = wid >> 2;
    const int g = t >> 2, c = t & 3, c2 = c * 2;

    float acc[2][4][4];
#pragma unroll
    for (int mt = 0; mt < 2; mt++)
#pragma unroll
        for (int nt = 0; nt < 4; nt++)
#pragma unroll
            for (int e = 0; e < 4; e++) acc[mt][nt][e] = 0.f;

    const int lr = tid >> 1;
    const int lh = (tid & 1) * 16;
    const int lrB = tid >> 2;
    const int lhB = (tid & 3) * 8;
    const float* arow = g_xi + (size_t)(m0 + lr) * DI + lh;
    const float* bhrow = g_wohi + (size_t)(n0 + lrB) * DI + lhB;
    const float* blrow = g_wolo + (size_t)(n0 + lrB) * DI + lhB;
    const uint32_t adst = sbase + (uint32_t)(lr * AP + lh) * 4;
    const uint32_t bhdst = sbase + (uint32_t)(9216 + lrB * AP + lhB) * 4;
    const uint32_t bldst = sbase + (uint32_t)(13824 + lrB * AP + lhB) * 4;

#define GO_ISSUE(i) do { \
        const int st_ = (i) & 1; const int kc_ = (i) * 32; \
        _Pragma("unroll") \
        for (int q = 0; q < 4; q++) \
            CP16(adst + (uint32_t)(st_ * ASTG + q * 4) * 4, arow + kc_ + q * 4); \
        _Pragma("unroll") \
        for (int q = 0; q < 2; q++) { \
            CP16(bhdst + (uint32_t)(st_ * BSTG + q * 4) * 4, bhrow + kc_ + q * 4); \
            CP16(bldst + (uint32_t)(st_ * BSTG + q * 4) * 4, blrow + kc_ + q * 4); \
        } \
        CP_COMMIT(); \
    } while (0)

    GO_ISSUE(0);

    for (int i = 0; i < 12; i++) {
        if (i + 1 < 12) { GO_ISSUE(i + 1); CP_WAIT1(); }
        else CP_WAIT0();
        __syncthreads();

        const float* cA = sm + (i & 1) * ASTG;
        const float* cBh = sm + 9216 + (i & 1) * BSTG;
        const float* cBl = sm + 13824 + (i & 1) * BSTG;
#pragma unroll
        for (int ks = 0; ks < 4; ks++) {
            const int K0 = ks * 8;
            uint32_t ah[2][4], al[2][4];
#pragma unroll
            for (int mt = 0; mt < 2; mt++) {
                const int R = wr * 32 + mt * 16;
#pragma unroll
                for (int j = 0; j < 4; j++) {
                    const int rr = R + g + (j & 1) * 8;
                    const int ccol = K0 + c + (j >> 1) * 4;
                    const float raw = cA[rr * AP + ccol];
                    const float hv = tf32v(raw);
                    ah[mt][j] = __float_as_uint(hv);
                    al[mt][j] = f2tf32(raw - hv);
                }
            }
#pragma unroll
            for (int nt = 0; nt < 4; nt++) {
                const int N = wc * 32 + nt * 8;
                uint32_t bh[2], bl[2];
                bh[0] = *(const uint32_t*)&cBh[(N + g) * AP + K0 + c];
                bh[1] = *(const uint32_t*)&cBh[(N + g) * AP + K0 + c + 4];
                bl[0] = *(const uint32_t*)&cBl[(N + g) * AP + K0 + c];
                bl[1] = *(const uint32_t*)&cBl[(N + g) * AP + K0 + c + 4];
#pragma unroll
                for (int mt = 0; mt < 2; mt++) {
                    mma_tf32(acc[mt][nt], ah[mt], bh);
                    mma_tf32(acc[mt][nt], ah[mt], bl);
                    mma_tf32(acc[mt][nt], al[mt], bh);
                }
            }
        }
        __syncthreads();
    }
#undef GO_ISSUE

#pragma unroll
    for (int mt = 0; mt < 2; mt++) {
#pragma unroll
        for (int nt = 0; nt < 4; nt++) {
            const int col = n0 + wc * 32 + nt * 8 + c2;
            const int r0 = m0 + wr * 32 + mt * 16 + g;
            *(float2*)&out[(size_t)r0 * CM + col] =
                make_float2(acc[mt][nt][0], acc[mt][nt][1]);
            *(float2*)&out[(size_t)(r0 + 8) * CM + col] =
                make_float2(acc[mt][nt][2], acc[mt][nt][3]);
        }
    }
}

// ---------------- launch ----------------
extern "C" void kernel_launch(void* const* d_in, const int* in_sizes, int n_in,
                              void* d_out, int out_size)
{
    const float* x      = (const float*)d_in[0];
    const float* prompt = (const float*)d_in[1];
    const float* W_in   = (const float*)d_in[2];
    const float* conv_w = (const float*)d_in[3];
    const float* conv_b = (const float*)d_in[4];
    const float* Wx     = (const float*)d_in[5];
    const float* Wdt    = (const float*)d_in[6];
    const float* b_dt   = (const float*)d_in[7];
    const float* A_log  = (const float*)d_in[8];
    const float* Dv     = (const float*)d_in[9];
    const float* Wp     = (const float*)d_in[10];
    const float* ln_g   = (const float*)d_in[11];
    const float* ln_b   = (const float*)d_in[12];
    const float* Wout   = (const float*)d_in[13];
    float* out = (float*)d_out;

    static bool attr_set = false;
    if (!attr_set) {
        cudaFuncSetAttribute(k_conv, cudaFuncAttributeMaxDynamicSharedMemorySize, 51200);
        cudaFuncSetAttribute(k_gemm_tf32, cudaFuncAttributeMaxDynamicSharedMemorySize, 73728);
        cudaFuncSetAttribute(k_proj_mma, cudaFuncAttributeMaxDynamicSharedMemorySize, 73728);
        cudaFuncSetAttribute(k_gemm_out, cudaFuncAttributeMaxDynamicSharedMemorySize, 73728);
        attr_set = true;
    }

    k_prep_w<<<(CM * NX + 255) / 256, 256>>>(W_in);
    k_prep_pw<<<(NP * KC + 255) / 256, 256>>>(Wx, Wp);
    k_prep_wout<<<(CM * DI + 255) / 256, 256>>>(Wout);
    k_gemm_tf32<<<dim3(M_ROWS / 128, NX / 128), 256, 73728>>>(x);
    k_conv<<<dim3(64, 3, BATCH), dim3(128, 8), 51200>>>(conv_w, conv_b);
    k_proj_mma<<<M_ROWS / 128, 256, 73728>>>(prompt);
    k_delta<<<M_ROWS / 8, DI>>>(Wdt, b_dt);
    k_scan1<<<dim3(DI / 128, NCH, BATCH), 128>>>(A_log);
    k_scan2<<<(BDN + 255) / 256, 256>>>();
    k_scan3<<<dim3(DI / 128, NCH, BATCH), 128>>>(A_log, Dv);
    k_lngate<<<M_ROWS / 16, 256>>>(ln_g, ln_b);
    k_gemm_out<<<dim3(M_ROWS / 128, 3), 256, 73728>>>(out);
}

// round 12
// speedup vs baseline: 1.2505x; 1.0200x over previous
#include <cuda_runtime.h>
#include <cuda_bf16.h>
#include <cstdint>

#define BATCH 4
#define L 4096
#define CM 192
#define DI 384
#define DS 16
#define DTR 12
#define M_ROWS (BATCH * L)   // 16384
#define NCH 128
#define CHL (L / NCH)        // 32
#define BDN (BATCH * DI * DS) // 24576
#define NX (2 * DI)          // 768
#define KC 576
#define NP 64
#define AP 36
#define ASTG (128 * AP)      // 4608 floats per A stage
#define BSTG (64 * AP)       // 2304 floats per 64-row B stage (proj/out kernels)
#define BFRG 2048            // fragment-packed B chunk (64 cols x 32 k)

// ---------------- scratch ----------------
__device__ float g_xi[(size_t)M_ROWS * DI];
__device__ float g_z[(size_t)M_ROWS * DI];
__device__ float g_u[(size_t)M_ROWS * DI];
__device__ float g_delta[(size_t)M_ROWS * DI];
__device__ float g_dtr[(size_t)M_ROWS * DTR];
__device__ float g_Bs[(size_t)M_ROWS * DS];
__device__ float g_Cs[(size_t)M_ROWS * DS];
__device__ float g_y[(size_t)M_ROWS * DI];
__device__ float g_hpart[(size_t)NCH * BDN];
__device__ float g_aP[(size_t)NCH * BDN];
__device__ float g_hin[(size_t)NCH * BDN];
__device__ float g_wtf[(size_t)NX * CM];    // W_in in MMA fragment order
__device__ float g_pwhi[(size_t)NP * KC];
__device__ float g_pwlo[(size_t)NP * KC];
__device__ float g_wohi[(size_t)CM * DI];
__device__ float g_wolo[(size_t)CM * DI];

__device__ __forceinline__ uint32_t f2tf32(float f)
{
    uint32_t r;
    asm("cvt.rna.tf32.f32 %0, %1;" : "=r"(r) : "f"(f));
    return r;
}
__device__ __forceinline__ float tf32v(float f) { return __uint_as_float(f2tf32(f)); }

#define CP16(dst, src) \
    asm volatile("cp.async.cg.shared.global [%0], [%1], 16;" :: "r"(dst), "l"(src))
#define CP_COMMIT() asm volatile("cp.async.commit_group;" ::: "memory")
#define CP_WAIT0()  asm volatile("cp.async.wait_group 0;" ::: "memory")
#define CP_WAIT1()  asm volatile("cp.async.wait_group 1;" ::: "memory")

// ---------------- prep kernels ----------------
// W_in fragment order: for ncb (64-col block), kci (32-k chunk):
// value (k, n) -> offset ncb*12288 + kci*2048 + j*256 + ks*64 + t*2 + slot
// where j=(n&63)>>3, g=n&7, ks=(k>>3)&3, cc=k&7, slot=cc>>2, t=g*4+(cc&3).
__global__ void k_prep_w(const float* __restrict__ Win)
{
    const int i = blockIdx.x * 256 + threadIdx.x;
    if (i >= CM * NX) return;
    const int k = i / NX, n = i % NX;
    const int ncb = n >> 6, j = (n & 63) >> 3, gg = n & 7;
    const int kci = k >> 5, ks = (k >> 3) & 3, cc = k & 7;
    const int slot = cc >> 2, tl = gg * 4 + (cc & 3);
    const size_t off = (size_t)ncb * 12288 + kci * 2048 + j * 256 + ks * 64 + tl * 2 + slot;
    g_wtf[off] = tf32v(Win[i]);
}

__global__ void k_prep_pw(const float* __restrict__ Wx, const float* __restrict__ Wp)
{
    const int i = blockIdx.x * 256 + threadIdx.x;
    if (i >= NP * KC) return;
    const int n = i / KC, k = i % KC;
    float v = 0.f;
    if (n < 44) {
        if (k < DI) v = Wx[(size_t)k * 44 + n];
        else if (n >= 28) v = Wp[(size_t)(k - DI) * DS + (n - 28)];
    }
    const float hi = tf32v(v);
    g_pwhi[i] = hi;
    g_pwlo[i] = tf32v(v - hi);
}

__global__ void k_prep_wout(const float* __restrict__ Wout)
{
    const int i = blockIdx.x * 256 + threadIdx.x;
    if (i >= CM * DI) return;
    const int k = i / CM, n = i % CM;
    const float v = Wout[i];
    const float hi = tf32v(v);
    g_wohi[(size_t)n * DI + k] = hi;
    g_wolo[(size_t)n * DI + k] = tf32v(v - hi);
}

__device__ __forceinline__ void mma_tf32(float* d, const uint32_t* a, const uint32_t* b)
{
    asm volatile(
        "mma.sync.aligned.m16n8k8.row.col.f32.tf32.tf32.f32 "
        "{%0,%1,%2,%3}, {%4,%5,%6,%7}, {%8,%9}, {%0,%1,%2,%3};"
        : "+f"(d[0]), "+f"(d[1]), "+f"(d[2]), "+f"(d[3])
        : "r"(a[0]), "r"(a[1]), "r"(a[2]), "r"(a[3]), "r"(b[0]), "r"(b[1]));
}

// ---------------- K1: xz = x @ W_in (tf32, 128x64 tile, frag-packed B) ----------------
// smem floats: A stages @ 0 / 4608; B stages @ 9216 / 11264. Total 13312 (53248 B).
__global__ __launch_bounds__(256) void k_gemm_tf32(const float* __restrict__ X)
{
    extern __shared__ float sm[];
    const uint32_t sbase = (uint32_t)__cvta_generic_to_shared(sm);
    const int tid = threadIdx.x;
    const int wid = tid >> 5, t = tid & 31;
    const int m0 = blockIdx.x * 128, ncb = blockIdx.y;   // 64-col block
    const int wr = wid & 3, wc = wid >> 2;               // 4 row x 2 col groups
    const int g = t >> 2, c = t & 3, c2 = c * 2;

    float acc[2][4][4];
#pragma unroll
    for (int mt = 0; mt < 2; mt++)
#pragma unroll
        for (int nt = 0; nt < 4; nt++)
#pragma unroll
            for (int e = 0; e < 4; e++) acc[mt][nt][e] = 0.f;

    const int lr = tid >> 1;
    const int lh = (tid & 1) * 16;
    const float* arow = X + (size_t)(m0 + lr) * CM + lh;
    const float* bbase = g_wtf + (size_t)ncb * 12288;
    const uint32_t adst = sbase + (uint32_t)(lr * AP + lh) * 4;
    const uint32_t bdst = sbase + (uint32_t)(9216 + tid * 4) * 4;

#define K1_ISSUE(i) do { \
        const int st_ = (i) & 1; const int kc_ = (i) * 32; \
        _Pragma("unroll") \
        for (int q = 0; q < 4; q++) \
            CP16(adst + (uint32_t)(st_ * ASTG + q * 4) * 4, arow + kc_ + q * 4); \
        CP16(bdst + (uint32_t)(st_ * BFRG) * 4, bbase + (i) * 2048 + tid * 4); \
        CP16(bdst + (uint32_t)(st_ * BFRG + 1024) * 4, bbase + (i) * 2048 + 1024 + tid * 4); \
        CP_COMMIT(); \
    } while (0)

    K1_ISSUE(0);

    for (int i = 0; i < 6; i++) {
        if (i + 1 < 6) { K1_ISSUE(i + 1); CP_WAIT1(); }
        else CP_WAIT0();
        __syncthreads();

        const float* cA = sm + (i & 1) * ASTG;
        const float* cB = sm + 9216 + (i & 1) * BFRG;
#pragma unroll
        for (int ks = 0; ks < 4; ks++) {
            const int K0 = ks * 8;
            uint32_t af[2][4];
#pragma unroll
            for (int mt = 0; mt < 2; mt++) {
                const int R = wr * 32 + mt * 16;
                af[mt][0] = f2tf32(cA[(R + g) * AP + K0 + c]);
                af[mt][1] = f2tf32(cA[(R + g + 8) * AP + K0 + c]);
                af[mt][2] = f2tf32(cA[(R + g) * AP + K0 + c + 4]);
                af[mt][3] = f2tf32(cA[(R + g + 8) * AP + K0 + c + 4]);
            }
#pragma unroll
            for (int nt = 0; nt < 4; nt++) {
                const int j = wc * 4 + nt;
                const float2 bv = *(const float2*)&cB[(j * 4 + ks) * 64 + t * 2];
                uint32_t bf[2] = {__float_as_uint(bv.x), __float_as_uint(bv.y)};
#pragma unroll
                for (int mt = 0; mt < 2; mt++)
                    mma_tf32(acc[mt][nt], af[mt], bf);
            }
        }
        __syncthreads();
    }
#undef K1_ISSUE

    const int n0 = ncb * 64;
    const bool toZ = (n0 >= DI);
#pragma unroll
    for (int mt = 0; mt < 2; mt++) {
#pragma unroll
        for (int nt = 0; nt < 4; nt++) {
            int nc = n0 + wc * 32 + nt * 8 + c2;
            if (toZ) nc -= DI;
            const int r0 = m0 + wr * 32 + mt * 16 + g;
            float* base = toZ ? g_z : g_xi;
            *(float2*)&base[(size_t)r0 * DI + nc] =
                make_float2(acc[mt][nt][0], acc[mt][nt][1]);
            *(float2*)&base[(size_t)(r0 + 8) * DI + nc] =
                make_float2(acc[mt][nt][2], acc[mt][nt][3]);
        }
    }
}

// ---------------- conv ----------------
__global__ __launch_bounds__(1024) void k_conv(const float* __restrict__ cw,
                                               const float* __restrict__ cb)
{
    extern __shared__ float cs[];
    const int b = blockIdx.z;
    const int d = blockIdx.y * 128 + threadIdx.x;
    const int h0 = (blockIdx.x >> 3) * 8;
    const int w0 = (blockIdx.x & 7) * 8;
    const int tx = threadIdx.x, ty = threadIdx.y;
    const size_t base = (size_t)b * L * DI;

#pragma unroll
    for (int i = 0; i < 13; i++) {
        const int p = ty + 8 * i;
        if (p < 100) {
            const int rr = p / 10, cc = p % 10;
            const int hh = h0 + rr - 1, ww = w0 + cc - 1;
            float v = 0.f;
            if (hh >= 0 && hh < 64 && ww >= 0 && ww < 64)
                v = g_xi[base + (size_t)(hh * 64 + ww) * DI + d];
            cs[p * 128 + tx] = v;
        }
    }
    __syncthreads();

    float W[9];
#pragma unroll
    for (int i = 0; i < 9; i++) W[i] = cw[d * 9 + i];
    const float bias = cb[d];

    float acc[8];
#pragma unroll
    for (int j = 0; j < 8; j++) acc[j] = bias;

#pragma unroll
    for (int r = 0; r < 3; r++) {
        float rv[10];
#pragma unroll
        for (int cc = 0; cc < 10; cc++) rv[cc] = cs[((ty + r) * 10 + cc) * 128 + tx];
#pragma unroll
        for (int j = 0; j < 8; j++) {
            acc[j] = fmaf(rv[j],     W[r * 3 + 0], acc[j]);
            acc[j] = fmaf(rv[j + 1], W[r * 3 + 1], acc[j]);
            acc[j] = fmaf(rv[j + 2], W[r * 3 + 2], acc[j]);
        }
    }
#pragma unroll
    for (int j = 0; j < 8; j++) {
        const float sig = 1.f / (1.f + __expf(-acc[j]));
        g_u[base + (size_t)((h0 + ty) * 64 + w0 + j) * DI + d] = acc[j] * sig;
    }
}

// ---------------- k_proj_mma: [u|prompt] @ Wcat via tf32x3 (cp.async pipeline) ----------------
__global__ __launch_bounds__(256) void k_proj_mma(const float* __restrict__ prompt)
{
    extern __shared__ float sm[];
    const uint32_t sbase = (uint32_t)__cvta_generic_to_shared(sm);
    const int tid = threadIdx.x;
    const int wid = tid >> 5, t = tid & 31;
    const int m0 = blockIdx.x * 128;
    const int wr = wid & 3, wc = wid >> 2;
    const int g = t >> 2, c = t & 3, c2 = c * 2;

    float acc[2][4][4];
#pragma unroll
    for (int mt = 0; mt < 2; mt++)
#pragma unroll
        for (int nt = 0; nt < 4; nt++)
#pragma unroll
            for (int e = 0; e < 4; e++) acc[mt][nt][e] = 0.f;

    const int lr = tid >> 1;
    const int lh = (tid & 1) * 16;
    const int lrB = tid >> 2;
    const int lhB = (tid & 3) * 8;
    const float* urow = g_u + (size_t)(m0 + lr) * DI + lh;
    const float* prow = prompt + (size_t)(m0 + lr) * CM + lh;
    const float* bhrow = g_pwhi + (size_t)lrB * KC + lhB;
    const float* blrow = g_pwlo + (size_t)lrB * KC + lhB;
    const uint32_t adst = sbase + (uint32_t)(lr * AP + lh) * 4;
    const uint32_t bhdst = sbase + (uint32_t)(9216 + lrB * AP + lhB) * 4;
    const uint32_t bldst = sbase + (uint32_t)(13824 + lrB * AP + lhB) * 4;

#define PJ_ISSUE(i) do { \
        const int st_ = (i) & 1; const int kc_ = (i) * 32; \
        const float* ar_ = (kc_ < DI) ? urow + kc_ : prow + (kc_ - DI); \
        _Pragma("unroll") \
        for (int q = 0; q < 4; q++) \
            CP16(adst + (uint32_t)(st_ * ASTG + q * 4) * 4, ar_ + q * 4); \
        _Pragma("unroll") \
        for (int q = 0; q < 2; q++) { \
            CP16(bhdst + (uint32_t)(st_ * BSTG + q * 4) * 4, bhrow + kc_ + q * 4); \
            CP16(bldst + (uint32_t)(st_ * BSTG + q * 4) * 4, blrow + kc_ + q * 4); \
        } \
        CP_COMMIT(); \
    } while (0)

    PJ_ISSUE(0);

    for (int i = 0; i < 18; i++) {
        if (i + 1 < 18) { PJ_ISSUE(i + 1); CP_WAIT1(); }
        else CP_WAIT0();
        __syncthreads();

        const float* cA = sm + (i & 1) * ASTG;
        const float* cBh = sm + 9216 + (i & 1) * BSTG;
        const float* cBl = sm + 13824 + (i & 1) * BSTG;
#pragma unroll
        for (int ks = 0; ks < 4; ks++) {
            const int K0 = ks * 8;
            uint32_t ah[2][4], al[2][4];
#pragma unroll
            for (int mt = 0; mt < 2; mt++) {
                const int R = wr * 32 + mt * 16;
#pragma unroll
                for (int j = 0; j < 4; j++) {
                    const int rr = R + g + (j & 1) * 8;
                    const int ccol = K0 + c + (j >> 1) * 4;
                    const float raw = cA[rr * AP + ccol];
                    const float hv = tf32v(raw);
                    ah[mt][j] = __float_as_uint(hv);
                    al[mt][j] = f2tf32(raw - hv);
                }
            }
#pragma unroll
            for (int nt = 0; nt < 4; nt++) {
                const int N = wc * 32 + nt * 8;
                uint32_t bh[2], bl[2];
                bh[0] = *(const uint32_t*)&cBh[(N + g) * AP + K0 + c];
                bh[1] = *(const uint32_t*)&cBh[(N + g) * AP + K0 + c + 4];
                bl[0] = *(const uint32_t*)&cBl[(N + g) * AP + K0 + c];
                bl[1] = *(const uint32_t*)&cBl[(N + g) * AP + K0 + c + 4];
#pragma unroll
                for (int mt = 0; mt < 2; mt++) {
                    mma_tf32(acc[mt][nt], ah[mt], bh);
                    mma_tf32(acc[mt][nt], ah[mt], bl);
                    mma_tf32(acc[mt][nt], al[mt], bh);
                }
            }
        }
        __syncthreads();
    }
#undef PJ_ISSUE

#pragma unroll
    for (int mt = 0; mt < 2; mt++) {
#pragma unroll
        for (int nt = 0; nt < 4; nt++) {
            const int col = wc * 32 + nt * 8 + c2;
            const int r0 = m0 + wr * 32 + mt * 16 + g;
#pragma unroll
            for (int hrow = 0; hrow < 2; hrow++) {
                const size_t row = (size_t)(r0 + hrow * 8);
                const float v0 = acc[mt][nt][hrow * 2 + 0];
                const float v1 = acc[mt][nt][hrow * 2 + 1];
                if (col < DTR)
                    *(float2*)&g_dtr[row * DTR + col] = make_float2(v0, v1);
                else if (col < DTR + DS)
                    *(float2*)&g_Bs[row * DS + (col - DTR)] = make_float2(v0, v1);
                else if (col < 44)
                    *(float2*)&g_Cs[row * DS + (col - DTR - DS)] = make_float2(v0, v1);
            }
        }
    }
}

// ---------------- k_delta ----------------
__global__ void k_delta(const float* __restrict__ Wdt, const float* __restrict__ bdt)
{
    __shared__ float sd[8][DTR];
    const int tid = threadIdx.x;
    const int row0 = blockIdx.x * 8;
    if (tid < 8 * DTR) sd[tid / DTR][tid % DTR] = g_dtr[(size_t)(row0 + tid / DTR) * DTR + tid % DTR];
    __syncthreads();

    float w[DTR];
#pragma unroll
    for (int rr = 0; rr < DTR; rr++) w[rr] = Wdt[(size_t)rr * DI + tid];
    const float bb = bdt[tid];
#pragma unroll
    for (int rr = 0; rr < 8; rr++) {
        float acc = bb;
#pragma unroll
        for (int r2 = 0; r2 < DTR; r2++) acc = fmaf(sd[rr][r2], w[r2], acc);
        const float sp = acc > 20.f ? acc : log1pf(__expf(acc));
        g_delta[(size_t)(row0 + rr) * DI + tid] = sp;
    }
}

// ---------------- scan helpers ----------------
__device__ __forceinline__ void pow_chain(float e1, float* av)
{
    const float e2 = e1 * e1, e4 = e2 * e2, e8 = e4 * e4;
    av[0] = e1;       av[1] = e2;       av[2] = e2 * e1;   av[3] = e4;
    av[4] = e4 * e1;  av[5] = e4 * e2;  av[6] = e4 * av[2]; av[7] = e8;
    av[8] = e8 * e1;  av[9] = e8 * e2;  av[10] = e8 * av[2]; av[11] = e8 * e4;
    av[12] = e8 * av[4]; av[13] = e8 * av[5]; av[14] = e8 * av[6]; av[15] = e8 * e8;
}

__device__ __forceinline__ bool a_structured(const float* __restrict__ Alog, int d, float& A0)
{
    A0 = -__expf(Alog[(size_t)d * DS]);
    bool ok = true;
#pragma unroll
    for (int n = 1; n < DS; n++) {
        const float Av = -__expf(Alog[(size_t)d * DS + n]);
        ok &= fabsf(Av - (n + 1) * A0) <= 1e-4f * fabsf((n + 1) * A0);
    }
    return ok;
}

// ---------------- S1 ----------------
__global__ void k_scan1(const float* __restrict__ Alog)
{
    __shared__ float sB[CHL][DS];
    const int d = blockIdx.x * 128 + threadIdx.x;
    const int c = blockIdx.y;
    const int b = blockIdx.z;
    const int l0 = c * CHL;

    {
        const float4* src = (const float4*)g_Bs + ((size_t)b * L + l0) * 4;
        ((float4*)sB)[threadIdx.x] = src[threadIdx.x];
    }

    float A0;
    const bool st = a_structured(Alog, d, A0);
    __syncthreads();

    float h[DS];
#pragma unroll
    for (int n = 0; n < DS; n++) h[n] = 0.f;
    float dsum = 0.f;

    const float* dp = g_delta + ((size_t)b * L + l0) * DI + d;
    const float* up = g_u + ((size_t)b * L + l0) * DI + d;

    if (st) {
        for (int l = 0; l < CHL; l++) {
            const float dl = dp[(size_t)l * DI];
            const float du = dl * up[(size_t)l * DI];
            dsum += dl;
            float av[DS];
            pow_chain(__expf(dl * A0), av);
#pragma unroll
            for (int n = 0; n < DS; n++) h[n] = fmaf(av[n], h[n], du * sB[l][n]);
        }
        float av[DS];
        pow_chain(__expf(dsum * A0), av);
        const size_t base = (size_t)c * BDN + ((size_t)b * DI + d) * DS;
#pragma unroll
        for (int n = 0; n < DS; n++) {
            g_hpart[base + n] = h[n];
            g_aP[base + n] = av[n];
        }
    } else {
        float A[DS];
#pragma unroll
        for (int n = 0; n < DS; n++) A[n] = -__expf(Alog[(size_t)d * DS + n]);
        for (int l = 0; l < CHL; l++) {
            const float dl = dp[(size_t)l * DI];
            const float du = dl * up[(size_t)l * DI];
            dsum += dl;
#pragma unroll
            for (int n = 0; n < DS; n++)
                h[n] = fmaf(__expf(dl * A[n]), h[n], du * sB[l][n]);
        }
        const size_t base = (size_t)c * BDN + ((size_t)b * DI + d) * DS;
#pragma unroll
        for (int n = 0; n < DS; n++) {
            g_hpart[base + n] = h[n];
            g_aP[base + n] = __expf(A[n] * dsum);
        }
    }
}

// ---------------- S2 ----------------
__global__ void k_scan2()
{
    const int idx = blockIdx.x * 256 + threadIdx.x;
    if (idx >= BDN) return;
    float h = 0.f;
    for (int c = 0; c < NCH; c++) {
        const size_t o = (size_t)c * BDN + idx;
        g_hin[o] = h;
        h = fmaf(g_aP[o], h, g_hpart[o]);
    }
}

// ---------------- S3 ----------------
__global__ void k_scan3(const float* __restrict__ Alog, const float* __restrict__ Dvec)
{
    __shared__ float sB[CHL][DS];
    __shared__ float sC[CHL][DS];
    const int d = blockIdx.x * 128 + threadIdx.x;
    const int c = blockIdx.y;
    const int b = blockIdx.z;
    const int l0 = c * CHL;

    {
        const float4* srcB = (const float4*)g_Bs + ((size_t)b * L + l0) * 4;
        const float4* srcC = (const float4*)g_Cs + ((size_t)b * L + l0) * 4;
        ((float4*)sB)[threadIdx.x] = srcB[threadIdx.x];
        ((float4*)sC)[threadIdx.x] = srcC[threadIdx.x];
    }

    float A0;
    const bool st = a_structured(Alog, d, A0);
    const float Dd = Dvec[d];
    __syncthreads();

    float h[DS];
    {
        const size_t base = (size_t)c * BDN + ((size_t)b * DI + d) * DS;
#pragma unroll
        for (int n = 0; n < DS; n++) h[n] = g_hin[base + n];
    }

    const float* dp = g_delta + ((size_t)b * L + l0) * DI + d;
    const float* up = g_u + ((size_t)b * L + l0) * DI + d;
    float* yp = g_y + ((size_t)b * L + l0) * DI + d;

    if (st) {
        for (int l = 0; l < CHL; l++) {
            const float dl = dp[(size_t)l * DI];
            const float uu = up[(size_t)l * DI];
            const float du = dl * uu;
            float av[DS];
            pow_chain(__expf(dl * A0), av);
            float y = uu * Dd;
#pragma unroll
            for (int n = 0; n < DS; n++) {
                h[n] = fmaf(av[n], h[n], du * sB[l][n]);
                y = fmaf(h[n], sC[l][n], y);
            }
            yp[(size_t)l * DI] = y;
        }
    } else {
        float A[DS];
#pragma unroll
        for (int n = 0; n < DS; n++) A[n] = -__expf(Alog[(size_t)d * DS + n]);
        for (int l = 0; l < CHL; l++) {
            const float dl = dp[(size_t)l * DI];
            const float uu = up[(size_t)l * DI];
            const float du = dl * uu;
            float y = uu * Dd;
#pragma unroll
            for (int n = 0; n < DS; n++) {
                h[n] = fmaf(__expf(dl * A[n]), h[n], du * sB[l][n]);
                y = fmaf(h[n], sC[l][n], y);
            }
            yp[(size_t)l * DI] = y;
        }
    }
}

// ---------------- k_lngate ----------------
__global__ __launch_bounds__(256) void k_lngate(const float* __restrict__ lng,
                                                const float* __restrict__ lnb)
{
    const int tid = threadIdx.x;
    const int r0 = blockIdx.x * 16;
    const int warp = tid >> 5, lane = tid & 31;

#pragma unroll
    for (int rr = 0; rr < 2; rr++) {
        const int r = warp * 2 + rr;
        const size_t row = (size_t)(r0 + r);
        float v[12];
        float s = 0.f, sq = 0.f;
#pragma unroll
        for (int i = 0; i < 12; i++) {
            v[i] = g_y[row * DI + lane + 32 * i];
            s += v[i];
            sq = fmaf(v[i], v[i], sq);
        }
#pragma unroll
        for (int o = 16; o > 0; o >>= 1) {
            s += __shfl_xor_sync(0xFFFFFFFFu, s, o);
            sq += __shfl_xor_sync(0xFFFFFFFFu, sq, o);
        }
        const float mu = s * (1.f / DI);
        const float var = sq * (1.f / DI) - mu * mu;
        const float rs = rsqrtf(var + 1e-5f);
#pragma unroll
        for (int i = 0; i < 12; i++) {
            const int k = lane + 32 * i;
            const float zn = g_z[row * DI + k];
            const float sig = 1.f / (1.f + __expf(-zn));
            const float g = fmaf((v[i] - mu) * rs, lng[k], lnb[k]);
            g_xi[row * DI + k] = g * zn * sig;
        }
    }
}

// ---------------- k_gemm_out: out = yg @ Wout via tf32x3 (cp.async pipeline) ----------------
__global__ __launch_bounds__(256) void k_gemm_out(float* __restrict__ out)
{
    extern __shared__ float sm[];
    const uint32_t sbase = (uint32_t)__cvta_generic_to_shared(sm);
    const int tid = threadIdx.x;
    const int wid = tid >> 5, t = tid & 31;
    const int m0 = blockIdx.x * 128, n0 = blockIdx.y * 64;
    const int wr = wid & 3, wc = wid >> 2;
    const int g = t >> 2, c = t & 3, c2 = c * 2;

    float acc[2][4][4];
#pragma unroll
    for (int mt = 0; mt < 2; mt++)
#pragma unroll
        for (int nt = 0; nt < 4; nt++)
#pragma unroll
            for (int e = 0; e < 4; e++) acc[mt][nt][e] = 0.f;

    const int lr = tid >> 1;
    const int lh = (tid & 1) * 16;
    const int lrB = tid >> 2;
    const int lhB = (tid & 3) * 8;
    const float* arow = g_xi + (size_t)(m0 + lr) * DI + lh;
    const float* bhrow = g_wohi + (size_t)(n0 + lrB) * DI + lhB;
    const float* blrow = g_wolo + (size_t)(n0 + lrB) * DI + lhB;
    const uint32_t adst = sbase + (uint32_t)(lr * AP + lh) * 4;
    const uint32_t bhdst = sbase + (uint32_t)(9216 + lrB * AP + lhB) * 4;
    const uint32_t bldst = sbase + (uint32_t)(13824 + lrB * AP + lhB) * 4;

#define GO_ISSUE(i) do { \
        const int st_ = (i) & 1; const int kc_ = (i) * 32; \
        _Pragma("unroll") \
        for (int q = 0; q < 4; q++) \
            CP16(adst + (uint32_t)(st_ * ASTG + q * 4) * 4, arow + kc_ + q * 4); \
        _Pragma("unroll") \
        for (int q = 0; q < 2; q++) { \
            CP16(bhdst + (uint32_t)(st_ * BSTG + q * 4) * 4, bhrow + kc_ + q * 4); \
            CP16(bldst + (uint32_t)(st_ * BSTG + q * 4) * 4, blrow + kc_ + q * 4); \
        } \
        CP_COMMIT(); \
    } while (0)

    GO_ISSUE(0);

    for (int i = 0; i < 12; i++) {
        if (i + 1 < 12) { GO_ISSUE(i + 1); CP_WAIT1(); }
        else CP_WAIT0();
        __syncthreads();

        const float* cA = sm + (i & 1) * ASTG;
        const float* cBh = sm + 9216 + (i & 1) * BSTG;
        const float* cBl = sm + 13824 + (i & 1) * BSTG;
#pragma unroll
        for (int ks = 0; ks < 4; ks++) {
            const int K0 = ks * 8;
            uint32_t ah[2][4], al[2][4];
#pragma unroll
            for (int mt = 0; mt < 2; mt++) {
                const int R = wr * 32 + mt * 16;
#pragma unroll
                for (int j = 0; j < 4; j++) {
                    const int rr = R + g + (j & 1) * 8;
                    const int ccol = K0 + c + (j >> 1) * 4;
                    const float raw = cA[rr * AP + ccol];
                    const float hv = tf32v(raw);
                    ah[mt][j] = __float_as_uint(hv);
                    al[mt][j] = f2tf32(raw - hv);
                }
            }
#pragma unroll
            for (int nt = 0; nt < 4; nt++) {
                const int N = wc * 32 + nt * 8;
                uint32_t bh[2], bl[2];
                bh[0] = *(const uint32_t*)&cBh[(N + g) * AP + K0 + c];
                bh[1] = *(const uint32_t*)&cBh[(N + g) * AP + K0 + c + 4];
                bl[0] = *(const uint32_t*)&cBl[(N + g) * AP + K0 + c];
                bl[1] = *(const uint32_t*)&cBl[(N + g) * AP + K0 + c + 4];
#pragma unroll
                for (int mt = 0; mt < 2; mt++) {
                    mma_tf32(acc[mt][nt], ah[mt], bh);
                    mma_tf32(acc[mt][nt], ah[mt], bl);
                    mma_tf32(acc[mt][nt], al[mt], bh);
                }
            }
        }
        __syncthreads();
    }
#undef GO_ISSUE

#pragma unroll
    for (int mt = 0; mt < 2; mt++) {
#pragma unroll
        for (int nt = 0; nt < 4; nt++) {
            const int col = n0 + wc * 32 + nt * 8 + c2;
            const int r0 = m0 + wr * 32 + mt * 16 + g;
            *(float2*)&out[(size_t)r0 * CM + col] =
                make_float2(acc[mt][nt][0], acc[mt][nt][1]);
            *(float2*)&out[(size_t)(r0 + 8) * CM + col] =
                make_float2(acc[mt][nt][2], acc[mt][nt][3]);
        }
    }
}

// ---------------- launch ----------------
extern "C" void kernel_launch(void* const* d_in, const int* in_sizes, int n_in,
                              void* d_out, int out_size)
{
    const float* x      = (const float*)d_in[0];
    const float* prompt = (const float*)d_in[1];
    const float* W_in   = (const float*)d_in[2];
    const float* conv_w = (const float*)d_in[3];
    const float* conv_b = (const float*)d_in[4];
    const float* Wx     = (const float*)d_in[5];
    const float* Wdt    = (const float*)d_in[6];
    const float* b_dt   = (const float*)d_in[7];
    const float* A_log  = (const float*)d_in[8];
    const float* Dv     = (const float*)d_in[9];
    const float* Wp     = (const float*)d_in[10];
    const float* ln_g   = (const float*)d_in[11];
    const float* ln_b   = (const float*)d_in[12];
    const float* Wout   = (const float*)d_in[13];
    float* out = (float*)d_out;

    static bool attr_set = false;
    if (!attr_set) {
        cudaFuncSetAttribute(k_conv, cudaFuncAttributeMaxDynamicSharedMemorySize, 51200);
        cudaFuncSetAttribute(k_gemm_tf32, cudaFuncAttributeMaxDynamicSharedMemorySize, 53248);
        cudaFuncSetAttribute(k_proj_mma, cudaFuncAttributeMaxDynamicSharedMemorySize, 73728);
        cudaFuncSetAttribute(k_gemm_out, cudaFuncAttributeMaxDynamicSharedMemorySize, 73728);
        attr_set = true;
    }

    k_prep_w<<<(CM * NX + 255) / 256, 256>>>(W_in);
    k_prep_pw<<<(NP * KC + 255) / 256, 256>>>(Wx, Wp);
    k_prep_wout<<<(CM * DI + 255) / 256, 256>>>(Wout);
    k_gemm_tf32<<<dim3(M_ROWS / 128, NX / 64), 256, 53248>>>(x);
    k_conv<<<dim3(64, 3, BATCH), dim3(128, 8), 51200>>>(conv_w, conv_b);
    k_proj_mma<<<M_ROWS / 128, 256, 73728>>>(prompt);
    k_delta<<<M_ROWS / 8, DI>>>(Wdt, b_dt);
    k_scan1<<<dim3(DI / 128, NCH, BATCH), 128>>>(A_log);
    k_scan2<<<(BDN + 255) / 256, 256>>>();
    k_scan3<<<dim3(DI / 128, NCH, BATCH), 128>>>(A_log, Dv);
    k_lngate<<<M_ROWS / 16, 256>>>(ln_g, ln_b);
    k_gemm_out<<<dim3(M_ROWS / 128, 3), 256, 73728>>>(out);
}